// round 10
// baseline (speedup 1.0000x reference)
#include <cuda_runtime.h>
#include <cuda_bf16.h>
#include <math.h>
#include <float.h>
#include <cstdint>

#define B 4096
#define T 200
#define BT (B*T)
#define GR 10    // batch rows per GRU block
#define GRH 5    // rows per thread-group (2 groups of 128 threads)

// ---------------- scratch (device globals: no allocs allowed) ----------------
__device__ float g_xg[(size_t)BT * 128];
__device__ float g_xc[(size_t)BT * 64];
__device__ float g_rnn1[(size_t)BT * 64];
__device__ float g_alpha[BT];
__device__ float g_final2[B * 64];
// split-bf16 weights for the two projection GEMMs: layout [n(192)][k(64)]
__device__ __nv_bfloat16 g_bh1[192 * 64];
__device__ __nv_bfloat16 g_bl1[192 * 64];
__device__ __nv_bfloat16 g_bh2[192 * 64];
__device__ __nv_bfloat16 g_bl2[192 * 64];

__device__ __forceinline__ float sigmoidf_fast(float x) {
    return 1.0f / (1.0f + __expf(-x));
}
__device__ __forceinline__ float tanh_fast(float x) {
    float ax = fabsf(x);
    float e = __expf(-2.0f * ax);
    float th = __fdividef(1.0f - e, 1.0f + e);
    return copysignf(th, x);
}

__device__ __forceinline__ uint32_t smem_u32(const void* p) {
    uint32_t a;
    asm("{ .reg .u64 t; cvta.to.shared.u64 t, %1; cvt.u32.u64 %0, t; }" : "=r"(a) : "l"(p));
    return a;
}
__device__ __forceinline__ void ldsm_x4(uint32_t& r0, uint32_t& r1, uint32_t& r2, uint32_t& r3,
                                        uint32_t addr) {
    asm volatile("ldmatrix.sync.aligned.m8n8.x4.shared.b16 {%0,%1,%2,%3}, [%4];"
                 : "=r"(r0), "=r"(r1), "=r"(r2), "=r"(r3) : "r"(addr));
}
__device__ __forceinline__ void mma16816(float* c, const uint32_t* a, uint32_t b0, uint32_t b1) {
    asm volatile("mma.sync.aligned.m16n8k16.row.col.f32.bf16.bf16.f32 "
                 "{%0,%1,%2,%3}, {%4,%5,%6,%7}, {%8,%9}, {%0,%1,%2,%3};"
                 : "+f"(c[0]), "+f"(c[1]), "+f"(c[2]), "+f"(c[3])
                 : "r"(a[0]), "r"(a[1]), "r"(a[2]), "r"(a[3]), "r"(b0), "r"(b1));
}

// ======================================================================
// Weight split prep: W[64,128]|[64,64] fp32 -> Bhi/Blo [n=192][k=64] bf16
// ======================================================================
__global__ void wsplit_kernel(const float* __restrict__ Wg, const float* __restrict__ Wc,
                              __nv_bfloat16* __restrict__ Bhi, __nv_bfloat16* __restrict__ Blo)
{
    int idx = blockIdx.x * 256 + threadIdx.x;
    if (idx >= 192 * 64) return;
    int n = idx >> 6, k = idx & 63;
    float w = (n < 128) ? Wg[k * 128 + n] : Wc[k * 64 + (n - 128)];
    __nv_bfloat16 hi = __float2bfloat16(w);
    __nv_bfloat16 lo = __float2bfloat16(w - __bfloat162float(hi));
    Bhi[idx] = hi;
    Blo[idx] = lo;
}

// ======================================================================
// HMMA projection: D[128 x 192] = A[128x64] @ W + bias (unchanged, passing).
// ======================================================================
#define PAD_K 72   // bf16 elements per smem row (144 B)
#define PSM_BIAS 0
#define PSM_AHI  768
#define PSM_ALO  (PSM_AHI + 128 * PAD_K * 2)
#define PSM_BHI  (PSM_ALO + 128 * PAD_K * 2)
#define PSM_BLO  (PSM_BHI + 192 * PAD_K * 2)
#define PSM_TOTAL (PSM_BLO + 192 * PAD_K * 2)   // 92928 bytes

template<int MODE>
__global__ void __launch_bounds__(256, 2) proj_mma_kernel(
        const float* __restrict__ src,
        const int*   __restrict__ hist_i,
        const float* __restrict__ alpha,
        const __nv_bfloat16* __restrict__ Bhi,
        const __nv_bfloat16* __restrict__ Blo,
        const float* __restrict__ bg,
        const float* __restrict__ bc,
        float* __restrict__ xg,
        float* __restrict__ xc)
{
    extern __shared__ char smem[];
    const uint32_t sbase = smem_u32(smem);
    const int tid = threadIdx.x;
    const int wid = tid >> 5;
    const int lane = tid & 31;
    const int m0 = blockIdx.x * 128;

    float* bs = (float*)(smem + PSM_BIAS);
    if (tid < 192) bs[tid] = (tid < 128) ? bg[tid] : bc[tid - 128];

    {
        const uint4* sh = (const uint4*)Bhi;
        const uint4* sl = (const uint4*)Blo;
#pragma unroll
        for (int i = 0; i < 6; i++) {
            int idx = tid + 256 * i;               // < 1536
            int n = idx >> 3, seg = idx & 7;
            int off = n * (PAD_K * 2) + seg * 16;
            *(uint4*)(smem + PSM_BHI + off) = sh[idx];
            *(uint4*)(smem + PSM_BLO + off) = sl[idx];
        }
    }

    {
        const int r = tid >> 1;
        const int half = tid & 1;
        const float* srow;
        float scale = 1.0f;
        if (MODE == 0) {
            srow = src + (size_t)hist_i[m0 + r] * 64;
        } else {
            srow = src + (size_t)(m0 + r) * 64;
            scale = alpha[m0 + r];
        }
        srow += half * 32;
        const int kb = half * 32;
#pragma unroll
        for (int c = 0; c < 4; c++) {
            float4 v0 = *(const float4*)(srow + 8 * c);
            float4 v1 = *(const float4*)(srow + 8 * c + 4);
            float vv[8] = {v0.x, v0.y, v0.z, v0.w, v1.x, v1.y, v1.z, v1.w};
            __nv_bfloat16 hb[8], lb[8];
#pragma unroll
            for (int e = 0; e < 8; e++) {
                float f = vv[e] * scale;
                hb[e] = __float2bfloat16(f);
                lb[e] = __float2bfloat16(f - __bfloat162float(hb[e]));
            }
            int off = r * (PAD_K * 2) + (kb + 8 * c) * 2;
            *(uint4*)(smem + PSM_AHI + off) = *(uint4*)hb;
            *(uint4*)(smem + PSM_ALO + off) = *(uint4*)lb;
        }
    }
    __syncthreads();

    const int arow = wid * 16 + (lane & 15);
    const int acolb = ((lane >> 4) << 3);
    const uint32_t a_off = (uint32_t)arow * (PAD_K * 2) + acolb * 2;
    const uint32_t aH_base = sbase + PSM_AHI + a_off;
    const uint32_t aL_base = sbase + PSM_ALO + a_off;

    const int bnrow_l = (lane & 7) + ((lane & 16) >> 1);
    const int bcol_l = (lane & 8);
    const uint32_t b_off_l = (uint32_t)bnrow_l * (PAD_K * 2) + bcol_l * 2;

    const int g = lane >> 2;
    const int tq = lane & 3;

#pragma unroll
    for (int nh = 0; nh < 2; nh++) {
        const uint32_t bH_base = sbase + PSM_BHI + b_off_l + (uint32_t)nh * 96 * (PAD_K * 2);
        const uint32_t bL_base = sbase + PSM_BLO + b_off_l + (uint32_t)nh * 96 * (PAD_K * 2);

        float acc[12][4];
#pragma unroll
        for (int i = 0; i < 12; i++)
#pragma unroll
            for (int q = 0; q < 4; q++) acc[i][q] = 0.0f;

#pragma unroll
        for (int ks = 0; ks < 4; ks++) {
            uint32_t aH[4], aL[4];
            ldsm_x4(aH[0], aH[1], aH[2], aH[3], aH_base + ks * 32);
            ldsm_x4(aL[0], aL[1], aL[2], aL[3], aL_base + ks * 32);
#pragma unroll
            for (int np = 0; np < 6; np++) {
                uint32_t bh0, bh1, bh2, bh3;
                ldsm_x4(bh0, bh1, bh2, bh3,
                        bH_base + (uint32_t)np * 16 * (PAD_K * 2) + ks * 32);
                mma16816(acc[2 * np],     aH, bh0, bh1);
                mma16816(acc[2 * np + 1], aH, bh2, bh3);
                mma16816(acc[2 * np],     aL, bh0, bh1);
                mma16816(acc[2 * np + 1], aL, bh2, bh3);
                uint32_t bl0, bl1, bl2, bl3;
                ldsm_x4(bl0, bl1, bl2, bl3,
                        bL_base + (uint32_t)np * 16 * (PAD_K * 2) + ks * 32);
                mma16816(acc[2 * np],     aH, bl0, bl1);
                mma16816(acc[2 * np + 1], aH, bl2, bl3);
            }
        }

        const int r0 = m0 + wid * 16 + g;
        const int r1 = r0 + 8;
#pragma unroll
        for (int nt = 0; nt < 12; nt++) {
            const int n = nh * 96 + nt * 8 + 2 * tq;
            const float bx = bs[n], by = bs[n + 1];
            float2 o0 = make_float2(acc[nt][0] + bx, acc[nt][1] + by);
            float2 o1 = make_float2(acc[nt][2] + bx, acc[nt][3] + by);
            if (n < 128) {
                *(float2*)(xg + (size_t)r0 * 128 + n) = o0;
                *(float2*)(xg + (size_t)r1 * 128 + n) = o1;
            } else {
                *(float2*)(xc + (size_t)r0 * 64 + (n - 128)) = o0;
                *(float2*)(xc + (size_t)r1 * 64 + (n - 128)) = o1;
            }
        }
    }
}

// ======================================================================
// GRU recurrence v6: R7 math, 256 threads = 2 independent row-groups of
// GRH=5 rows sharing one smem weight copy. Doubles warps/SM for latency
// cover without extra smem. Gate: thread (j,group); candidate: pair-split
// k (c = j>>1, half = j&1) within each group, combined via shfl_xor(1).
// ======================================================================
template<bool STORE_ALL>
__global__ void __launch_bounds__(256) gru_kernel(
                           const float* __restrict__ xg,
                           const float* __restrict__ xc,
                           const float* __restrict__ mask,
                           const float* __restrict__ Ug,  // [64,128]
                           const float* __restrict__ Uc,  // [64,64]
                           float* __restrict__ out)
{
    extern __shared__ float sm[];
    float* UgsT = sm;                     // [128][68]
    float* UcsT = UgsT + 128 * 68;        // [64][72] split layout
    float* hs   = UcsT + 64 * 72;         // [GR][64]
    float* rhs  = hs + GR * 64;           // [GR][72] split layout
    float* zs   = rhs + GR * 72;          // [GR][64]
    float* msk  = zs + GR * 64;           // [GR][T]

    const int tid  = threadIdx.x;         // 0..255
    const int grp  = tid >> 7;            // row group 0/1
    const int j    = tid & 127;           // gate column
    const int b0   = blockIdx.x * GR;
    const int c    = j >> 1;              // candidate column 0..63
    const int half = j & 1;
    const int r0   = grp * GRH;

    for (int idx = tid; idx < 128 * 64; idx += 256)
        UgsT[(idx & 127) * 68 + (idx >> 7)] = Ug[idx];
    for (int idx = tid; idx < 64 * 64; idx += 256) {
        int k = idx >> 6, cc = idx & 63;
        UcsT[cc * 72 + (k >> 5) * 36 + (k & 31)] = Uc[idx];
    }
    for (int idx = tid; idx < GR * 64; idx += 256) hs[idx] = 0.0f;

    int br[GRH];
    bool val[GRH];
#pragma unroll
    for (int i = 0; i < GRH; i++) {
        int b = b0 + r0 + i;
        val[i] = (b < B);
        br[i] = val[i] ? b : (B - 1);
    }
    for (int idx = tid; idx < GR * T; idx += 256) {
        int r = idx / T, t = idx - r * T;
        int bb = b0 + r; if (bb >= B) bb = B - 1;
        msk[idx] = mask[(size_t)bb * T + t];
    }
    __syncthreads();

    float xgv[GRH];
#pragma unroll
    for (int i = 0; i < GRH; i++)
        xgv[i] = xg[(size_t)br[i] * (T * 128) + j];

    const float* wg  = UgsT + j * 68;
    const float* wcp = UcsT + c * 72 + half * 36;

    for (int t = 0; t < T; t++) {
        // prefetch xc (consumed at candidate init by half==0; symmetric load)
        float xcv[GRH];
#pragma unroll
        for (int i = 0; i < GRH; i++)
            xcv[i] = xc[(size_t)br[i] * (T * 64) + t * 64 + c];

        // ---- gate matvec: column j, GRH rows ----
        float acc[GRH];
#pragma unroll
        for (int i = 0; i < GRH; i++) acc[i] = xgv[i];

#pragma unroll 4
        for (int k4 = 0; k4 < 16; k4++) {
            float4 w = *(const float4*)(wg + 4 * k4);
#pragma unroll
            for (int i = 0; i < GRH; i++) {
                float4 h4 = *(const float4*)(hs + (r0 + i) * 64 + 4 * k4);
                acc[i] = fmaf(h4.x, w.x, acc[i]);
                acc[i] = fmaf(h4.y, w.y, acc[i]);
                acc[i] = fmaf(h4.z, w.z, acc[i]);
                acc[i] = fmaf(h4.w, w.w, acc[i]);
            }
        }

        // prefetch next xg
        if (t + 1 < T) {
#pragma unroll
            for (int i = 0; i < GRH; i++)
                xgv[i] = xg[(size_t)br[i] * (T * 128) + (t + 1) * 128 + j];
        }

#pragma unroll
        for (int i = 0; i < GRH; i++) {
            float gv = sigmoidf_fast(acc[i]);
            int r = r0 + i;
            if (j < 64) rhs[r * 72 + (j >> 5) * 36 + (j & 31)] = gv * hs[r * 64 + j];
            else        zs[r * 64 + (j - 64)] = gv;
        }
        __syncthreads();

        // ---- candidate matvec (pair-split k within group) ----
        float cacc[GRH];
#pragma unroll
        for (int i = 0; i < GRH; i++) cacc[i] = (half == 0) ? xcv[i] : 0.0f;

#pragma unroll 4
        for (int k4 = 0; k4 < 8; k4++) {
            float4 w = *(const float4*)(wcp + 4 * k4);
#pragma unroll
            for (int i = 0; i < GRH; i++) {
                float4 rh = *(const float4*)(rhs + (r0 + i) * 72 + half * 36 + 4 * k4);
                cacc[i] = fmaf(rh.x, w.x, cacc[i]);
                cacc[i] = fmaf(rh.y, w.y, cacc[i]);
                cacc[i] = fmaf(rh.z, w.z, cacc[i]);
                cacc[i] = fmaf(rh.w, w.w, cacc[i]);
            }
        }

#pragma unroll
        for (int i = 0; i < GRH; i++) {
            float tot = cacc[i] + __shfl_xor_sync(0xffffffffu, cacc[i], 1);
            float cand = tanh_fast(tot);
            int r = r0 + i;
            float z = zs[r * 64 + c];
            float h = hs[r * 64 + c];
            float hn = fmaf(z, h - cand, cand);      // z*h + (1-z)*cand
            float m = msk[r * T + t];
            float hnew = fmaf(m, hn - h, h);
            if (half == 0) {
                hs[r * 64 + c] = hnew;
                if (STORE_ALL && val[i])
                    out[(size_t)br[i] * (T * 64) + t * 64 + c] = hnew;
            }
        }
        __syncthreads();
    }

    if (!STORE_ALL && j < 64) {
#pragma unroll
        for (int i = 0; i < GRH; i++)
            if (val[i]) out[(size_t)br[i] * 64 + j] = hs[(r0 + i) * 64 + j];
    }
}

// ======================================================================
// DIN attention (unchanged).
// ======================================================================
__global__ void __launch_bounds__(320) attn_kernel(
                            const int*   __restrict__ item_i,
                            const float* __restrict__ item_emb,
                            const float* __restrict__ rnn1,
                            const float* __restrict__ mask,
                            const float* __restrict__ Wa1, const float* __restrict__ ba1,
                            const float* __restrict__ Wa2, const float* __restrict__ ba2,
                            const float* __restrict__ Wa3, const float* __restrict__ ba3,
                            float* __restrict__ alpha)
{
    extern __shared__ float sm[];
    float* Weff = sm;
    float* base = Weff + 64 * 80;
    float* Wa2s = base + 80;
    float* ba2s = Wa2s + 80 * 40;
    float* Wa3s = ba2s + 40;
    float* qs   = Wa3s + 40;
    float* Ks   = qs + 64;
    float* d1s  = Ks + 32 * 68;
    float* d2s  = d1s + 32 * 80;
    float* sc   = d2s + 32 * 40;
    float* red  = sc + 224;

    const int b = blockIdx.x;
    const int tid = threadIdx.x;

    const int l1_t0 = (tid / 20) * 2;
    const int l1_c0 = (tid % 20) * 4;
    const int l2_t0 = (tid / 10) * 2;
    const int l2_c0 = (tid % 10) * 4;

    if (tid < 64) qs[tid] = item_emb[(size_t)item_i[b] * 64 + tid];
    __syncthreads();

    if (tid < 80) {
        int c = tid;
        float acc = ba1[c];
#pragma unroll 8
        for (int k = 0; k < 64; k++)
            acc = fmaf(qs[k], Wa1[k * 80 + c] + Wa1[(128 + k) * 80 + c], acc);
        base[c] = acc;
    }
    for (int idx = tid; idx < 64 * 80; idx += 320) {
        int k = idx / 80, c = idx - k * 80;
        Weff[idx] = Wa1[(64 + k) * 80 + c] - Wa1[(128 + k) * 80 + c]
                  + qs[k] * Wa1[(192 + k) * 80 + c];
    }
    for (int idx = tid; idx < 80 * 40; idx += 320) Wa2s[idx] = Wa2[idx];
    if (tid < 40) { ba2s[tid] = ba2[tid]; Wa3s[tid] = Wa3[tid]; }
    __syncthreads();

    const float ba3v = ba3[0];

    for (int cc = 0; cc < 7; cc++) {
        const int tt0 = cc * 32;

        for (int idx = tid; idx < 512; idx += 320) {
            int tl = idx >> 4, k4 = idx & 15;
            int tg = tt0 + tl; if (tg > T - 1) tg = T - 1;
            float4 v = *(const float4*)(rnn1 + ((size_t)b * T + tg) * 64 + 4 * k4);
            *(float4*)(Ks + tl * 68 + 4 * k4) = v;
        }
        __syncthreads();

        {
            float4 bse = *(const float4*)(base + l1_c0);
            float a00 = bse.x, a01 = bse.y, a02 = bse.z, a03 = bse.w;
            float a10 = bse.x, a11 = bse.y, a12 = bse.z, a13 = bse.w;
#pragma unroll 4
            for (int k4 = 0; k4 < 16; k4++) {
                float4 k0 = *(const float4*)(Ks + l1_t0 * 68 + 4 * k4);
                float4 k1 = *(const float4*)(Ks + (l1_t0 + 1) * 68 + 4 * k4);
                const float kk0[4] = {k0.x, k0.y, k0.z, k0.w};
                const float kk1[4] = {k1.x, k1.y, k1.z, k1.w};
#pragma unroll
                for (int kk = 0; kk < 4; kk++) {
                    float4 w = *(const float4*)(Weff + (4 * k4 + kk) * 80 + l1_c0);
                    a00 = fmaf(kk0[kk], w.x, a00); a01 = fmaf(kk0[kk], w.y, a01);
                    a02 = fmaf(kk0[kk], w.z, a02); a03 = fmaf(kk0[kk], w.w, a03);
                    a10 = fmaf(kk1[kk], w.x, a10); a11 = fmaf(kk1[kk], w.y, a11);
                    a12 = fmaf(kk1[kk], w.z, a12); a13 = fmaf(kk1[kk], w.w, a13);
                }
            }
            float4 o0 = make_float4(sigmoidf_fast(a00), sigmoidf_fast(a01),
                                    sigmoidf_fast(a02), sigmoidf_fast(a03));
            float4 o1 = make_float4(sigmoidf_fast(a10), sigmoidf_fast(a11),
                                    sigmoidf_fast(a12), sigmoidf_fast(a13));
            *(float4*)(d1s + l1_t0 * 80 + l1_c0) = o0;
            *(float4*)(d1s + (l1_t0 + 1) * 80 + l1_c0) = o1;
        }
        __syncthreads();

        if (tid < 160) {
            float4 bse = *(const float4*)(ba2s + l2_c0);
            float a00 = bse.x, a01 = bse.y, a02 = bse.z, a03 = bse.w;
            float a10 = bse.x, a11 = bse.y, a12 = bse.z, a13 = bse.w;
#pragma unroll 4
            for (int k4 = 0; k4 < 20; k4++) {
                float4 d0 = *(const float4*)(d1s + l2_t0 * 80 + 4 * k4);
                float4 d1 = *(const float4*)(d1s + (l2_t0 + 1) * 80 + 4 * k4);
                const float dd0[4] = {d0.x, d0.y, d0.z, d0.w};
                const float dd1[4] = {d1.x, d1.y, d1.z, d1.w};
#pragma unroll
                for (int kk = 0; kk < 4; kk++) {
                    float4 w = *(const float4*)(Wa2s + (4 * k4 + kk) * 40 + l2_c0);
                    a00 = fmaf(dd0[kk], w.x, a00); a01 = fmaf(dd0[kk], w.y, a01);
                    a02 = fmaf(dd0[kk], w.z, a02); a03 = fmaf(dd0[kk], w.w, a03);
                    a10 = fmaf(dd1[kk], w.x, a10); a11 = fmaf(dd1[kk], w.y, a11);
                    a12 = fmaf(dd1[kk], w.z, a12); a13 = fmaf(dd1[kk], w.w, a13);
                }
            }
            float4 o0 = make_float4(sigmoidf_fast(a00), sigmoidf_fast(a01),
                                    sigmoidf_fast(a02), sigmoidf_fast(a03));
            float4 o1 = make_float4(sigmoidf_fast(a10), sigmoidf_fast(a11),
                                    sigmoidf_fast(a12), sigmoidf_fast(a13));
            *(float4*)(d2s + l2_t0 * 40 + l2_c0) = o0;
            *(float4*)(d2s + (l2_t0 + 1) * 40 + l2_c0) = o1;
        }
        __syncthreads();

        if (tid < 32) {
            float acc = ba3v;
#pragma unroll
            for (int k4 = 0; k4 < 10; k4++) {
                float4 d = *(const float4*)(d2s + tid * 40 + 4 * k4);
                float4 w = *(const float4*)(Wa3s + 4 * k4);
                acc = fmaf(d.x, w.x, acc); acc = fmaf(d.y, w.y, acc);
                acc = fmaf(d.z, w.z, acc); acc = fmaf(d.w, w.w, acc);
            }
            int tg = tt0 + tid;
            if (tg < T) {
                float m = mask[(size_t)b * T + tg];
                sc[tg] = (m > 0.0f) ? acc : -1e9f;
            }
        }
        __syncthreads();
    }

    float v = (tid < T) ? sc[tid] : -FLT_MAX;
#pragma unroll
    for (int o = 16; o > 0; o >>= 1) v = fmaxf(v, __shfl_xor_sync(0xffffffffu, v, o));
    if ((tid & 31) == 0) red[tid >> 5] = v;
    __syncthreads();
    if (tid == 0) {
        float mx = red[0];
#pragma unroll
        for (int w = 1; w < 10; w++) mx = fmaxf(mx, red[w]);
        red[12] = mx;
    }
    __syncthreads();
    float mx = red[12];

    float e = (tid < T) ? __expf(sc[tid] - mx) : 0.0f;
    float s = e;
#pragma unroll
    for (int o = 16; o > 0; o >>= 1) s += __shfl_xor_sync(0xffffffffu, s, o);
    __syncthreads();
    if ((tid & 31) == 0) red[tid >> 5] = s;
    __syncthreads();
    if (tid == 0) {
        float sum = 0.0f;
#pragma unroll
        for (int w = 0; w < 10; w++) sum += red[w];
        red[13] = 1.0f / sum;
    }
    __syncthreads();
    if (tid < T) alpha[(size_t)b * T + tid] = e * red[13];
}

// ======================================================================
// FCN head + hist_sum (unchanged).
// ======================================================================
__global__ void fcn_kernel(const int* __restrict__ u, const int* __restrict__ ii,
                           const int* __restrict__ hist_i,
                           const float* __restrict__ item_emb,
                           const float* __restrict__ user_emb,
                           const float* __restrict__ final2,
                           const float* __restrict__ W1, const float* __restrict__ b1,
                           const float* __restrict__ p1,
                           const float* __restrict__ W2, const float* __restrict__ b2,
                           const float* __restrict__ p2,
                           const float* __restrict__ W3, const float* __restrict__ b3,
                           float* __restrict__ out)
{
    __shared__ float xs[320];
    __shared__ float h1s[128];
    __shared__ float h2s[40];

    const int b = blockIdx.x;
    const int tid = threadIdx.x;

    if (tid < 64) {
        const int* hi = hist_i + (size_t)b * T;
        float s0 = 0.f, s1 = 0.f, s2 = 0.f, s3 = 0.f;
        for (int t = 0; t < T; t += 4) {
            s0 += item_emb[(size_t)hi[t]     * 64 + tid];
            s1 += item_emb[(size_t)hi[t + 1] * 64 + tid];
            s2 += item_emb[(size_t)hi[t + 2] * 64 + tid];
            s3 += item_emb[(size_t)hi[t + 3] * 64 + tid];
        }
        xs[128 + tid] = (s0 + s1) + (s2 + s3);
    } else {
        int j = tid - 64;
        xs[j]       = user_emb[(size_t)u[b]  * 64 + j];
        xs[64 + j]  = item_emb[(size_t)ii[b] * 64 + j];
        xs[256 + j] = final2[(size_t)b * 64 + j];
    }
    __syncthreads();
    if (tid < 64) xs[192 + tid] = xs[64 + tid] * xs[128 + tid];
    __syncthreads();

    {
        float a0 = b1[tid], a1 = 0.0f;
#pragma unroll 8
        for (int k = 0; k < 320; k += 2) {
            a0 = fmaf(xs[k],     W1[k * 128 + tid],       a0);
            a1 = fmaf(xs[k + 1], W1[(k + 1) * 128 + tid], a1);
        }
        float h = a0 + a1;
        h1s[tid] = (h >= 0.0f) ? h : p1[tid] * h;
    }
    __syncthreads();

    if (tid < 40) {
        float a0 = b2[tid], a1 = 0.0f;
#pragma unroll 16
        for (int k = 0; k < 128; k += 2) {
            a0 = fmaf(h1s[k],     W2[k * 40 + tid],       a0);
            a1 = fmaf(h1s[k + 1], W2[(k + 1) * 40 + tid], a1);
        }
        float h = a0 + a1;
        h2s[tid] = (h >= 0.0f) ? h : p2[tid] * h;
    }
    __syncthreads();

    if (tid == 0) {
        float acc = b3[0];
#pragma unroll
        for (int k = 0; k < 40; k++) acc = fmaf(h2s[k], W3[k], acc);
        out[b] = acc;
    }
}

// ======================================================================
extern "C" void kernel_launch(void* const* d_in, const int* in_sizes, int n_in,
                              void* d_out, int out_size)
{
    const int*   u        = (const int*)d_in[0];
    const int*   ii       = (const int*)d_in[1];
    const int*   hist_i   = (const int*)d_in[2];
    const float* mask     = (const float*)d_in[3];
    const float* item_emb = (const float*)d_in[4];
    const float* user_emb = (const float*)d_in[5];
    const float* g1_Wg = (const float*)d_in[6];
    const float* g1_Ug = (const float*)d_in[7];
    const float* g1_bg = (const float*)d_in[8];
    const float* g1_Wc = (const float*)d_in[9];
    const float* g1_Uc = (const float*)d_in[10];
    const float* g1_bc = (const float*)d_in[11];
    const float* Wa1 = (const float*)d_in[12];
    const float* ba1 = (const float*)d_in[13];
    const float* Wa2 = (const float*)d_in[14];
    const float* ba2 = (const float*)d_in[15];
    const float* Wa3 = (const float*)d_in[16];
    const float* ba3 = (const float*)d_in[17];
    const float* g2_Wg = (const float*)d_in[18];
    const float* g2_Ug = (const float*)d_in[19];
    const float* g2_bg = (const float*)d_in[20];
    const float* g2_Wc = (const float*)d_in[21];
    const float* g2_Uc = (const float*)d_in[22];
    const float* g2_bc = (const float*)d_in[23];
    const float* W1 = (const float*)d_in[24];
    const float* b1 = (const float*)d_in[25];
    const float* p1 = (const float*)d_in[26];
    const float* W2 = (const float*)d_in[27];
    const float* b2 = (const float*)d_in[28];
    const float* p2 = (const float*)d_in[29];
    const float* W3 = (const float*)d_in[30];
    const float* b3 = (const float*)d_in[31];
    float* out = (float*)d_out;

    float *xg, *xc, *rnn1, *alpha, *final2;
    __nv_bfloat16 *bh1, *bl1, *bh2, *bl2;
    cudaGetSymbolAddress((void**)&xg,     g_xg);
    cudaGetSymbolAddress((void**)&xc,     g_xc);
    cudaGetSymbolAddress((void**)&rnn1,   g_rnn1);
    cudaGetSymbolAddress((void**)&alpha,  g_alpha);
    cudaGetSymbolAddress((void**)&final2, g_final2);
    cudaGetSymbolAddress((void**)&bh1, g_bh1);
    cudaGetSymbolAddress((void**)&bl1, g_bl1);
    cudaGetSymbolAddress((void**)&bh2, g_bh2);
    cudaGetSymbolAddress((void**)&bl2, g_bl2);

    const int GRU_SMEM  = (128 * 68 + 64 * 72 + GR * 64 + GR * 72 + GR * 64 + GR * T) * 4; // 69248
    const int ATTN_SMEM = (64*80 + 80 + 80*40 + 40 + 40 + 64
                         + 32*68 + 32*80 + 32*40 + 224 + 16) * 4;

    cudaFuncSetAttribute(proj_mma_kernel<0>, cudaFuncAttributeMaxDynamicSharedMemorySize, PSM_TOTAL);
    cudaFuncSetAttribute(proj_mma_kernel<1>, cudaFuncAttributeMaxDynamicSharedMemorySize, PSM_TOTAL);
    cudaFuncSetAttribute(gru_kernel<true>,  cudaFuncAttributeMaxDynamicSharedMemorySize, GRU_SMEM);
    cudaFuncSetAttribute(gru_kernel<false>, cudaFuncAttributeMaxDynamicSharedMemorySize, GRU_SMEM);
    cudaFuncSetAttribute(attn_kernel, cudaFuncAttributeMaxDynamicSharedMemorySize, ATTN_SMEM);

    const int GRU_GRID = (B + GR - 1) / GR;   // 410

    // 0) split projection weights to bf16 hi/lo (both GRUs)
    wsplit_kernel<<<48, 256>>>(g1_Wg, g1_Wc, bh1, bl1);
    wsplit_kernel<<<48, 256>>>(g2_Wg, g2_Wc, bh2, bl2);
    // 1) GRU1 input projections via HMMA tensor cores
    proj_mma_kernel<0><<<BT / 128, 256, PSM_TOTAL>>>(item_emb, hist_i, nullptr,
                                                     bh1, bl1, g1_bg, g1_bc, xg, xc);
    // 2) GRU1 recurrence -> rnn1
    gru_kernel<true><<<GRU_GRID, 256, GRU_SMEM>>>(xg, xc, mask, g1_Ug, g1_Uc, rnn1);
    // 3) DIN attention -> alpha
    attn_kernel<<<B, 320, ATTN_SMEM>>>(ii, item_emb, rnn1, mask,
                                       Wa1, ba1, Wa2, ba2, Wa3, ba3, alpha);
    // 4) GRU2 input projections via HMMA (rnn1 * alpha)
    proj_mma_kernel<1><<<BT / 128, 256, PSM_TOTAL>>>(rnn1, nullptr, alpha,
                                                     bh2, bl2, g2_bg, g2_bc, xg, xc);
    // 5) GRU2 recurrence -> final2 only
    gru_kernel<false><<<GRU_GRID, 256, GRU_SMEM>>>(xg, xc, mask, g2_Ug, g2_Uc, final2);
    // 6) FCN head -> logits
    fcn_kernel<<<B, 128>>>(u, ii, hist_i, item_emb, user_emb, final2,
                           W1, b1, p1, W2, b2, p2, W3, b3, out);
}

// round 11
// speedup vs baseline: 1.1315x; 1.1315x over previous
#include <cuda_runtime.h>
#include <cuda_bf16.h>
#include <math.h>
#include <float.h>
#include <cstdint>

#define B 4096
#define T 200
#define BT (B*T)
#define GR 10   // batch rows per GRU block

// ---------------- scratch (device globals: no allocs allowed) ----------------
__device__ float g_xg[(size_t)BT * 128];
__device__ float g_xc[(size_t)BT * 64];
__device__ float g_rnn1[(size_t)BT * 64];
__device__ float g_alpha[BT];
__device__ float g_final2[B * 64];
// split-bf16 weights for the two projection GEMMs: layout [n(192)][k(64)]
__device__ __nv_bfloat16 g_bh1[192 * 64];
__device__ __nv_bfloat16 g_bl1[192 * 64];
__device__ __nv_bfloat16 g_bh2[192 * 64];
__device__ __nv_bfloat16 g_bl2[192 * 64];

__device__ __forceinline__ float sigmoidf_fast(float x) {
    return 1.0f / (1.0f + __expf(-x));
}
__device__ __forceinline__ float tanh_fast(float x) {
    float ax = fabsf(x);
    float e = __expf(-2.0f * ax);
    float th = __fdividef(1.0f - e, 1.0f + e);
    return copysignf(th, x);
}

__device__ __forceinline__ uint32_t smem_u32(const void* p) {
    uint32_t a;
    asm("{ .reg .u64 t; cvta.to.shared.u64 t, %1; cvt.u32.u64 %0, t; }" : "=r"(a) : "l"(p));
    return a;
}
__device__ __forceinline__ void ldsm_x4(uint32_t& r0, uint32_t& r1, uint32_t& r2, uint32_t& r3,
                                        uint32_t addr) {
    asm volatile("ldmatrix.sync.aligned.m8n8.x4.shared.b16 {%0,%1,%2,%3}, [%4];"
                 : "=r"(r0), "=r"(r1), "=r"(r2), "=r"(r3) : "r"(addr));
}
__device__ __forceinline__ void mma16816(float* c, const uint32_t* a, uint32_t b0, uint32_t b1) {
    asm volatile("mma.sync.aligned.m16n8k16.row.col.f32.bf16.bf16.f32 "
                 "{%0,%1,%2,%3}, {%4,%5,%6,%7}, {%8,%9}, {%0,%1,%2,%3};"
                 : "+f"(c[0]), "+f"(c[1]), "+f"(c[2]), "+f"(c[3])
                 : "r"(a[0]), "r"(a[1]), "r"(a[2]), "r"(a[3]), "r"(b0), "r"(b1));
}
// split-bf16 pair store helper (two adjacent cols)
__device__ __forceinline__ void store_bf16_pair(char* basep, int byteoff, float v0, float v1,
                                                char* basel, float l0, float l1) {
    __nv_bfloat162 h, l;
    h.x = __float2bfloat16(v0); h.y = __float2bfloat16(v1);
    l.x = __float2bfloat16(l0); l.y = __float2bfloat16(l1);
    *(__nv_bfloat162*)(basep + byteoff) = h;
    *(__nv_bfloat162*)(basel + byteoff) = l;
}

// ======================================================================
// Weight split prep: W[64,128]|[64,64] fp32 -> Bhi/Blo [n=192][k=64] bf16
// ======================================================================
__global__ void wsplit_kernel(const float* __restrict__ Wg, const float* __restrict__ Wc,
                              __nv_bfloat16* __restrict__ Bhi, __nv_bfloat16* __restrict__ Blo)
{
    int idx = blockIdx.x * 256 + threadIdx.x;
    if (idx >= 192 * 64) return;
    int n = idx >> 6, k = idx & 63;
    float w = (n < 128) ? Wg[k * 128 + n] : Wc[k * 64 + (n - 128)];
    __nv_bfloat16 hi = __float2bfloat16(w);
    __nv_bfloat16 lo = __float2bfloat16(w - __bfloat162float(hi));
    Bhi[idx] = hi;
    Blo[idx] = lo;
}

// ======================================================================
// HMMA projection (unchanged, passing).
// ======================================================================
#define PAD_K 72
#define PSM_BIAS 0
#define PSM_AHI  768
#define PSM_ALO  (PSM_AHI + 128 * PAD_K * 2)
#define PSM_BHI  (PSM_ALO + 128 * PAD_K * 2)
#define PSM_BLO  (PSM_BHI + 192 * PAD_K * 2)
#define PSM_TOTAL (PSM_BLO + 192 * PAD_K * 2)   // 92928 bytes

template<int MODE>
__global__ void __launch_bounds__(256, 2) proj_mma_kernel(
        const float* __restrict__ src,
        const int*   __restrict__ hist_i,
        const float* __restrict__ alpha,
        const __nv_bfloat16* __restrict__ Bhi,
        const __nv_bfloat16* __restrict__ Blo,
        const float* __restrict__ bg,
        const float* __restrict__ bc,
        float* __restrict__ xg,
        float* __restrict__ xc)
{
    extern __shared__ char smem[];
    const uint32_t sbase = smem_u32(smem);
    const int tid = threadIdx.x;
    const int wid = tid >> 5;
    const int lane = tid & 31;
    const int m0 = blockIdx.x * 128;

    float* bs = (float*)(smem + PSM_BIAS);
    if (tid < 192) bs[tid] = (tid < 128) ? bg[tid] : bc[tid - 128];

    {
        const uint4* sh = (const uint4*)Bhi;
        const uint4* sl = (const uint4*)Blo;
#pragma unroll
        for (int i = 0; i < 6; i++) {
            int idx = tid + 256 * i;
            int n = idx >> 3, seg = idx & 7;
            int off = n * (PAD_K * 2) + seg * 16;
            *(uint4*)(smem + PSM_BHI + off) = sh[idx];
            *(uint4*)(smem + PSM_BLO + off) = sl[idx];
        }
    }

    {
        const int r = tid >> 1;
        const int half = tid & 1;
        const float* srow;
        float scale = 1.0f;
        if (MODE == 0) {
            srow = src + (size_t)hist_i[m0 + r] * 64;
        } else {
            srow = src + (size_t)(m0 + r) * 64;
            scale = alpha[m0 + r];
        }
        srow += half * 32;
        const int kb = half * 32;
#pragma unroll
        for (int c = 0; c < 4; c++) {
            float4 v0 = *(const float4*)(srow + 8 * c);
            float4 v1 = *(const float4*)(srow + 8 * c + 4);
            float vv[8] = {v0.x, v0.y, v0.z, v0.w, v1.x, v1.y, v1.z, v1.w};
            __nv_bfloat16 hb[8], lb[8];
#pragma unroll
            for (int e = 0; e < 8; e++) {
                float f = vv[e] * scale;
                hb[e] = __float2bfloat16(f);
                lb[e] = __float2bfloat16(f - __bfloat162float(hb[e]));
            }
            int off = r * (PAD_K * 2) + (kb + 8 * c) * 2;
            *(uint4*)(smem + PSM_AHI + off) = *(uint4*)hb;
            *(uint4*)(smem + PSM_ALO + off) = *(uint4*)lb;
        }
    }
    __syncthreads();

    const int arow = wid * 16 + (lane & 15);
    const int acolb = ((lane >> 4) << 3);
    const uint32_t a_off = (uint32_t)arow * (PAD_K * 2) + acolb * 2;
    const uint32_t aH_base = sbase + PSM_AHI + a_off;
    const uint32_t aL_base = sbase + PSM_ALO + a_off;

    const int bnrow_l = (lane & 7) + ((lane & 16) >> 1);
    const int bcol_l = (lane & 8);
    const uint32_t b_off_l = (uint32_t)bnrow_l * (PAD_K * 2) + bcol_l * 2;

    const int g = lane >> 2;
    const int tq = lane & 3;

#pragma unroll
    for (int nh = 0; nh < 2; nh++) {
        const uint32_t bH_base = sbase + PSM_BHI + b_off_l + (uint32_t)nh * 96 * (PAD_K * 2);
        const uint32_t bL_base = sbase + PSM_BLO + b_off_l + (uint32_t)nh * 96 * (PAD_K * 2);

        float acc[12][4];
#pragma unroll
        for (int i = 0; i < 12; i++)
#pragma unroll
            for (int qq = 0; qq < 4; qq++) acc[i][qq] = 0.0f;

#pragma unroll
        for (int ks = 0; ks < 4; ks++) {
            uint32_t aH[4], aL[4];
            ldsm_x4(aH[0], aH[1], aH[2], aH[3], aH_base + ks * 32);
            ldsm_x4(aL[0], aL[1], aL[2], aL[3], aL_base + ks * 32);
#pragma unroll
            for (int np = 0; np < 6; np++) {
                uint32_t bh0, bh1, bh2, bh3;
                ldsm_x4(bh0, bh1, bh2, bh3,
                        bH_base + (uint32_t)np * 16 * (PAD_K * 2) + ks * 32);
                mma16816(acc[2 * np],     aH, bh0, bh1);
                mma16816(acc[2 * np + 1], aH, bh2, bh3);
                mma16816(acc[2 * np],     aL, bh0, bh1);
                mma16816(acc[2 * np + 1], aL, bh2, bh3);
                uint32_t bl0, bl1, bl2, bl3;
                ldsm_x4(bl0, bl1, bl2, bl3,
                        bL_base + (uint32_t)np * 16 * (PAD_K * 2) + ks * 32);
                mma16816(acc[2 * np],     aH, bl0, bl1);
                mma16816(acc[2 * np + 1], aH, bl2, bl3);
            }
        }

        const int r0 = m0 + wid * 16 + g;
        const int r1 = r0 + 8;
#pragma unroll
        for (int nt = 0; nt < 12; nt++) {
            const int n = nh * 96 + nt * 8 + 2 * tq;
            const float bx = bs[n], by = bs[n + 1];
            float2 o0 = make_float2(acc[nt][0] + bx, acc[nt][1] + by);
            float2 o1 = make_float2(acc[nt][2] + bx, acc[nt][3] + by);
            if (n < 128) {
                *(float2*)(xg + (size_t)r0 * 128 + n) = o0;
                *(float2*)(xg + (size_t)r1 * 128 + n) = o1;
            } else {
                *(float2*)(xc + (size_t)r0 * 64 + (n - 128)) = o0;
                *(float2*)(xc + (size_t)r1 * 64 + (n - 128)) = o1;
            }
        }
    }
}

// ======================================================================
// GRU recurrence — exact R7 version (3573 µs baseline).
// ======================================================================
template<bool STORE_ALL>
__global__ void __launch_bounds__(128) gru_kernel(
                           const float* __restrict__ xg,
                           const float* __restrict__ xc,
                           const float* __restrict__ mask,
                           const float* __restrict__ Ug,  // [64,128]
                           const float* __restrict__ Uc,  // [64,64]
                           float* __restrict__ out)
{
    extern __shared__ float sm[];
    float* UgsT = sm;                     // [128][68]
    float* UcsT = UgsT + 128 * 68;        // [64][72] split layout
    float* hs   = UcsT + 64 * 72;         // [GR][64]
    float* rhs  = hs + GR * 64;           // [GR][72] split layout
    float* zs   = rhs + GR * 72;          // [GR][64]
    float* msk  = zs + GR * 64;           // [GR][T]

    const int j = threadIdx.x;
    const int b0 = blockIdx.x * GR;
    const int c = j >> 1;
    const int half = j & 1;

    for (int idx = j; idx < 128 * 64; idx += 128) {
        int k = idx >> 7, jj = idx & 127;
        UgsT[jj * 68 + k] = Ug[idx];
    }
    for (int idx = j; idx < 64 * 64; idx += 128) {
        int k = idx >> 6, cc = idx & 63;
        UcsT[cc * 72 + (k >> 5) * 36 + (k & 31)] = Uc[idx];
    }
    for (int idx = j; idx < GR * 64; idx += 128) hs[idx] = 0.0f;

    int br[GR];
    bool val[GR];
#pragma unroll
    for (int r = 0; r < GR; r++) {
        int b = b0 + r;
        val[r] = (b < B);
        br[r] = val[r] ? b : (B - 1);
    }

    for (int idx = j; idx < GR * T; idx += 128) {
        int r = idx / T, t = idx - r * T;
        msk[idx] = mask[(size_t)br[r] * T + t];
    }
    __syncthreads();

    float xgv[GR];
#pragma unroll
    for (int r = 0; r < GR; r++)
        xgv[r] = xg[(size_t)br[r] * T * 128 + j];

    const float* wc_base = UcsT + c * 72 + half * 36;

    for (int t = 0; t < T; t++) {
        float acc[GR];
#pragma unroll
        for (int r = 0; r < GR; r++) acc[r] = xgv[r];

#pragma unroll 4
        for (int k4 = 0; k4 < 16; k4++) {
            float4 w = *(const float4*)(UgsT + j * 68 + 4 * k4);
#pragma unroll
            for (int r = 0; r < GR; r++) {
                float4 h4 = *(const float4*)(hs + r * 64 + 4 * k4);
                acc[r] = fmaf(h4.x, w.x, acc[r]);
                acc[r] = fmaf(h4.y, w.y, acc[r]);
                acc[r] = fmaf(h4.z, w.z, acc[r]);
                acc[r] = fmaf(h4.w, w.w, acc[r]);
            }
        }

        if (t + 1 < T) {
#pragma unroll
            for (int r = 0; r < GR; r++)
                xgv[r] = xg[(size_t)br[r] * T * 128 + (t + 1) * 128 + j];
        }

#pragma unroll
        for (int r = 0; r < GR; r++) {
            float g = sigmoidf_fast(acc[r]);
            if (j < 64) rhs[r * 72 + (j >> 5) * 36 + (j & 31)] = g * hs[r * 64 + j];
            else        zs[r * 64 + (j - 64)] = g;
        }
        __syncthreads();

        {
            float cacc[GR];
#pragma unroll
            for (int r = 0; r < GR; r++)
                cacc[r] = (half == 0) ? xc[(size_t)br[r] * T * 64 + t * 64 + c] : 0.0f;

#pragma unroll 4
            for (int k4 = 0; k4 < 8; k4++) {
                float4 w = *(const float4*)(wc_base + 4 * k4);
#pragma unroll
                for (int r = 0; r < GR; r++) {
                    float4 rh = *(const float4*)(rhs + r * 72 + half * 36 + 4 * k4);
                    cacc[r] = fmaf(rh.x, w.x, cacc[r]);
                    cacc[r] = fmaf(rh.y, w.y, cacc[r]);
                    cacc[r] = fmaf(rh.z, w.z, cacc[r]);
                    cacc[r] = fmaf(rh.w, w.w, cacc[r]);
                }
            }

#pragma unroll
            for (int r = 0; r < GR; r++) {
                float tot = cacc[r] + __shfl_xor_sync(0xffffffffu, cacc[r], 1);
                float cc = tanhf(tot);
                float z = zs[r * 64 + c];
                float h = hs[r * 64 + c];
                float hn = fmaf(z, h - cc, cc);
                float m = msk[r * T + t];
                float hnew = fmaf(m, hn - h, h);
                if (half == 0) {
                    hs[r * 64 + c] = hnew;
                    if (STORE_ALL && val[r])
                        out[(size_t)br[r] * T * 64 + t * 64 + c] = hnew;
                }
            }
        }
        __syncthreads();
    }

    if (!STORE_ALL && j < 64) {
#pragma unroll
        for (int r = 0; r < GR; r++)
            if (val[r]) out[(size_t)br[r] * 64 + j] = hs[r * 64 + j];
    }
}

// ======================================================================
// DIN attention via HMMA. One CTA (256 thr) per batch row.
//  layer1: K[208x64] @ WeffT[80x64]  (split-bf16, 3-term)
//  layer2: d1[208x80] @ Wa2T[48x80]  (split-bf16, 3-term)
//  layer3: in-register dot + quad-shfl reduce -> masked scores -> softmax
// ======================================================================
#define AT_ROWS 208
#define APK  72     // k-pad for K/WeffT (144 B rows)
#define APK2 88     // k-pad for d1/Wa2T (176 B rows)

#define ASM_QS    0
#define ASM_BASE  (64 * 4)
#define ASM_BA2   (ASM_BASE + 96 * 4)
#define ASM_WA3   (ASM_BA2 + 48 * 4)
#define ASM_SC    (ASM_WA3 + 40 * 4)
#define ASM_RED   (ASM_SC + 208 * 4)
#define ASM_KHI   2048
#define ASM_KLO   (ASM_KHI + AT_ROWS * APK * 2)
#define ASM_WHI   (ASM_KLO + AT_ROWS * APK * 2)
#define ASM_WLO   (ASM_WHI + 80 * APK * 2)
#define ASM_W2HI  (ASM_WLO + 80 * APK * 2)
#define ASM_W2LO  (ASM_W2HI + 48 * APK2 * 2)
#define ASM_D1HI  (ASM_W2LO + 48 * APK2 * 2)
#define ASM_D1LO  (ASM_D1HI + AT_ROWS * APK2 * 2)
#define ASM_TOTAL (ASM_D1LO + AT_ROWS * APK2 * 2)   // 175104 bytes

__global__ void __launch_bounds__(256, 1) attn_mma_kernel(
        const int*   __restrict__ item_i,
        const float* __restrict__ item_emb,
        const float* __restrict__ rnn1,
        const float* __restrict__ mask,
        const float* __restrict__ Wa1, const float* __restrict__ ba1,
        const float* __restrict__ Wa2, const float* __restrict__ ba2,
        const float* __restrict__ Wa3, const float* __restrict__ ba3,
        float* __restrict__ alpha)
{
    extern __shared__ char smem[];
    const uint32_t sbase = smem_u32(smem);
    const int b = blockIdx.x;
    const int tid = threadIdx.x;
    const int wid = tid >> 5, lane = tid & 31;

    float* qs   = (float*)(smem + ASM_QS);
    float* base = (float*)(smem + ASM_BASE);
    float* ba2s = (float*)(smem + ASM_BA2);
    float* wa3s = (float*)(smem + ASM_WA3);
    float* sc   = (float*)(smem + ASM_SC);
    float* red  = (float*)(smem + ASM_RED);

    if (tid < 64) qs[tid] = item_emb[(size_t)item_i[b] * 64 + tid];
    if (tid >= 64 && tid < 112) ba2s[tid - 64] = (tid - 64 < 40) ? ba2[tid - 64] : 0.0f;
    if (tid >= 112 && tid < 152) wa3s[tid - 112] = Wa3[tid - 112];
    // zero K pad rows 200..207 (both planes): 8 rows x 9 uint4
    for (int i = tid; i < 72; i += 256) {
        int r = 200 + i / 9, s = i % 9;
        *(uint4*)(smem + ASM_KHI + r * 144 + s * 16) = make_uint4(0, 0, 0, 0);
        *(uint4*)(smem + ASM_KLO + r * 144 + s * 16) = make_uint4(0, 0, 0, 0);
    }
    // zero Wa2T pad rows 40..47: 8 rows x 11 uint4
    for (int i = tid; i < 88; i += 256) {
        int r = 40 + i / 11, s = i % 11;
        *(uint4*)(smem + ASM_W2HI + r * 176 + s * 16) = make_uint4(0, 0, 0, 0);
        *(uint4*)(smem + ASM_W2LO + r * 176 + s * 16) = make_uint4(0, 0, 0, 0);
    }
    __syncthreads();   // qs ready

    // base[c] = ba1[c] + q @ (W0 + W2)
    if (tid < 80) {
        float acc = ba1[tid];
#pragma unroll 8
        for (int k = 0; k < 64; k++)
            acc = fmaf(qs[k], Wa1[k * 80 + tid] + Wa1[(128 + k) * 80 + tid], acc);
        base[tid] = acc;
    }
    // WeffT[c][k] = (W1 - W2)[k][c] + q_k * W3[k][c], split bf16
    for (int idx = tid; idx < 5120; idx += 256) {
        int k = idx / 80, c = idx - k * 80;
        float w = Wa1[(64 + k) * 80 + c] - Wa1[(128 + k) * 80 + c]
                + qs[k] * Wa1[(192 + k) * 80 + c];
        __nv_bfloat16 hi = __float2bfloat16(w);
        __nv_bfloat16 lo = __float2bfloat16(w - __bfloat162float(hi));
        *(__nv_bfloat16*)(smem + ASM_WHI + c * 144 + k * 2) = hi;
        *(__nv_bfloat16*)(smem + ASM_WLO + c * 144 + k * 2) = lo;
    }
    // Wa2T[n][k], split bf16 (Wa2 global is [80][40])
    for (int idx = tid; idx < 3200; idx += 256) {
        int k = idx / 40, n = idx - k * 40;
        float w = Wa2[idx];
        __nv_bfloat16 hi = __float2bfloat16(w);
        __nv_bfloat16 lo = __float2bfloat16(w - __bfloat162float(hi));
        *(__nv_bfloat16*)(smem + ASM_W2HI + n * 176 + k * 2) = hi;
        *(__nv_bfloat16*)(smem + ASM_W2LO + n * 176 + k * 2) = lo;
    }
    // K = rnn1[b] [200 x 64] -> split bf16
    for (int idx = tid; idx < 3200; idx += 256) {
        int r = idx >> 4, c4 = idx & 15;
        float4 v = *(const float4*)(rnn1 + ((size_t)b * T + r) * 64 + c4 * 4);
        __nv_bfloat16 h[4], l[4];
        h[0] = __float2bfloat16(v.x); l[0] = __float2bfloat16(v.x - __bfloat162float(h[0]));
        h[1] = __float2bfloat16(v.y); l[1] = __float2bfloat16(v.y - __bfloat162float(h[1]));
        h[2] = __float2bfloat16(v.z); l[2] = __float2bfloat16(v.z - __bfloat162float(h[2]));
        h[3] = __float2bfloat16(v.w); l[3] = __float2bfloat16(v.w - __bfloat162float(h[3]));
        int off = r * 144 + c4 * 8;
        *(uint2*)(smem + ASM_KHI + off) = *(uint2*)h;
        *(uint2*)(smem + ASM_KLO + off) = *(uint2*)l;
    }
    __syncthreads();

    const int arow_l = lane & 15;
    const int acolb  = (lane >> 4) << 3;
    const int bnrow_l = (lane & 7) + ((lane & 16) >> 1);
    const int bcol_l  = lane & 8;
    const int g = lane >> 2, q = lane & 3;
    const float ba3v = ba3[0];

    // ---------------- layer 1 ----------------
    for (int mt = wid; mt < 13; mt += 8) {
        float acc[10][4];
#pragma unroll
        for (int nt = 0; nt < 10; nt++) {
            float b0 = base[nt * 8 + 2 * q], b1 = base[nt * 8 + 2 * q + 1];
            acc[nt][0] = b0; acc[nt][1] = b1; acc[nt][2] = b0; acc[nt][3] = b1;
        }
        const uint32_t aHb = sbase + ASM_KHI + (uint32_t)(mt * 16 + arow_l) * 144 + acolb * 2;
        const uint32_t aLb = sbase + ASM_KLO + (uint32_t)(mt * 16 + arow_l) * 144 + acolb * 2;
        const uint32_t bHb = sbase + ASM_WHI + (uint32_t)bnrow_l * 144 + bcol_l * 2;
        const uint32_t bLb = sbase + ASM_WLO + (uint32_t)bnrow_l * 144 + bcol_l * 2;
#pragma unroll
        for (int ks = 0; ks < 4; ks++) {
            uint32_t aH[4], aL[4];
            ldsm_x4(aH[0], aH[1], aH[2], aH[3], aHb + ks * 32);
            ldsm_x4(aL[0], aL[1], aL[2], aL[3], aLb + ks * 32);
#pragma unroll
            for (int np = 0; np < 5; np++) {
                uint32_t b0, b1, b2, b3;
                ldsm_x4(b0, b1, b2, b3, bHb + (uint32_t)np * 16 * 144 + ks * 32);
                mma16816(acc[2 * np],     aH, b0, b1);
                mma16816(acc[2 * np + 1], aH, b2, b3);
                mma16816(acc[2 * np],     aL, b0, b1);
                mma16816(acc[2 * np + 1], aL, b2, b3);
                ldsm_x4(b0, b1, b2, b3, bLb + (uint32_t)np * 16 * 144 + ks * 32);
                mma16816(acc[2 * np],     aH, b0, b1);
                mma16816(acc[2 * np + 1], aH, b2, b3);
            }
        }
        // epilogue: sigmoid -> split bf16 -> d1
        const int r0 = mt * 16 + g, r1 = r0 + 8;
#pragma unroll
        for (int nt = 0; nt < 10; nt++) {
            const int c0 = nt * 8 + 2 * q;
            float s00 = sigmoidf_fast(acc[nt][0]);
            float s01 = sigmoidf_fast(acc[nt][1]);
            float s10 = sigmoidf_fast(acc[nt][2]);
            float s11 = sigmoidf_fast(acc[nt][3]);
            __nv_bfloat16 h00 = __float2bfloat16(s00), h01 = __float2bfloat16(s01);
            __nv_bfloat16 h10 = __float2bfloat16(s10), h11 = __float2bfloat16(s11);
            store_bf16_pair(smem + ASM_D1HI, r0 * 176 + c0 * 2, s00, s01,
                            smem + ASM_D1LO,
                            s00 - __bfloat162float(h00), s01 - __bfloat162float(h01));
            store_bf16_pair(smem + ASM_D1HI, r1 * 176 + c0 * 2, s10, s11,
                            smem + ASM_D1LO,
                            s10 - __bfloat162float(h10), s11 - __bfloat162float(h11));
        }
    }
    __syncthreads();

    // ---------------- layer 2 + layer 3 ----------------
    for (int mt = wid; mt < 13; mt += 8) {
        float acc[6][4];
#pragma unroll
        for (int nt = 0; nt < 6; nt++) {
            float b0 = ba2s[nt * 8 + 2 * q], b1 = ba2s[nt * 8 + 2 * q + 1];
            acc[nt][0] = b0; acc[nt][1] = b1; acc[nt][2] = b0; acc[nt][3] = b1;
        }
        const uint32_t aHb = sbase + ASM_D1HI + (uint32_t)(mt * 16 + arow_l) * 176 + acolb * 2;
        const uint32_t aLb = sbase + ASM_D1LO + (uint32_t)(mt * 16 + arow_l) * 176 + acolb * 2;
        const uint32_t bHb = sbase + ASM_W2HI + (uint32_t)bnrow_l * 176 + bcol_l * 2;
        const uint32_t bLb = sbase + ASM_W2LO + (uint32_t)bnrow_l * 176 + bcol_l * 2;
#pragma unroll
        for (int ks = 0; ks < 5; ks++) {
            uint32_t aH[4], aL[4];
            ldsm_x4(aH[0], aH[1], aH[2], aH[3], aHb + ks * 32);
            ldsm_x4(aL[0], aL[1], aL[2], aL[3], aLb + ks * 32);
#pragma unroll
            for (int np = 0; np < 3; np++) {
                uint32_t b0, b1, b2, b3;
                ldsm_x4(b0, b1, b2, b3, bHb + (uint32_t)np * 16 * 176 + ks * 32);
                mma16816(acc[2 * np],     aH, b0, b1);
                mma16816(acc[2 * np + 1], aH, b2, b3);
                mma16816(acc[2 * np],     aL, b0, b1);
                mma16816(acc[2 * np + 1], aL, b2, b3);
                ldsm_x4(b0, b1, b2, b3, bLb + (uint32_t)np * 16 * 176 + ks * 32);
                mma16816(acc[2 * np],     aH, b0, b1);
                mma16816(acc[2 * np + 1], aH, b2, b3);
            }
        }
        // layer 3: dot with Wa3 over valid cols (nt 0..4), quad reduce
        float s0 = 0.0f, s1 = 0.0f;
#pragma unroll
        for (int nt = 0; nt < 5; nt++) {
            const int c0 = nt * 8 + 2 * q;
            float w0 = wa3s[c0], w1 = wa3s[c0 + 1];
            s0 = fmaf(sigmoidf_fast(acc[nt][0]), w0, s0);
            s0 = fmaf(sigmoidf_fast(acc[nt][1]), w1, s0);
            s1 = fmaf(sigmoidf_fast(acc[nt][2]), w0, s1);
            s1 = fmaf(sigmoidf_fast(acc[nt][3]), w1, s1);
        }
        s0 += __shfl_xor_sync(0xffffffffu, s0, 1);
        s0 += __shfl_xor_sync(0xffffffffu, s0, 2);
        s1 += __shfl_xor_sync(0xffffffffu, s1, 1);
        s1 += __shfl_xor_sync(0xffffffffu, s1, 2);
        if (q == 0) {
            int t0 = mt * 16 + g, t1 = t0 + 8;
            if (t0 < T) {
                float m = mask[(size_t)b * T + t0];
                sc[t0] = (m > 0.0f) ? (s0 + ba3v) : -1e9f;
            }
            if (t1 < T) {
                float m = mask[(size_t)b * T + t1];
                sc[t1] = (m > 0.0f) ? (s1 + ba3v) : -1e9f;
            }
        }
    }
    __syncthreads();

    // ---------------- masked softmax over T=200 (8 warps) ----------------
    float v = (tid < T) ? sc[tid] : -FLT_MAX;
#pragma unroll
    for (int o = 16; o > 0; o >>= 1) v = fmaxf(v, __shfl_xor_sync(0xffffffffu, v, o));
    if (lane == 0) red[wid] = v;
    __syncthreads();
    if (tid == 0) {
        float mx = red[0];
#pragma unroll
        for (int w = 1; w < 8; w++) mx = fmaxf(mx, red[w]);
        red[12] = mx;
    }
    __syncthreads();
    float mx = red[12];

    float e = (tid < T) ? __expf(sc[tid] - mx) : 0.0f;
    float s = e;
#pragma unroll
    for (int o = 16; o > 0; o >>= 1) s += __shfl_xor_sync(0xffffffffu, s, o);
    __syncthreads();
    if (lane == 0) red[wid] = s;
    __syncthreads();
    if (tid == 0) {
        float sum = 0.0f;
#pragma unroll
        for (int w = 0; w < 8; w++) sum += red[w];
        red[13] = 1.0f / sum;
    }
    __syncthreads();
    if (tid < T) alpha[(size_t)b * T + tid] = e * red[13];
}

// ======================================================================
// FCN head + hist_sum (unchanged).
// ======================================================================
__global__ void fcn_kernel(const int* __restrict__ u, const int* __restrict__ ii,
                           const int* __restrict__ hist_i,
                           const float* __restrict__ item_emb,
                           const float* __restrict__ user_emb,
                           const float* __restrict__ final2,
                           const float* __restrict__ W1, const float* __restrict__ b1,
                           const float* __restrict__ p1,
                           const float* __restrict__ W2, const float* __restrict__ b2,
                           const float* __restrict__ p2,
                           const float* __restrict__ W3, const float* __restrict__ b3,
                           float* __restrict__ out)
{
    __shared__ float xs[320];
    __shared__ float h1s[128];
    __shared__ float h2s[40];

    const int b = blockIdx.x;
    const int tid = threadIdx.x;

    if (tid < 64) {
        const int* hi = hist_i + (size_t)b * T;
        float s0 = 0.f, s1 = 0.f, s2 = 0.f, s3 = 0.f;
        for (int t = 0; t < T; t += 4) {
            s0 += item_emb[(size_t)hi[t]     * 64 + tid];
            s1 += item_emb[(size_t)hi[t + 1] * 64 + tid];
            s2 += item_emb[(size_t)hi[t + 2] * 64 + tid];
            s3 += item_emb[(size_t)hi[t + 3] * 64 + tid];
        }
        xs[128 + tid] = (s0 + s1) + (s2 + s3);
    } else {
        int j = tid - 64;
        xs[j]       = user_emb[(size_t)u[b]  * 64 + j];
        xs[64 + j]  = item_emb[(size_t)ii[b] * 64 + j];
        xs[256 + j] = final2[(size_t)b * 64 + j];
    }
    __syncthreads();
    if (tid < 64) xs[192 + tid] = xs[64 + tid] * xs[128 + tid];
    __syncthreads();

    {
        float a0 = b1[tid], a1 = 0.0f;
#pragma unroll 8
        for (int k = 0; k < 320; k += 2) {
            a0 = fmaf(xs[k],     W1[k * 128 + tid],       a0);
            a1 = fmaf(xs[k + 1], W1[(k + 1) * 128 + tid], a1);
        }
        float h = a0 + a1;
        h1s[tid] = (h >= 0.0f) ? h : p1[tid] * h;
    }
    __syncthreads();

    if (tid < 40) {
        float a0 = b2[tid], a1 = 0.0f;
#pragma unroll 16
        for (int k = 0; k < 128; k += 2) {
            a0 = fmaf(h1s[k],     W2[k * 40 + tid],       a0);
            a1 = fmaf(h1s[k + 1], W2[(k + 1) * 40 + tid], a1);
        }
        float h = a0 + a1;
        h2s[tid] = (h >= 0.0f) ? h : p2[tid] * h;
    }
    __syncthreads();

    if (tid == 0) {
        float acc = b3[0];
#pragma unroll
        for (int k = 0; k < 40; k++) acc = fmaf(h2s[k], W3[k], acc);
        out[b] = acc;
    }
}

// ======================================================================
extern "C" void kernel_launch(void* const* d_in, const int* in_sizes, int n_in,
                              void* d_out, int out_size)
{
    const int*   u        = (const int*)d_in[0];
    const int*   ii       = (const int*)d_in[1];
    const int*   hist_i   = (const int*)d_in[2];
    const float* mask     = (const float*)d_in[3];
    const float* item_emb = (const float*)d_in[4];
    const float* user_emb = (const float*)d_in[5];
    const float* g1_Wg = (const float*)d_in[6];
    const float* g1_Ug = (const float*)d_in[7];
    const float* g1_bg = (const float*)d_in[8];
    const float* g1_Wc = (const float*)d_in[9];
    const float* g1_Uc = (const float*)d_in[10];
    const float* g1_bc = (const float*)d_in[11];
    const float* Wa1 = (const float*)d_in[12];
    const float* ba1 = (const float*)d_in[13];
    const float* Wa2 = (const float*)d_in[14];
    const float* ba2 = (const float*)d_in[15];
    const float* Wa3 = (const float*)d_in[16];
    const float* ba3 = (const float*)d_in[17];
    const float* g2_Wg = (const float*)d_in[18];
    const float* g2_Ug = (const float*)d_in[19];
    const float* g2_bg = (const float*)d_in[20];
    const float* g2_Wc = (const float*)d_in[21];
    const float* g2_Uc = (const float*)d_in[22];
    const float* g2_bc = (const float*)d_in[23];
    const float* W1 = (const float*)d_in[24];
    const float* b1 = (const float*)d_in[25];
    const float* p1 = (const float*)d_in[26];
    const float* W2 = (const float*)d_in[27];
    const float* b2 = (const float*)d_in[28];
    const float* p2 = (const float*)d_in[29];
    const float* W3 = (const float*)d_in[30];
    const float* b3 = (const float*)d_in[31];
    float* out = (float*)d_out;

    float *xg, *xc, *rnn1, *alpha, *final2;
    __nv_bfloat16 *bh1, *bl1, *bh2, *bl2;
    cudaGetSymbolAddress((void**)&xg,     g_xg);
    cudaGetSymbolAddress((void**)&xc,     g_xc);
    cudaGetSymbolAddress((void**)&rnn1,   g_rnn1);
    cudaGetSymbolAddress((void**)&alpha,  g_alpha);
    cudaGetSymbolAddress((void**)&final2, g_final2);
    cudaGetSymbolAddress((void**)&bh1, g_bh1);
    cudaGetSymbolAddress((void**)&bl1, g_bl1);
    cudaGetSymbolAddress((void**)&bh2, g_bh2);
    cudaGetSymbolAddress((void**)&bl2, g_bl2);

    const int GRU_SMEM = (128 * 68 + 64 * 72 + GR * 64 + GR * 72 + GR * 64 + GR * T) * 4;

    cudaFuncSetAttribute(proj_mma_kernel<0>, cudaFuncAttributeMaxDynamicSharedMemorySize, PSM_TOTAL);
    cudaFuncSetAttribute(proj_mma_kernel<1>, cudaFuncAttributeMaxDynamicSharedMemorySize, PSM_TOTAL);
    cudaFuncSetAttribute(gru_kernel<true>,  cudaFuncAttributeMaxDynamicSharedMemorySize, GRU_SMEM);
    cudaFuncSetAttribute(gru_kernel<false>, cudaFuncAttributeMaxDynamicSharedMemorySize, GRU_SMEM);
    cudaFuncSetAttribute(attn_mma_kernel, cudaFuncAttributeMaxDynamicSharedMemorySize, ASM_TOTAL);

    const int GRU_GRID = (B + GR - 1) / GR;   // 410

    // 0) split projection weights to bf16 hi/lo (both GRUs)
    wsplit_kernel<<<48, 256>>>(g1_Wg, g1_Wc, bh1, bl1);
    wsplit_kernel<<<48, 256>>>(g2_Wg, g2_Wc, bh2, bl2);
    // 1) GRU1 input projections via HMMA
    proj_mma_kernel<0><<<BT / 128, 256, PSM_TOTAL>>>(item_emb, hist_i, nullptr,
                                                     bh1, bl1, g1_bg, g1_bc, xg, xc);
    // 2) GRU1 recurrence -> rnn1
    gru_kernel<true><<<GRU_GRID, 128, GRU_SMEM>>>(xg, xc, mask, g1_Ug, g1_Uc, rnn1);
    // 3) DIN attention via HMMA -> alpha
    attn_mma_kernel<<<B, 256, ASM_TOTAL>>>(ii, item_emb, rnn1, mask,
                                           Wa1, ba1, Wa2, ba2, Wa3, ba3, alpha);
    // 4) GRU2 input projections via HMMA (rnn1 * alpha)
    proj_mma_kernel<1><<<BT / 128, 256, PSM_TOTAL>>>(rnn1, nullptr, alpha,
                                                     bh2, bl2, g2_bg, g2_bc, xg, xc);
    // 5) GRU2 recurrence -> final2 only
    gru_kernel<false><<<GRU_GRID, 128, GRU_SMEM>>>(xg, xc, mask, g2_Ug, g2_Uc, final2);
    // 6) FCN head -> logits
    fcn_kernel<<<B, 128>>>(u, ii, hist_i, item_emb, user_emb, final2,
                           W1, b1, p1, W2, b2, p2, W3, b3, out);
}

// round 12
// speedup vs baseline: 1.2599x; 1.1135x over previous
#include <cuda_runtime.h>
#include <cuda_bf16.h>
#include <math.h>
#include <float.h>
#include <cstdint>

#define B 4096
#define T 200
#define BT (B*T)
#define GR 10   // batch rows per GRU block

// ---------------- scratch (device globals: no allocs allowed) ----------------
__device__ float g_xg[(size_t)BT * 128];
__device__ float g_xc[(size_t)BT * 64];
__device__ float g_rnn1[(size_t)BT * 64];
__device__ float g_alpha[BT];
__device__ float g_final2[B * 64];
// split-bf16 weights for the two projection GEMMs: layout [n(192)][k(64)]
__device__ __nv_bfloat16 g_bh1[192 * 64];
__device__ __nv_bfloat16 g_bl1[192 * 64];
__device__ __nv_bfloat16 g_bh2[192 * 64];
__device__ __nv_bfloat16 g_bl2[192 * 64];

__device__ __forceinline__ float sigmoidf_fast(float x) {
    return 1.0f / (1.0f + __expf(-x));
}
__device__ __forceinline__ float tanh_fast(float x) {
    float ax = fabsf(x);
    float e = __expf(-2.0f * ax);
    float th = __fdividef(1.0f - e, 1.0f + e);
    return copysignf(th, x);
}

__device__ __forceinline__ uint32_t smem_u32(const void* p) {
    uint32_t a;
    asm("{ .reg .u64 t; cvta.to.shared.u64 t, %1; cvt.u32.u64 %0, t; }" : "=r"(a) : "l"(p));
    return a;
}
__device__ __forceinline__ void ldsm_x4(uint32_t& r0, uint32_t& r1, uint32_t& r2, uint32_t& r3,
                                        uint32_t addr) {
    asm volatile("ldmatrix.sync.aligned.m8n8.x4.shared.b16 {%0,%1,%2,%3}, [%4];"
                 : "=r"(r0), "=r"(r1), "=r"(r2), "=r"(r3) : "r"(addr));
}
__device__ __forceinline__ void mma16816(float* c, const uint32_t* a, uint32_t b0, uint32_t b1) {
    asm volatile("mma.sync.aligned.m16n8k16.row.col.f32.bf16.bf16.f32 "
                 "{%0,%1,%2,%3}, {%4,%5,%6,%7}, {%8,%9}, {%0,%1,%2,%3};"
                 : "+f"(c[0]), "+f"(c[1]), "+f"(c[2]), "+f"(c[3])
                 : "r"(a[0]), "r"(a[1]), "r"(a[2]), "r"(a[3]), "r"(b0), "r"(b1));
}
__device__ __forceinline__ void store_bf16_pair(char* basep, int byteoff, float v0, float v1,
                                                char* basel, float l0, float l1) {
    __nv_bfloat162 h, l;
    h.x = __float2bfloat16(v0); h.y = __float2bfloat16(v1);
    l.x = __float2bfloat16(l0); l.y = __float2bfloat16(l1);
    *(__nv_bfloat162*)(basep + byteoff) = h;
    *(__nv_bfloat162*)(basel + byteoff) = l;
}

// ======================================================================
// Weight split prep: W[64,128]|[64,64] fp32 -> Bhi/Blo [n=192][k=64] bf16
// ======================================================================
__global__ void wsplit_kernel(const float* __restrict__ Wg, const float* __restrict__ Wc,
                              __nv_bfloat16* __restrict__ Bhi, __nv_bfloat16* __restrict__ Blo)
{
    int idx = blockIdx.x * 256 + threadIdx.x;
    if (idx >= 192 * 64) return;
    int n = idx >> 6, k = idx & 63;
    float w = (n < 128) ? Wg[k * 128 + n] : Wc[k * 64 + (n - 128)];
    __nv_bfloat16 hi = __float2bfloat16(w);
    __nv_bfloat16 lo = __float2bfloat16(w - __bfloat162float(hi));
    Bhi[idx] = hi;
    Blo[idx] = lo;
}

// ======================================================================
// HMMA projection (unchanged, passing).
// ======================================================================
#define PAD_K 72
#define PSM_BIAS 0
#define PSM_AHI  768
#define PSM_ALO  (PSM_AHI + 128 * PAD_K * 2)
#define PSM_BHI  (PSM_ALO + 128 * PAD_K * 2)
#define PSM_BLO  (PSM_BHI + 192 * PAD_K * 2)
#define PSM_TOTAL (PSM_BLO + 192 * PAD_K * 2)   // 92928 bytes

template<int MODE>
__global__ void __launch_bounds__(256, 2) proj_mma_kernel(
        const float* __restrict__ src,
        const int*   __restrict__ hist_i,
        const float* __restrict__ alpha,
        const __nv_bfloat16* __restrict__ Bhi,
        const __nv_bfloat16* __restrict__ Blo,
        const float* __restrict__ bg,
        const float* __restrict__ bc,
        float* __restrict__ xg,
        float* __restrict__ xc)
{
    extern __shared__ char smem[];
    const uint32_t sbase = smem_u32(smem);
    const int tid = threadIdx.x;
    const int wid = tid >> 5;
    const int lane = tid & 31;
    const int m0 = blockIdx.x * 128;

    float* bs = (float*)(smem + PSM_BIAS);
    if (tid < 192) bs[tid] = (tid < 128) ? bg[tid] : bc[tid - 128];

    {
        const uint4* sh = (const uint4*)Bhi;
        const uint4* sl = (const uint4*)Blo;
#pragma unroll
        for (int i = 0; i < 6; i++) {
            int idx = tid + 256 * i;
            int n = idx >> 3, seg = idx & 7;
            int off = n * (PAD_K * 2) + seg * 16;
            *(uint4*)(smem + PSM_BHI + off) = sh[idx];
            *(uint4*)(smem + PSM_BLO + off) = sl[idx];
        }
    }

    {
        const int r = tid >> 1;
        const int half = tid & 1;
        const float* srow;
        float scale = 1.0f;
        if (MODE == 0) {
            srow = src + (size_t)hist_i[m0 + r] * 64;
        } else {
            srow = src + (size_t)(m0 + r) * 64;
            scale = alpha[m0 + r];
        }
        srow += half * 32;
        const int kb = half * 32;
#pragma unroll
        for (int c = 0; c < 4; c++) {
            float4 v0 = *(const float4*)(srow + 8 * c);
            float4 v1 = *(const float4*)(srow + 8 * c + 4);
            float vv[8] = {v0.x, v0.y, v0.z, v0.w, v1.x, v1.y, v1.z, v1.w};
            __nv_bfloat16 hb[8], lb[8];
#pragma unroll
            for (int e = 0; e < 8; e++) {
                float f = vv[e] * scale;
                hb[e] = __float2bfloat16(f);
                lb[e] = __float2bfloat16(f - __bfloat162float(hb[e]));
            }
            int off = r * (PAD_K * 2) + (kb + 8 * c) * 2;
            *(uint4*)(smem + PSM_AHI + off) = *(uint4*)hb;
            *(uint4*)(smem + PSM_ALO + off) = *(uint4*)lb;
        }
    }
    __syncthreads();

    const int arow = wid * 16 + (lane & 15);
    const int acolb = ((lane >> 4) << 3);
    const uint32_t a_off = (uint32_t)arow * (PAD_K * 2) + acolb * 2;
    const uint32_t aH_base = sbase + PSM_AHI + a_off;
    const uint32_t aL_base = sbase + PSM_ALO + a_off;

    const int bnrow_l = (lane & 7) + ((lane & 16) >> 1);
    const int bcol_l = (lane & 8);
    const uint32_t b_off_l = (uint32_t)bnrow_l * (PAD_K * 2) + bcol_l * 2;

    const int g = lane >> 2;
    const int tq = lane & 3;

#pragma unroll
    for (int nh = 0; nh < 2; nh++) {
        const uint32_t bH_base = sbase + PSM_BHI + b_off_l + (uint32_t)nh * 96 * (PAD_K * 2);
        const uint32_t bL_base = sbase + PSM_BLO + b_off_l + (uint32_t)nh * 96 * (PAD_K * 2);

        float acc[12][4];
#pragma unroll
        for (int i = 0; i < 12; i++)
#pragma unroll
            for (int qq = 0; qq < 4; qq++) acc[i][qq] = 0.0f;

#pragma unroll
        for (int ks = 0; ks < 4; ks++) {
            uint32_t aH[4], aL[4];
            ldsm_x4(aH[0], aH[1], aH[2], aH[3], aH_base + ks * 32);
            ldsm_x4(aL[0], aL[1], aL[2], aL[3], aL_base + ks * 32);
#pragma unroll
            for (int np = 0; np < 6; np++) {
                uint32_t bh0, bh1, bh2, bh3;
                ldsm_x4(bh0, bh1, bh2, bh3,
                        bH_base + (uint32_t)np * 16 * (PAD_K * 2) + ks * 32);
                mma16816(acc[2 * np],     aH, bh0, bh1);
                mma16816(acc[2 * np + 1], aH, bh2, bh3);
                mma16816(acc[2 * np],     aL, bh0, bh1);
                mma16816(acc[2 * np + 1], aL, bh2, bh3);
                uint32_t bl0, bl1, bl2, bl3;
                ldsm_x4(bl0, bl1, bl2, bl3,
                        bL_base + (uint32_t)np * 16 * (PAD_K * 2) + ks * 32);
                mma16816(acc[2 * np],     aH, bl0, bl1);
                mma16816(acc[2 * np + 1], aH, bl2, bl3);
            }
        }

        const int r0 = m0 + wid * 16 + g;
        const int r1 = r0 + 8;
#pragma unroll
        for (int nt = 0; nt < 12; nt++) {
            const int n = nh * 96 + nt * 8 + 2 * tq;
            const float bx = bs[n], by = bs[n + 1];
            float2 o0 = make_float2(acc[nt][0] + bx, acc[nt][1] + by);
            float2 o1 = make_float2(acc[nt][2] + bx, acc[nt][3] + by);
            if (n < 128) {
                *(float2*)(xg + (size_t)r0 * 128 + n) = o0;
                *(float2*)(xg + (size_t)r1 * 128 + n) = o1;
            } else {
                *(float2*)(xc + (size_t)r0 * 64 + (n - 128)) = o0;
                *(float2*)(xc + (size_t)r1 * 64 + (n - 128)) = o1;
            }
        }
    }
}

// ======================================================================
// GRU recurrence — R7 version (best SIMT variant), tanh_fast micro-opt.
// ======================================================================
template<bool STORE_ALL>
__global__ void __launch_bounds__(128) gru_kernel(
                           const float* __restrict__ xg,
                           const float* __restrict__ xc,
                           const float* __restrict__ mask,
                           const float* __restrict__ Ug,  // [64,128]
                           const float* __restrict__ Uc,  // [64,64]
                           float* __restrict__ out)
{
    extern __shared__ float sm[];
    float* UgsT = sm;                     // [128][68]
    float* UcsT = UgsT + 128 * 68;        // [64][72] split layout
    float* hs   = UcsT + 64 * 72;         // [GR][64]
    float* rhs  = hs + GR * 64;           // [GR][72] split layout
    float* zs   = rhs + GR * 72;          // [GR][64]
    float* msk  = zs + GR * 64;           // [GR][T]

    const int j = threadIdx.x;
    const int b0 = blockIdx.x * GR;
    const int c = j >> 1;
    const int half = j & 1;

    for (int idx = j; idx < 128 * 64; idx += 128) {
        int k = idx >> 7, jj = idx & 127;
        UgsT[jj * 68 + k] = Ug[idx];
    }
    for (int idx = j; idx < 64 * 64; idx += 128) {
        int k = idx >> 6, cc = idx & 63;
        UcsT[cc * 72 + (k >> 5) * 36 + (k & 31)] = Uc[idx];
    }
    for (int idx = j; idx < GR * 64; idx += 128) hs[idx] = 0.0f;

    int br[GR];
    bool val[GR];
#pragma unroll
    for (int r = 0; r < GR; r++) {
        int b = b0 + r;
        val[r] = (b < B);
        br[r] = val[r] ? b : (B - 1);
    }

    for (int idx = j; idx < GR * T; idx += 128) {
        int r = idx / T, t = idx - r * T;
        msk[idx] = mask[(size_t)br[r] * T + t];
    }
    __syncthreads();

    float xgv[GR];
#pragma unroll
    for (int r = 0; r < GR; r++)
        xgv[r] = xg[(size_t)br[r] * T * 128 + j];

    const float* wc_base = UcsT + c * 72 + half * 36;

    for (int t = 0; t < T; t++) {
        float acc[GR];
#pragma unroll
        for (int r = 0; r < GR; r++) acc[r] = xgv[r];

#pragma unroll 4
        for (int k4 = 0; k4 < 16; k4++) {
            float4 w = *(const float4*)(UgsT + j * 68 + 4 * k4);
#pragma unroll
            for (int r = 0; r < GR; r++) {
                float4 h4 = *(const float4*)(hs + r * 64 + 4 * k4);
                acc[r] = fmaf(h4.x, w.x, acc[r]);
                acc[r] = fmaf(h4.y, w.y, acc[r]);
                acc[r] = fmaf(h4.z, w.z, acc[r]);
                acc[r] = fmaf(h4.w, w.w, acc[r]);
            }
        }

        if (t + 1 < T) {
#pragma unroll
            for (int r = 0; r < GR; r++)
                xgv[r] = xg[(size_t)br[r] * T * 128 + (t + 1) * 128 + j];
        }

#pragma unroll
        for (int r = 0; r < GR; r++) {
            float g = sigmoidf_fast(acc[r]);
            if (j < 64) rhs[r * 72 + (j >> 5) * 36 + (j & 31)] = g * hs[r * 64 + j];
            else        zs[r * 64 + (j - 64)] = g;
        }
        __syncthreads();

        {
            float cacc[GR];
#pragma unroll
            for (int r = 0; r < GR; r++)
                cacc[r] = (half == 0) ? xc[(size_t)br[r] * T * 64 + t * 64 + c] : 0.0f;

#pragma unroll 4
            for (int k4 = 0; k4 < 8; k4++) {
                float4 w = *(const float4*)(wc_base + 4 * k4);
#pragma unroll
                for (int r = 0; r < GR; r++) {
                    float4 rh = *(const float4*)(rhs + r * 72 + half * 36 + 4 * k4);
                    cacc[r] = fmaf(rh.x, w.x, cacc[r]);
                    cacc[r] = fmaf(rh.y, w.y, cacc[r]);
                    cacc[r] = fmaf(rh.z, w.z, cacc[r]);
                    cacc[r] = fmaf(rh.w, w.w, cacc[r]);
                }
            }

#pragma unroll
            for (int r = 0; r < GR; r++) {
                float tot = cacc[r] + __shfl_xor_sync(0xffffffffu, cacc[r], 1);
                float cc = tanh_fast(tot);
                float z = zs[r * 64 + c];
                float h = hs[r * 64 + c];
                float hn = fmaf(z, h - cc, cc);
                float m = msk[r * T + t];
                float hnew = fmaf(m, hn - h, h);
                if (half == 0) {
                    hs[r * 64 + c] = hnew;
                    if (STORE_ALL && val[r])
                        out[(size_t)br[r] * T * 64 + t * 64 + c] = hnew;
                }
            }
        }
        __syncthreads();
    }

    if (!STORE_ALL && j < 64) {
#pragma unroll
        for (int r = 0; r < GR; r++)
            if (val[r]) out[(size_t)br[r] * 64 + j] = hs[r * 64 + j];
    }
}

// ======================================================================
// DIN attention via HMMA, chunked to 2x112 rows -> 113.7 KB smem
// -> 2 CTAs/SM. Same fragment machinery as R11 (validated).
// ======================================================================
#define ACH 112       // rows per chunk (7 m-tiles)
#define APK  72       // k-pad for K/WeffT (144 B rows)
#define APK2 88       // k-pad for d1/Wa2T (176 B rows)

#define ASM_QS    0
#define ASM_BASE  256
#define ASM_BA2   640
#define ASM_WA3   832
#define ASM_SC    992                 // 224 floats
#define ASM_RED   1888
#define ASM_KHI   2048
#define ASM_KLO   (ASM_KHI + ACH * APK * 2)      // +16128
#define ASM_WHI   (ASM_KLO + ACH * APK * 2)
#define ASM_WLO   (ASM_WHI + 80 * APK * 2)       // +11520
#define ASM_W2HI  (ASM_WLO + 80 * APK * 2)
#define ASM_W2LO  (ASM_W2HI + 48 * APK2 * 2)     // +8448
#define ASM_D1HI  (ASM_W2LO + 48 * APK2 * 2)
#define ASM_D1LO  (ASM_D1HI + ACH * APK2 * 2)    // +19712
#define ASM_TOTAL (ASM_D1LO + ACH * APK2 * 2)    // 113664 bytes

__global__ void __launch_bounds__(256, 2) attn_mma_kernel(
        const int*   __restrict__ item_i,
        const float* __restrict__ item_emb,
        const float* __restrict__ rnn1,
        const float* __restrict__ mask,
        const float* __restrict__ Wa1, const float* __restrict__ ba1,
        const float* __restrict__ Wa2, const float* __restrict__ ba2,
        const float* __restrict__ Wa3, const float* __restrict__ ba3,
        float* __restrict__ alpha)
{
    extern __shared__ char smem[];
    const uint32_t sbase = smem_u32(smem);
    const int b = blockIdx.x;
    const int tid = threadIdx.x;
    const int wid = tid >> 5, lane = tid & 31;

    float* qs   = (float*)(smem + ASM_QS);
    float* base = (float*)(smem + ASM_BASE);
    float* ba2s = (float*)(smem + ASM_BA2);
    float* wa3s = (float*)(smem + ASM_WA3);
    float* sc   = (float*)(smem + ASM_SC);
    float* red  = (float*)(smem + ASM_RED);

    if (tid < 64) qs[tid] = item_emb[(size_t)item_i[b] * 64 + tid];
    if (tid >= 64 && tid < 112) ba2s[tid - 64] = (tid - 64 < 40) ? ba2[tid - 64] : 0.0f;
    if (tid >= 112 && tid < 152) wa3s[tid - 112] = Wa3[tid - 112];
    // zero Wa2T pad rows 40..47: 8 rows x 11 uint4
    for (int i = tid; i < 88; i += 256) {
        int r = 40 + i / 11, s = i % 11;
        *(uint4*)(smem + ASM_W2HI + r * 176 + s * 16) = make_uint4(0, 0, 0, 0);
        *(uint4*)(smem + ASM_W2LO + r * 176 + s * 16) = make_uint4(0, 0, 0, 0);
    }
    __syncthreads();   // qs ready

    // base[c] = ba1[c] + q @ (W0 + W2)
    if (tid < 80) {
        float acc = ba1[tid];
#pragma unroll 8
        for (int k = 0; k < 64; k++)
            acc = fmaf(qs[k], Wa1[k * 80 + tid] + Wa1[(128 + k) * 80 + tid], acc);
        base[tid] = acc;
    }
    // WeffT[c][k] = (W1 - W2)[k][c] + q_k * W3[k][c], split bf16
    for (int idx = tid; idx < 5120; idx += 256) {
        int k = idx / 80, c = idx - k * 80;
        float w = Wa1[(64 + k) * 80 + c] - Wa1[(128 + k) * 80 + c]
                + qs[k] * Wa1[(192 + k) * 80 + c];
        __nv_bfloat16 hi = __float2bfloat16(w);
        __nv_bfloat16 lo = __float2bfloat16(w - __bfloat162float(hi));
        *(__nv_bfloat16*)(smem + ASM_WHI + c * 144 + k * 2) = hi;
        *(__nv_bfloat16*)(smem + ASM_WLO + c * 144 + k * 2) = lo;
    }
    // Wa2T[n][k], split bf16 (Wa2 global is [80][40])
    for (int idx = tid; idx < 3200; idx += 256) {
        int k = idx / 40, n = idx - k * 40;
        float w = Wa2[idx];
        __nv_bfloat16 hi = __float2bfloat16(w);
        __nv_bfloat16 lo = __float2bfloat16(w - __bfloat162float(hi));
        *(__nv_bfloat16*)(smem + ASM_W2HI + n * 176 + k * 2) = hi;
        *(__nv_bfloat16*)(smem + ASM_W2LO + n * 176 + k * 2) = lo;
    }

    const int arow_l = lane & 15;
    const int acolb  = (lane >> 4) << 3;
    const int bnrow_l = (lane & 7) + ((lane & 16) >> 1);
    const int bcol_l  = lane & 8;
    const int g = lane >> 2, q = lane & 3;
    const float ba3v = ba3[0];

    for (int cc = 0; cc < 2; cc++) {
        const int t0 = cc * ACH;

        // stage K chunk [t0, t0+112) -> split bf16 (clamped at T-1)
        __syncthreads();   // prior chunk's layer1 done reading K
        for (int idx = tid; idx < ACH * 16; idx += 256) {
            int r = idx >> 4, c4 = idx & 15;
            int tg = t0 + r; if (tg > T - 1) tg = T - 1;
            float4 v = *(const float4*)(rnn1 + ((size_t)b * T + tg) * 64 + c4 * 4);
            __nv_bfloat16 h[4], l[4];
            h[0] = __float2bfloat16(v.x); l[0] = __float2bfloat16(v.x - __bfloat162float(h[0]));
            h[1] = __float2bfloat16(v.y); l[1] = __float2bfloat16(v.y - __bfloat162float(h[1]));
            h[2] = __float2bfloat16(v.z); l[2] = __float2bfloat16(v.z - __bfloat162float(h[2]));
            h[3] = __float2bfloat16(v.w); l[3] = __float2bfloat16(v.w - __bfloat162float(h[3]));
            int off = r * 144 + c4 * 8;
            *(uint2*)(smem + ASM_KHI + off) = *(uint2*)h;
            *(uint2*)(smem + ASM_KLO + off) = *(uint2*)l;
        }
        __syncthreads();

        // ---------------- layer 1 (7 m-tiles over 8 warps) ----------------
        for (int mt = wid; mt < 7; mt += 8) {
            float acc[10][4];
#pragma unroll
            for (int nt = 0; nt < 10; nt++) {
                float b0 = base[nt * 8 + 2 * q], b1 = base[nt * 8 + 2 * q + 1];
                acc[nt][0] = b0; acc[nt][1] = b1; acc[nt][2] = b0; acc[nt][3] = b1;
            }
            const uint32_t aHb = sbase + ASM_KHI + (uint32_t)(mt * 16 + arow_l) * 144 + acolb * 2;
            const uint32_t aLb = sbase + ASM_KLO + (uint32_t)(mt * 16 + arow_l) * 144 + acolb * 2;
            const uint32_t bHb = sbase + ASM_WHI + (uint32_t)bnrow_l * 144 + bcol_l * 2;
            const uint32_t bLb = sbase + ASM_WLO + (uint32_t)bnrow_l * 144 + bcol_l * 2;
#pragma unroll
            for (int ks = 0; ks < 4; ks++) {
                uint32_t aH[4], aL[4];
                ldsm_x4(aH[0], aH[1], aH[2], aH[3], aHb + ks * 32);
                ldsm_x4(aL[0], aL[1], aL[2], aL[3], aLb + ks * 32);
#pragma unroll
                for (int np = 0; np < 5; np++) {
                    uint32_t b0, b1, b2, b3;
                    ldsm_x4(b0, b1, b2, b3, bHb + (uint32_t)np * 16 * 144 + ks * 32);
                    mma16816(acc[2 * np],     aH, b0, b1);
                    mma16816(acc[2 * np + 1], aH, b2, b3);
                    mma16816(acc[2 * np],     aL, b0, b1);
                    mma16816(acc[2 * np + 1], aL, b2, b3);
                    ldsm_x4(b0, b1, b2, b3, bLb + (uint32_t)np * 16 * 144 + ks * 32);
                    mma16816(acc[2 * np],     aH, b0, b1);
                    mma16816(acc[2 * np + 1], aH, b2, b3);
                }
            }
            const int r0 = mt * 16 + g, r1 = r0 + 8;
#pragma unroll
            for (int nt = 0; nt < 10; nt++) {
                const int c0 = nt * 8 + 2 * q;
                float s00 = sigmoidf_fast(acc[nt][0]);
                float s01 = sigmoidf_fast(acc[nt][1]);
                float s10 = sigmoidf_fast(acc[nt][2]);
                float s11 = sigmoidf_fast(acc[nt][3]);
                __nv_bfloat16 h00 = __float2bfloat16(s00), h01 = __float2bfloat16(s01);
                __nv_bfloat16 h10 = __float2bfloat16(s10), h11 = __float2bfloat16(s11);
                store_bf16_pair(smem + ASM_D1HI, r0 * 176 + c0 * 2, s00, s01,
                                smem + ASM_D1LO,
                                s00 - __bfloat162float(h00), s01 - __bfloat162float(h01));
                store_bf16_pair(smem + ASM_D1HI, r1 * 176 + c0 * 2, s10, s11,
                                smem + ASM_D1LO,
                                s10 - __bfloat162float(h10), s11 - __bfloat162float(h11));
            }
        }
        __syncthreads();

        // ---------------- layer 2 + layer 3 ----------------
        for (int mt = wid; mt < 7; mt += 8) {
            float acc[6][4];
#pragma unroll
            for (int nt = 0; nt < 6; nt++) {
                float b0 = ba2s[nt * 8 + 2 * q], b1 = ba2s[nt * 8 + 2 * q + 1];
                acc[nt][0] = b0; acc[nt][1] = b1; acc[nt][2] = b0; acc[nt][3] = b1;
            }
            const uint32_t aHb = sbase + ASM_D1HI + (uint32_t)(mt * 16 + arow_l) * 176 + acolb * 2;
            const uint32_t aLb = sbase + ASM_D1LO + (uint32_t)(mt * 16 + arow_l) * 176 + acolb * 2;
            const uint32_t bHb = sbase + ASM_W2HI + (uint32_t)bnrow_l * 176 + bcol_l * 2;
            const uint32_t bLb = sbase + ASM_W2LO + (uint32_t)bnrow_l * 176 + bcol_l * 2;
#pragma unroll
            for (int ks = 0; ks < 5; ks++) {
                uint32_t aH[4], aL[4];
                ldsm_x4(aH[0], aH[1], aH[2], aH[3], aHb + ks * 32);
                ldsm_x4(aL[0], aL[1], aL[2], aL[3], aLb + ks * 32);
#pragma unroll
                for (int np = 0; np < 3; np++) {
                    uint32_t b0, b1, b2, b3;
                    ldsm_x4(b0, b1, b2, b3, bHb + (uint32_t)np * 16 * 176 + ks * 32);
                    mma16816(acc[2 * np],     aH, b0, b1);
                    mma16816(acc[2 * np + 1], aH, b2, b3);
                    mma16816(acc[2 * np],     aL, b0, b1);
                    mma16816(acc[2 * np + 1], aL, b2, b3);
                    ldsm_x4(b0, b1, b2, b3, bLb + (uint32_t)np * 16 * 176 + ks * 32);
                    mma16816(acc[2 * np],     aH, b0, b1);
                    mma16816(acc[2 * np + 1], aH, b2, b3);
                }
            }
            // layer 3: dot with Wa3 (valid cols nt 0..4), quad reduce
            float s0 = 0.0f, s1 = 0.0f;
#pragma unroll
            for (int nt = 0; nt < 5; nt++) {
                const int c0 = nt * 8 + 2 * q;
                float w0 = wa3s[c0], w1 = wa3s[c0 + 1];
                s0 = fmaf(sigmoidf_fast(acc[nt][0]), w0, s0);
                s0 = fmaf(sigmoidf_fast(acc[nt][1]), w1, s0);
                s1 = fmaf(sigmoidf_fast(acc[nt][2]), w0, s1);
                s1 = fmaf(sigmoidf_fast(acc[nt][3]), w1, s1);
            }
            s0 += __shfl_xor_sync(0xffffffffu, s0, 1);
            s0 += __shfl_xor_sync(0xffffffffu, s0, 2);
            s1 += __shfl_xor_sync(0xffffffffu, s1, 1);
            s1 += __shfl_xor_sync(0xffffffffu, s1, 2);
            if (q == 0) {
                int t0g = t0 + mt * 16 + g, t1g = t0g + 8;
                if (t0g < T) {
                    float m = mask[(size_t)b * T + t0g];
                    sc[t0g] = (m > 0.0f) ? (s0 + ba3v) : -1e9f;
                }
                if (t1g < T) {
                    float m = mask[(size_t)b * T + t1g];
                    sc[t1g] = (m > 0.0f) ? (s1 + ba3v) : -1e9f;
                }
            }
        }
    }
    __syncthreads();

    // ---------------- masked softmax over T=200 (8 warps) ----------------
    float v = (tid < T) ? sc[tid] : -FLT_MAX;
#pragma unroll
    for (int o = 16; o > 0; o >>= 1) v = fmaxf(v, __shfl_xor_sync(0xffffffffu, v, o));
    if (lane == 0) red[wid] = v;
    __syncthreads();
    if (tid == 0) {
        float mx = red[0];
#pragma unroll
        for (int w = 1; w < 8; w++) mx = fmaxf(mx, red[w]);
        red[12] = mx;
    }
    __syncthreads();
    float mx = red[12];

    float e = (tid < T) ? __expf(sc[tid] - mx) : 0.0f;
    float s = e;
#pragma unroll
    for (int o = 16; o > 0; o >>= 1) s += __shfl_xor_sync(0xffffffffu, s, o);
    __syncthreads();
    if (lane == 0) red[wid] = s;
    __syncthreads();
    if (tid == 0) {
        float sum = 0.0f;
#pragma unroll
        for (int w = 0; w < 8; w++) sum += red[w];
        red[13] = 1.0f / sum;
    }
    __syncthreads();
    if (tid < T) alpha[(size_t)b * T + tid] = e * red[13];
}

// ======================================================================
// FCN head + hist_sum (unchanged).
// ======================================================================
__global__ void fcn_kernel(const int* __restrict__ u, const int* __restrict__ ii,
                           const int* __restrict__ hist_i,
                           const float* __restrict__ item_emb,
                           const float* __restrict__ user_emb,
                           const float* __restrict__ final2,
                           const float* __restrict__ W1, const float* __restrict__ b1,
                           const float* __restrict__ p1,
                           const float* __restrict__ W2, const float* __restrict__ b2,
                           const float* __restrict__ p2,
                           const float* __restrict__ W3, const float* __restrict__ b3,
                           float* __restrict__ out)
{
    __shared__ float xs[320];
    __shared__ float h1s[128];
    __shared__ float h2s[40];

    const int b = blockIdx.x;
    const int tid = threadIdx.x;

    if (tid < 64) {
        const int* hi = hist_i + (size_t)b * T;
        float s0 = 0.f, s1 = 0.f, s2 = 0.f, s3 = 0.f;
        for (int t = 0; t < T; t += 4) {
            s0 += item_emb[(size_t)hi[t]     * 64 + tid];
            s1 += item_emb[(size_t)hi[t + 1] * 64 + tid];
            s2 += item_emb[(size_t)hi[t + 2] * 64 + tid];
            s3 += item_emb[(size_t)hi[t + 3] * 64 + tid];
        }
        xs[128 + tid] = (s0 + s1) + (s2 + s3);
    } else {
        int j = tid - 64;
        xs[j]       = user_emb[(size_t)u[b]  * 64 + j];
        xs[64 + j]  = item_emb[(size_t)ii[b] * 64 + j];
        xs[256 + j] = final2[(size_t)b * 64 + j];
    }
    __syncthreads();
    if (tid < 64) xs[192 + tid] = xs[64 + tid] * xs[128 + tid];
    __syncthreads();

    {
        float a0 = b1[tid], a1 = 0.0f;
#pragma unroll 8
        for (int k = 0; k < 320; k += 2) {
            a0 = fmaf(xs[k],     W1[k * 128 + tid],       a0);
            a1 = fmaf(xs[k + 1], W1[(k + 1) * 128 + tid], a1);
        }
        float h = a0 + a1;
        h1s[tid] = (h >= 0.0f) ? h : p1[tid] * h;
    }
    __syncthreads();

    if (tid < 40) {
        float a0 = b2[tid], a1 = 0.0f;
#pragma unroll 16
        for (int k = 0; k < 128; k += 2) {
            a0 = fmaf(h1s[k],     W2[k * 40 + tid],       a0);
            a1 = fmaf(h1s[k + 1], W2[(k + 1) * 40 + tid], a1);
        }
        float h = a0 + a1;
        h2s[tid] = (h >= 0.0f) ? h : p2[tid] * h;
    }
    __syncthreads();

    if (tid == 0) {
        float acc = b3[0];
#pragma unroll
        for (int k = 0; k < 40; k++) acc = fmaf(h2s[k], W3[k], acc);
        out[b] = acc;
    }
}

// ======================================================================
extern "C" void kernel_launch(void* const* d_in, const int* in_sizes, int n_in,
                              void* d_out, int out_size)
{
    const int*   u        = (const int*)d_in[0];
    const int*   ii       = (const int*)d_in[1];
    const int*   hist_i   = (const int*)d_in[2];
    const float* mask     = (const float*)d_in[3];
    const float* item_emb = (const float*)d_in[4];
    const float* user_emb = (const float*)d_in[5];
    const float* g1_Wg = (const float*)d_in[6];
    const float* g1_Ug = (const float*)d_in[7];
    const float* g1_bg = (const float*)d_in[8];
    const float* g1_Wc = (const float*)d_in[9];
    const float* g1_Uc = (const float*)d_in[10];
    const float* g1_bc = (const float*)d_in[11];
    const float* Wa1 = (const float*)d_in[12];
    const float* ba1 = (const float*)d_in[13];
    const float* Wa2 = (const float*)d_in[14];
    const float* ba2 = (const float*)d_in[15];
    const float* Wa3 = (const float*)d_in[16];
    const float* ba3 = (const float*)d_in[17];
    const float* g2_Wg = (const float*)d_in[18];
    const float* g2_Ug = (const float*)d_in[19];
    const float* g2_bg = (const float*)d_in[20];
    const float* g2_Wc = (const float*)d_in[21];
    const float* g2_Uc = (const float*)d_in[22];
    const float* g2_bc = (const float*)d_in[23];
    const float* W1 = (const float*)d_in[24];
    const float* b1 = (const float*)d_in[25];
    const float* p1 = (const float*)d_in[26];
    const float* W2 = (const float*)d_in[27];
    const float* b2 = (const float*)d_in[28];
    const float* p2 = (const float*)d_in[29];
    const float* W3 = (const float*)d_in[30];
    const float* b3 = (const float*)d_in[31];
    float* out = (float*)d_out;

    float *xg, *xc, *rnn1, *alpha, *final2;
    __nv_bfloat16 *bh1, *bl1, *bh2, *bl2;
    cudaGetSymbolAddress((void**)&xg,     g_xg);
    cudaGetSymbolAddress((void**)&xc,     g_xc);
    cudaGetSymbolAddress((void**)&rnn1,   g_rnn1);
    cudaGetSymbolAddress((void**)&alpha,  g_alpha);
    cudaGetSymbolAddress((void**)&final2, g_final2);
    cudaGetSymbolAddress((void**)&bh1, g_bh1);
    cudaGetSymbolAddress((void**)&bl1, g_bl1);
    cudaGetSymbolAddress((void**)&bh2, g_bh2);
    cudaGetSymbolAddress((void**)&bl2, g_bl2);

    const int GRU_SMEM = (128 * 68 + 64 * 72 + GR * 64 + GR * 72 + GR * 64 + GR * T) * 4;

    cudaFuncSetAttribute(proj_mma_kernel<0>, cudaFuncAttributeMaxDynamicSharedMemorySize, PSM_TOTAL);
    cudaFuncSetAttribute(proj_mma_kernel<1>, cudaFuncAttributeMaxDynamicSharedMemorySize, PSM_TOTAL);
    cudaFuncSetAttribute(gru_kernel<true>,  cudaFuncAttributeMaxDynamicSharedMemorySize, GRU_SMEM);
    cudaFuncSetAttribute(gru_kernel<false>, cudaFuncAttributeMaxDynamicSharedMemorySize, GRU_SMEM);
    cudaFuncSetAttribute(attn_mma_kernel, cudaFuncAttributeMaxDynamicSharedMemorySize, ASM_TOTAL);

    const int GRU_GRID = (B + GR - 1) / GR;   // 410

    // 0) split projection weights to bf16 hi/lo (both GRUs)
    wsplit_kernel<<<48, 256>>>(g1_Wg, g1_Wc, bh1, bl1);
    wsplit_kernel<<<48, 256>>>(g2_Wg, g2_Wc, bh2, bl2);
    // 1) GRU1 input projections via HMMA
    proj_mma_kernel<0><<<BT / 128, 256, PSM_TOTAL>>>(item_emb, hist_i, nullptr,
                                                     bh1, bl1, g1_bg, g1_bc, xg, xc);
    // 2) GRU1 recurrence -> rnn1
    gru_kernel<true><<<GRU_GRID, 128, GRU_SMEM>>>(xg, xc, mask, g1_Ug, g1_Uc, rnn1);
    // 3) DIN attention via HMMA (chunked, 2 CTAs/SM) -> alpha
    attn_mma_kernel<<<B, 256, ASM_TOTAL>>>(ii, item_emb, rnn1, mask,
                                           Wa1, ba1, Wa2, ba2, Wa3, ba3, alpha);
    // 4) GRU2 input projections via HMMA (rnn1 * alpha)
    proj_mma_kernel<1><<<BT / 128, 256, PSM_TOTAL>>>(rnn1, nullptr, alpha,
                                                     bh2, bl2, g2_bg, g2_bc, xg, xc);
    // 5) GRU2 recurrence -> final2 only
    gru_kernel<false><<<GRU_GRID, 128, GRU_SMEM>>>(xg, xc, mask, g2_Ug, g2_Uc, final2);
    // 6) FCN head -> logits
    fcn_kernel<<<B, 128>>>(u, ii, hist_i, item_emb, user_emb, final2,
                           W1, b1, p1, W2, b2, p2, W3, b3, out);
}

// round 14
// speedup vs baseline: 1.6763x; 1.3305x over previous
#include <cuda_runtime.h>
#include <cuda_bf16.h>
#include <math.h>
#include <float.h>
#include <cstdint>

#define B 4096
#define T 200
#define BT (B*T)
#define GM 32   // batch rows per GRU-TC block (grid = 128)

// ---------------- scratch (device globals: no allocs allowed) ----------------
__device__ float g_xg[(size_t)BT * 128];
__device__ float g_xc[(size_t)BT * 64];
__device__ float g_rnn1[(size_t)BT * 64];
__device__ float g_alpha[BT];
__device__ float g_final2[B * 64];
// split-bf16 weights for the two projection GEMMs: layout [n(192)][k(64)]
__device__ __nv_bfloat16 g_bh1[192 * 64];
__device__ __nv_bfloat16 g_bl1[192 * 64];
__device__ __nv_bfloat16 g_bh2[192 * 64];
__device__ __nv_bfloat16 g_bl2[192 * 64];

__device__ __forceinline__ float sigmoidf_fast(float x) {
    return 1.0f / (1.0f + __expf(-x));
}
__device__ __forceinline__ float tanh_fast(float x) {
    float ax = fabsf(x);
    float e = __expf(-2.0f * ax);
    float th = __fdividef(1.0f - e, 1.0f + e);
    return copysignf(th, x);
}

__device__ __forceinline__ uint32_t smem_u32(const void* p) {
    uint32_t a;
    asm("{ .reg .u64 t; cvta.to.shared.u64 t, %1; cvt.u32.u64 %0, t; }" : "=r"(a) : "l"(p));
    return a;
}
__device__ __forceinline__ void ldsm_x4(uint32_t& r0, uint32_t& r1, uint32_t& r2, uint32_t& r3,
                                        uint32_t addr) {
    asm volatile("ldmatrix.sync.aligned.m8n8.x4.shared.b16 {%0,%1,%2,%3}, [%4];"
                 : "=r"(r0), "=r"(r1), "=r"(r2), "=r"(r3) : "r"(addr));
}
__device__ __forceinline__ void mma16816(float* c, const uint32_t* a, uint32_t b0, uint32_t b1) {
    asm volatile("mma.sync.aligned.m16n8k16.row.col.f32.bf16.bf16.f32 "
                 "{%0,%1,%2,%3}, {%4,%5,%6,%7}, {%8,%9}, {%0,%1,%2,%3};"
                 : "+f"(c[0]), "+f"(c[1]), "+f"(c[2]), "+f"(c[3])
                 : "r"(a[0]), "r"(a[1]), "r"(a[2]), "r"(a[3]), "r"(b0), "r"(b1));
}
__device__ __forceinline__ void store_bf16_pair(char* basep, int byteoff, float v0, float v1,
                                                char* basel, float l0, float l1) {
    __nv_bfloat162 h, l;
    h.x = __float2bfloat16(v0); h.y = __float2bfloat16(v1);
    l.x = __float2bfloat16(l0); l.y = __float2bfloat16(l1);
    *(__nv_bfloat162*)(basep + byteoff) = h;
    *(__nv_bfloat162*)(basel + byteoff) = l;
}
// split fp32 -> hi/lo bf16 pair store at byte offset (pair of adjacent cols)
__device__ __forceinline__ void split_pair(char* hi_base, char* lo_base, int byteoff,
                                           float v0, float v1) {
    __nv_bfloat16 h0 = __float2bfloat16(v0), h1 = __float2bfloat16(v1);
    store_bf16_pair(hi_base, byteoff, v0, v1, lo_base,
                    v0 - __bfloat162float(h0), v1 - __bfloat162float(h1));
}

// ======================================================================
// Weight split prep: W[64,128]|[64,64] fp32 -> Bhi/Blo [n=192][k=64] bf16
// ======================================================================
__global__ void wsplit_kernel(const float* __restrict__ Wg, const float* __restrict__ Wc,
                              __nv_bfloat16* __restrict__ Bhi, __nv_bfloat16* __restrict__ Blo)
{
    int idx = blockIdx.x * 256 + threadIdx.x;
    if (idx >= 192 * 64) return;
    int n = idx >> 6, k = idx & 63;
    float w = (n < 128) ? Wg[k * 128 + n] : Wc[k * 64 + (n - 128)];
    __nv_bfloat16 hi = __float2bfloat16(w);
    __nv_bfloat16 lo = __float2bfloat16(w - __bfloat162float(hi));
    Bhi[idx] = hi;
    Blo[idx] = lo;
}

// ======================================================================
// HMMA projection (unchanged, passing).
// ======================================================================
#define PAD_K 72
#define PSM_BIAS 0
#define PSM_AHI  768
#define PSM_ALO  (PSM_AHI + 128 * PAD_K * 2)
#define PSM_BHI  (PSM_ALO + 128 * PAD_K * 2)
#define PSM_BLO  (PSM_BHI + 192 * PAD_K * 2)
#define PSM_TOTAL (PSM_BLO + 192 * PAD_K * 2)   // 92928 bytes

template<int MODE>
__global__ void __launch_bounds__(256, 2) proj_mma_kernel(
        const float* __restrict__ src,
        const int*   __restrict__ hist_i,
        const float* __restrict__ alpha,
        const __nv_bfloat16* __restrict__ Bhi,
        const __nv_bfloat16* __restrict__ Blo,
        const float* __restrict__ bg,
        const float* __restrict__ bc,
        float* __restrict__ xg,
        float* __restrict__ xc)
{
    extern __shared__ char smem[];
    const uint32_t sbase = smem_u32(smem);
    const int tid = threadIdx.x;
    const int wid = tid >> 5;
    const int lane = tid & 31;
    const int m0 = blockIdx.x * 128;

    float* bs = (float*)(smem + PSM_BIAS);
    if (tid < 192) bs[tid] = (tid < 128) ? bg[tid] : bc[tid - 128];

    {
        const uint4* sh = (const uint4*)Bhi;
        const uint4* sl = (const uint4*)Blo;
#pragma unroll
        for (int i = 0; i < 6; i++) {
            int idx = tid + 256 * i;
            int n = idx >> 3, seg = idx & 7;
            int off = n * (PAD_K * 2) + seg * 16;
            *(uint4*)(smem + PSM_BHI + off) = sh[idx];
            *(uint4*)(smem + PSM_BLO + off) = sl[idx];
        }
    }

    {
        const int r = tid >> 1;
        const int half = tid & 1;
        const float* srow;
        float scale = 1.0f;
        if (MODE == 0) {
            srow = src + (size_t)hist_i[m0 + r] * 64;
        } else {
            srow = src + (size_t)(m0 + r) * 64;
            scale = alpha[m0 + r];
        }
        srow += half * 32;
        const int kb = half * 32;
#pragma unroll
        for (int c = 0; c < 4; c++) {
            float4 v0 = *(const float4*)(srow + 8 * c);
            float4 v1 = *(const float4*)(srow + 8 * c + 4);
            float vv[8] = {v0.x, v0.y, v0.z, v0.w, v1.x, v1.y, v1.z, v1.w};
            __nv_bfloat16 hb[8], lb[8];
#pragma unroll
            for (int e = 0; e < 8; e++) {
                float f = vv[e] * scale;
                hb[e] = __float2bfloat16(f);
                lb[e] = __float2bfloat16(f - __bfloat162float(hb[e]));
            }
            int off = r * (PAD_K * 2) + (kb + 8 * c) * 2;
            *(uint4*)(smem + PSM_AHI + off) = *(uint4*)hb;
            *(uint4*)(smem + PSM_ALO + off) = *(uint4*)lb;
        }
    }
    __syncthreads();

    const int arow = wid * 16 + (lane & 15);
    const int acolb = ((lane >> 4) << 3);
    const uint32_t a_off = (uint32_t)arow * (PAD_K * 2) + acolb * 2;
    const uint32_t aH_base = sbase + PSM_AHI + a_off;
    const uint32_t aL_base = sbase + PSM_ALO + a_off;

    const int bnrow_l = (lane & 7) + ((lane & 16) >> 1);
    const int bcol_l = (lane & 8);
    const uint32_t b_off_l = (uint32_t)bnrow_l * (PAD_K * 2) + bcol_l * 2;

    const int g = lane >> 2;
    const int tq = lane & 3;

#pragma unroll
    for (int nh = 0; nh < 2; nh++) {
        const uint32_t bH_base = sbase + PSM_BHI + b_off_l + (uint32_t)nh * 96 * (PAD_K * 2);
        const uint32_t bL_base = sbase + PSM_BLO + b_off_l + (uint32_t)nh * 96 * (PAD_K * 2);

        float acc[12][4];
#pragma unroll
        for (int i = 0; i < 12; i++)
#pragma unroll
            for (int qq = 0; qq < 4; qq++) acc[i][qq] = 0.0f;

#pragma unroll
        for (int ks = 0; ks < 4; ks++) {
            uint32_t aH[4], aL[4];
            ldsm_x4(aH[0], aH[1], aH[2], aH[3], aH_base + ks * 32);
            ldsm_x4(aL[0], aL[1], aL[2], aL[3], aL_base + ks * 32);
#pragma unroll
            for (int np = 0; np < 6; np++) {
                uint32_t bh0, bh1, bh2, bh3;
                ldsm_x4(bh0, bh1, bh2, bh3,
                        bH_base + (uint32_t)np * 16 * (PAD_K * 2) + ks * 32);
                mma16816(acc[2 * np],     aH, bh0, bh1);
                mma16816(acc[2 * np + 1], aH, bh2, bh3);
                mma16816(acc[2 * np],     aL, bh0, bh1);
                mma16816(acc[2 * np + 1], aL, bh2, bh3);
                uint32_t bl0, bl1, bl2, bl3;
                ldsm_x4(bl0, bl1, bl2, bl3,
                        bL_base + (uint32_t)np * 16 * (PAD_K * 2) + ks * 32);
                mma16816(acc[2 * np],     aH, bl0, bl1);
                mma16816(acc[2 * np + 1], aH, bl2, bl3);
            }
        }

        const int r0 = m0 + wid * 16 + g;
        const int r1 = r0 + 8;
#pragma unroll
        for (int nt = 0; nt < 12; nt++) {
            const int n = nh * 96 + nt * 8 + 2 * tq;
            const float bx = bs[n], by = bs[n + 1];
            float2 o0 = make_float2(acc[nt][0] + bx, acc[nt][1] + by);
            float2 o1 = make_float2(acc[nt][2] + bx, acc[nt][3] + by);
            if (n < 128) {
                *(float2*)(xg + (size_t)r0 * 128 + n) = o0;
                *(float2*)(xg + (size_t)r1 * 128 + n) = o1;
            } else {
                *(float2*)(xc + (size_t)r0 * 64 + (n - 128)) = o0;
                *(float2*)(xc + (size_t)r1 * 64 + (n - 128)) = o1;
            }
        }
    }
}

// ======================================================================
// GRU recurrence via HMMA: per CTA 32 batch rows, per step
//   gate[32x128] = h[32x64] @ Ug    (split-bf16, 3-term, fp32 accum)
//   cand[32x64]  = rhs[32x64] @ Uc
// h kept fp32 in smem; re-split to bf16 each step. 8 warps =
// (mt = wid&1) x (nb = wid>>1). Warps 0-3 cols 0-63 (rhs), 4-7 z.
// ======================================================================
#define GSM_UG_HI 0
#define GSM_UG_LO (GSM_UG_HI + 128 * 144)
#define GSM_UC_HI (GSM_UG_LO + 128 * 144)
#define GSM_UC_LO (GSM_UC_HI + 64 * 144)
#define GSM_HA_HI (GSM_UC_LO + 64 * 144)
#define GSM_HA_LO (GSM_HA_HI + GM * 144)
#define GSM_RA_HI (GSM_HA_LO + GM * 144)
#define GSM_RA_LO (GSM_RA_HI + GM * 144)
#define GSM_HF    (GSM_RA_LO + GM * 144)         // fp32 [32][68]
#define GSM_ZF    (GSM_HF + GM * 68 * 4)         // fp32 [32][68]
#define GSM_MSK   (GSM_ZF + GM * 68 * 4)         // fp32 [32][200]
#define GSM_TOTAL (GSM_MSK + GM * 200 * 4)       // 116736 bytes

template<bool STORE_ALL>
__global__ void __launch_bounds__(256, 1) gru_tc_kernel(
        const float* __restrict__ xg,
        const float* __restrict__ xc,
        const float* __restrict__ mask,
        const float* __restrict__ Ug,   // [64,128]
        const float* __restrict__ Uc,   // [64,64]
        float* __restrict__ out)        // [B,T,64] or [B,64]
{
    extern __shared__ char smem[];
    const uint32_t sbase = smem_u32(smem);
    const int tid = threadIdx.x;
    const int wid = tid >> 5, lane = tid & 31;
    const int b0 = blockIdx.x * GM;

    // ---- stage UgT/UcT split-bf16 (scalar 2-byte stores; alignment-safe) ----
    for (int idx = tid; idx < 128 * 64; idx += 256) {
        int k = idx >> 7, n = idx & 127;
        float w = Ug[k * 128 + n];
        __nv_bfloat16 hi = __float2bfloat16(w);
        *(__nv_bfloat16*)(smem + GSM_UG_HI + n * 144 + k * 2) = hi;
        *(__nv_bfloat16*)(smem + GSM_UG_LO + n * 144 + k * 2) =
            __float2bfloat16(w - __bfloat162float(hi));
    }
    for (int idx = tid; idx < 64 * 64; idx += 256) {
        int k = idx >> 6, n = idx & 63;
        float w = Uc[k * 64 + n];
        __nv_bfloat16 hi = __float2bfloat16(w);
        *(__nv_bfloat16*)(smem + GSM_UC_HI + n * 144 + k * 2) = hi;
        *(__nv_bfloat16*)(smem + GSM_UC_LO + n * 144 + k * 2) =
            __float2bfloat16(w - __bfloat162float(hi));
    }
    // zero hA (both planes contiguous: 2*GM*144 bytes) and h fp32
    for (int idx = tid; idx < (2 * GM * 144) / 16; idx += 256)
        ((uint4*)(smem + GSM_HA_HI))[idx] = make_uint4(0, 0, 0, 0);
    for (int idx = tid; idx < GM * 68; idx += 256)
        ((float*)(smem + GSM_HF))[idx] = 0.0f;
    // mask -> smem
    float* msk = (float*)(smem + GSM_MSK);
    for (int idx = tid; idx < GM * T; idx += 256) {
        int r = idx / T, t = idx - r * T;
        msk[idx] = mask[(size_t)(b0 + r) * T + t];
    }
    __syncthreads();

    const int mt = wid & 1;
    const int nb = wid >> 1;              // gate: 32-col block; cand: 16-col block
    const int g = lane >> 2, q = lane & 3;
    const int arow_l = lane & 15;
    const int acolb = (lane >> 4) << 3;
    const int bnrow_l = (lane & 7) + ((lane & 16) >> 1);
    const int bcol_l = lane & 8;

    const int r0 = mt * 16 + g;           // rows r0, r0+8
    const size_t xg0 = (size_t)(b0 + r0) * (T * 128);
    const size_t xg1 = (size_t)(b0 + r0 + 8) * (T * 128);
    const size_t xc0 = (size_t)(b0 + r0) * (T * 64);
    const size_t xc1 = (size_t)(b0 + r0 + 8) * (T * 64);

    const uint32_t aHg = sbase + GSM_HA_HI + (uint32_t)(mt * 16 + arow_l) * 144 + acolb * 2;
    const uint32_t aLg = sbase + GSM_HA_LO + (uint32_t)(mt * 16 + arow_l) * 144 + acolb * 2;
    const uint32_t aHc = sbase + GSM_RA_HI + (uint32_t)(mt * 16 + arow_l) * 144 + acolb * 2;
    const uint32_t aLc = sbase + GSM_RA_LO + (uint32_t)(mt * 16 + arow_l) * 144 + acolb * 2;
    const uint32_t bHg = sbase + GSM_UG_HI + (uint32_t)(nb * 32 + bnrow_l) * 144 + bcol_l * 2;
    const uint32_t bLg = sbase + GSM_UG_LO + (uint32_t)(nb * 32 + bnrow_l) * 144 + bcol_l * 2;
    const uint32_t bHc = sbase + GSM_UC_HI + (uint32_t)(nb * 16 + bnrow_l) * 144 + bcol_l * 2;
    const uint32_t bLc = sbase + GSM_UC_LO + (uint32_t)(nb * 16 + bnrow_l) * 144 + bcol_l * 2;

    float* hf = (float*)(smem + GSM_HF);
    float* zf = (float*)(smem + GSM_ZF);

    for (int t = 0; t < T; t++) {
        // ---------------- gate ----------------
        float xgv[16];
#pragma unroll
        for (int nt = 0; nt < 4; nt++) {
            const int col = nb * 32 + nt * 8 + 2 * q;
            float2 v0 = *(const float2*)(xg + xg0 + (size_t)t * 128 + col);
            float2 v1 = *(const float2*)(xg + xg1 + (size_t)t * 128 + col);
            xgv[4 * nt + 0] = v0.x; xgv[4 * nt + 1] = v0.y;
            xgv[4 * nt + 2] = v1.x; xgv[4 * nt + 3] = v1.y;
        }

        float acc[4][4];
#pragma unroll
        for (int i = 0; i < 4; i++)
#pragma unroll
            for (int e = 0; e < 4; e++) acc[i][e] = 0.0f;

#pragma unroll
        for (int ks = 0; ks < 4; ks++) {
            uint32_t aH[4], aL[4];
            ldsm_x4(aH[0], aH[1], aH[2], aH[3], aHg + ks * 32);
            ldsm_x4(aL[0], aL[1], aL[2], aL[3], aLg + ks * 32);
#pragma unroll
            for (int np = 0; np < 2; np++) {
                uint32_t c0, c1, c2, c3;
                ldsm_x4(c0, c1, c2, c3, bHg + (uint32_t)np * 16 * 144 + ks * 32);
                mma16816(acc[2 * np],     aH, c0, c1);
                mma16816(acc[2 * np + 1], aH, c2, c3);
                mma16816(acc[2 * np],     aL, c0, c1);
                mma16816(acc[2 * np + 1], aL, c2, c3);
                ldsm_x4(c0, c1, c2, c3, bLg + (uint32_t)np * 16 * 144 + ks * 32);
                mma16816(acc[2 * np],     aH, c0, c1);
                mma16816(acc[2 * np + 1], aH, c2, c3);
            }
        }

        if (wid < 4) {
            // cols 0..63: rhs = sigmoid(gate) * h  -> split bf16
#pragma unroll
            for (int nt = 0; nt < 4; nt++) {
                const int col = nb * 32 + nt * 8 + 2 * q;
                float s0 = sigmoidf_fast(acc[nt][0] + xgv[4 * nt + 0]);
                float s1 = sigmoidf_fast(acc[nt][1] + xgv[4 * nt + 1]);
                float s2 = sigmoidf_fast(acc[nt][2] + xgv[4 * nt + 2]);
                float s3 = sigmoidf_fast(acc[nt][3] + xgv[4 * nt + 3]);
                float rh0 = s0 * hf[r0 * 68 + col];
                float rh1 = s1 * hf[r0 * 68 + col + 1];
                float rh2 = s2 * hf[(r0 + 8) * 68 + col];
                float rh3 = s3 * hf[(r0 + 8) * 68 + col + 1];
                split_pair(smem + GSM_RA_HI, smem + GSM_RA_LO, r0 * 144 + col * 2, rh0, rh1);
                split_pair(smem + GSM_RA_HI, smem + GSM_RA_LO, (r0 + 8) * 144 + col * 2, rh2, rh3);
            }
        } else {
            // cols 64..127: z
#pragma unroll
            for (int nt = 0; nt < 4; nt++) {
                const int zc = nb * 32 + nt * 8 + 2 * q - 64;
                zf[r0 * 68 + zc]           = sigmoidf_fast(acc[nt][0] + xgv[4 * nt + 0]);
                zf[r0 * 68 + zc + 1]       = sigmoidf_fast(acc[nt][1] + xgv[4 * nt + 1]);
                zf[(r0 + 8) * 68 + zc]     = sigmoidf_fast(acc[nt][2] + xgv[4 * nt + 2]);
                zf[(r0 + 8) * 68 + zc + 1] = sigmoidf_fast(acc[nt][3] + xgv[4 * nt + 3]);
            }
        }
        __syncthreads();

        // ---------------- candidate ----------------
        float xcv[8];
#pragma unroll
        for (int nt = 0; nt < 2; nt++) {
            const int col = nb * 16 + nt * 8 + 2 * q;
            float2 v0 = *(const float2*)(xc + xc0 + (size_t)t * 64 + col);
            float2 v1 = *(const float2*)(xc + xc1 + (size_t)t * 64 + col);
            xcv[4 * nt + 0] = v0.x; xcv[4 * nt + 1] = v0.y;
            xcv[4 * nt + 2] = v1.x; xcv[4 * nt + 3] = v1.y;
        }

        float cac[2][4];
#pragma unroll
        for (int i = 0; i < 2; i++)
#pragma unroll
            for (int e = 0; e < 4; e++) cac[i][e] = 0.0f;

#pragma unroll
        for (int ks = 0; ks < 4; ks++) {
            uint32_t aH[4], aL[4];
            ldsm_x4(aH[0], aH[1], aH[2], aH[3], aHc + ks * 32);
            ldsm_x4(aL[0], aL[1], aL[2], aL[3], aLc + ks * 32);
            uint32_t c0, c1, c2, c3;
            ldsm_x4(c0, c1, c2, c3, bHc + ks * 32);
            mma16816(cac[0], aH, c0, c1);
            mma16816(cac[1], aH, c2, c3);
            mma16816(cac[0], aL, c0, c1);
            mma16816(cac[1], aL, c2, c3);
            ldsm_x4(c0, c1, c2, c3, bLc + ks * 32);
            mma16816(cac[0], aH, c0, c1);
            mma16816(cac[1], aH, c2, c3);
        }

        // epilogue: h update
#pragma unroll
        for (int nt = 0; nt < 2; nt++) {
            const int col = nb * 16 + nt * 8 + 2 * q;
            float hn[4];
#pragma unroll
            for (int e = 0; e < 4; e++) {
                const int rr = (e < 2) ? r0 : (r0 + 8);
                const int cc = col + (e & 1);
                float cand = tanh_fast(cac[nt][e] + xcv[4 * nt + e]);
                float z = zf[rr * 68 + cc];
                float h = hf[rr * 68 + cc];
                float v = fmaf(z, h - cand, cand);
                float m = msk[rr * T + t];
                hn[e] = fmaf(m, v - h, h);
                hf[rr * 68 + cc] = hn[e];
            }
            split_pair(smem + GSM_HA_HI, smem + GSM_HA_LO, r0 * 144 + col * 2, hn[0], hn[1]);
            split_pair(smem + GSM_HA_HI, smem + GSM_HA_LO, (r0 + 8) * 144 + col * 2, hn[2], hn[3]);
            if (STORE_ALL) {
                *(float2*)(out + (size_t)(b0 + r0) * (T * 64) + (size_t)t * 64 + col) =
                    make_float2(hn[0], hn[1]);
                *(float2*)(out + (size_t)(b0 + r0 + 8) * (T * 64) + (size_t)t * 64 + col) =
                    make_float2(hn[2], hn[3]);
            }
        }
        __syncthreads();
    }

    if (!STORE_ALL) {
        for (int idx = tid; idx < GM * 64; idx += 256) {
            int r = idx >> 6, c = idx & 63;
            out[(size_t)(b0 + r) * 64 + c] = hf[r * 68 + c];
        }
    }
}

// ======================================================================
// DIN attention via HMMA, chunked (2 CTAs/SM) — unchanged from R12.
// ======================================================================
#define ACH 112
#define APK  72
#define APK2 88

#define ASM_QS    0
#define ASM_BASE  256
#define ASM_BA2   640
#define ASM_WA3   832
#define ASM_SC    992
#define ASM_RED   1888
#define ASM_KHI   2048
#define ASM_KLO   (ASM_KHI + ACH * APK * 2)
#define ASM_WHI   (ASM_KLO + ACH * APK * 2)
#define ASM_WLO   (ASM_WHI + 80 * APK * 2)
#define ASM_W2HI  (ASM_WLO + 80 * APK * 2)
#define ASM_W2LO  (ASM_W2HI + 48 * APK2 * 2)
#define ASM_D1HI  (ASM_W2LO + 48 * APK2 * 2)
#define ASM_D1LO  (ASM_D1HI + ACH * APK2 * 2)
#define ASM_TOTAL (ASM_D1LO + ACH * APK2 * 2)   // 113664

__global__ void __launch_bounds__(256, 2) attn_mma_kernel(
        const int*   __restrict__ item_i,
        const float* __restrict__ item_emb,
        const float* __restrict__ rnn1,
        const float* __restrict__ mask,
        const float* __restrict__ Wa1, const float* __restrict__ ba1,
        const float* __restrict__ Wa2, const float* __restrict__ ba2,
        const float* __restrict__ Wa3, const float* __restrict__ ba3,
        float* __restrict__ alpha)
{
    extern __shared__ char smem[];
    const uint32_t sbase = smem_u32(smem);
    const int b = blockIdx.x;
    const int tid = threadIdx.x;
    const int wid = tid >> 5, lane = tid & 31;

    float* qs   = (float*)(smem + ASM_QS);
    float* base = (float*)(smem + ASM_BASE);
    float* ba2s = (float*)(smem + ASM_BA2);
    float* wa3s = (float*)(smem + ASM_WA3);
    float* sc   = (float*)(smem + ASM_SC);
    float* red  = (float*)(smem + ASM_RED);

    if (tid < 64) qs[tid] = item_emb[(size_t)item_i[b] * 64 + tid];
    if (tid >= 64 && tid < 112) ba2s[tid - 64] = (tid - 64 < 40) ? ba2[tid - 64] : 0.0f;
    if (tid >= 112 && tid < 152) wa3s[tid - 112] = Wa3[tid - 112];
    for (int i = tid; i < 88; i += 256) {
        int r = 40 + i / 11, s = i % 11;
        *(uint4*)(smem + ASM_W2HI + r * 176 + s * 16) = make_uint4(0, 0, 0, 0);
        *(uint4*)(smem + ASM_W2LO + r * 176 + s * 16) = make_uint4(0, 0, 0, 0);
    }
    __syncthreads();

    if (tid < 80) {
        float acc = ba1[tid];
#pragma unroll 8
        for (int k = 0; k < 64; k++)
            acc = fmaf(qs[k], Wa1[k * 80 + tid] + Wa1[(128 + k) * 80 + tid], acc);
        base[tid] = acc;
    }
    for (int idx = tid; idx < 5120; idx += 256) {
        int k = idx / 80, c = idx - k * 80;
        float w = Wa1[(64 + k) * 80 + c] - Wa1[(128 + k) * 80 + c]
                + qs[k] * Wa1[(192 + k) * 80 + c];
        __nv_bfloat16 hi = __float2bfloat16(w);
        *(__nv_bfloat16*)(smem + ASM_WHI + c * 144 + k * 2) = hi;
        *(__nv_bfloat16*)(smem + ASM_WLO + c * 144 + k * 2) =
            __float2bfloat16(w - __bfloat162float(hi));
    }
    for (int idx = tid; idx < 3200; idx += 256) {
        int k = idx / 40, n = idx - k * 40;
        float w = Wa2[idx];
        __nv_bfloat16 hi = __float2bfloat16(w);
        *(__nv_bfloat16*)(smem + ASM_W2HI + n * 176 + k * 2) = hi;
        *(__nv_bfloat16*)(smem + ASM_W2LO + n * 176 + k * 2) =
            __float2bfloat16(w - __bfloat162float(hi));
    }

    const int arow_l = lane & 15;
    const int acolb  = (lane >> 4) << 3;
    const int bnrow_l = (lane & 7) + ((lane & 16) >> 1);
    const int bcol_l  = lane & 8;
    const int g = lane >> 2, q = lane & 3;
    const float ba3v = ba3[0];

    for (int cc = 0; cc < 2; cc++) {
        const int t0 = cc * ACH;

        __syncthreads();
        for (int idx = tid; idx < ACH * 16; idx += 256) {
            int r = idx >> 4, c4 = idx & 15;
            int tg = t0 + r; if (tg > T - 1) tg = T - 1;
            float4 v = *(const float4*)(rnn1 + ((size_t)b * T + tg) * 64 + c4 * 4);
            __nv_bfloat16 h[4], l[4];
            h[0] = __float2bfloat16(v.x); l[0] = __float2bfloat16(v.x - __bfloat162float(h[0]));
            h[1] = __float2bfloat16(v.y); l[1] = __float2bfloat16(v.y - __bfloat162float(h[1]));
            h[2] = __float2bfloat16(v.z); l[2] = __float2bfloat16(v.z - __bfloat162float(h[2]));
            h[3] = __float2bfloat16(v.w); l[3] = __float2bfloat16(v.w - __bfloat162float(h[3]));
            int off = r * 144 + c4 * 8;
            *(uint2*)(smem + ASM_KHI + off) = *(uint2*)h;
            *(uint2*)(smem + ASM_KLO + off) = *(uint2*)l;
        }
        __syncthreads();

        for (int mtl = wid; mtl < 7; mtl += 8) {
            float acc[10][4];
#pragma unroll
            for (int nt = 0; nt < 10; nt++) {
                float b0 = base[nt * 8 + 2 * q], b1 = base[nt * 8 + 2 * q + 1];
                acc[nt][0] = b0; acc[nt][1] = b1; acc[nt][2] = b0; acc[nt][3] = b1;
            }
            const uint32_t aHb = sbase + ASM_KHI + (uint32_t)(mtl * 16 + arow_l) * 144 + acolb * 2;
            const uint32_t aLb = sbase + ASM_KLO + (uint32_t)(mtl * 16 + arow_l) * 144 + acolb * 2;
            const uint32_t bHb = sbase + ASM_WHI + (uint32_t)bnrow_l * 144 + bcol_l * 2;
            const uint32_t bLb = sbase + ASM_WLO + (uint32_t)bnrow_l * 144 + bcol_l * 2;
#pragma unroll
            for (int ks = 0; ks < 4; ks++) {
                uint32_t aH[4], aL[4];
                ldsm_x4(aH[0], aH[1], aH[2], aH[3], aHb + ks * 32);
                ldsm_x4(aL[0], aL[1], aL[2], aL[3], aLb + ks * 32);
#pragma unroll
                for (int np = 0; np < 5; np++) {
                    uint32_t c0, c1, c2, c3;
                    ldsm_x4(c0, c1, c2, c3, bHb + (uint32_t)np * 16 * 144 + ks * 32);
                    mma16816(acc[2 * np],     aH, c0, c1);
                    mma16816(acc[2 * np + 1], aH, c2, c3);
                    mma16816(acc[2 * np],     aL, c0, c1);
                    mma16816(acc[2 * np + 1], aL, c2, c3);
                    ldsm_x4(c0, c1, c2, c3, bLb + (uint32_t)np * 16 * 144 + ks * 32);
                    mma16816(acc[2 * np],     aH, c0, c1);
                    mma16816(acc[2 * np + 1], aH, c2, c3);
                }
            }
            const int r0 = mtl * 16 + g, r1 = r0 + 8;
#pragma unroll
            for (int nt = 0; nt < 10; nt++) {
                const int c0 = nt * 8 + 2 * q;
                float s00 = sigmoidf_fast(acc[nt][0]);
                float s01 = sigmoidf_fast(acc[nt][1]);
                float s10 = sigmoidf_fast(acc[nt][2]);
                float s11 = sigmoidf_fast(acc[nt][3]);
                split_pair(smem + ASM_D1HI, smem + ASM_D1LO, r0 * 176 + c0 * 2, s00, s01);
                split_pair(smem + ASM_D1HI, smem + ASM_D1LO, r1 * 176 + c0 * 2, s10, s11);
            }
        }
        __syncthreads();

        for (int mtl = wid; mtl < 7; mtl += 8) {
            float acc[6][4];
#pragma unroll
            for (int nt = 0; nt < 6; nt++) {
                float b0 = ba2s[nt * 8 + 2 * q], b1 = ba2s[nt * 8 + 2 * q + 1];
                acc[nt][0] = b0; acc[nt][1] = b1; acc[nt][2] = b0; acc[nt][3] = b1;
            }
            const uint32_t aHb = sbase + ASM_D1HI + (uint32_t)(mtl * 16 + arow_l) * 176 + acolb * 2;
            const uint32_t aLb = sbase + ASM_D1LO + (uint32_t)(mtl * 16 + arow_l) * 176 + acolb * 2;
            const uint32_t bHb = sbase + ASM_W2HI + (uint32_t)bnrow_l * 176 + bcol_l * 2;
            const uint32_t bLb = sbase + ASM_W2LO + (uint32_t)bnrow_l * 176 + bcol_l * 2;
#pragma unroll
            for (int ks = 0; ks < 5; ks++) {
                uint32_t aH[4], aL[4];
                ldsm_x4(aH[0], aH[1], aH[2], aH[3], aHb + ks * 32);
                ldsm_x4(aL[0], aL[1], aL[2], aL[3], aLb + ks * 32);
#pragma unroll
                for (int np = 0; np < 3; np++) {
                    uint32_t c0, c1, c2, c3;
                    ldsm_x4(c0, c1, c2, c3, bHb + (uint32_t)np * 16 * 176 + ks * 32);
                    mma16816(acc[2 * np],     aH, c0, c1);
                    mma16816(acc[2 * np + 1], aH, c2, c3);
                    mma16816(acc[2 * np],     aL, c0, c1);
                    mma16816(acc[2 * np + 1], aL, c2, c3);
                    ldsm_x4(c0, c1, c2, c3, bLb + (uint32_t)np * 16 * 176 + ks * 32);
                    mma16816(acc[2 * np],     aH, c0, c1);
                    mma16816(acc[2 * np + 1], aH, c2, c3);
                }
            }
            float s0 = 0.0f, s1 = 0.0f;
#pragma unroll
            for (int nt = 0; nt < 5; nt++) {
                const int c0 = nt * 8 + 2 * q;
                float w0 = wa3s[c0], w1 = wa3s[c0 + 1];
                s0 = fmaf(sigmoidf_fast(acc[nt][0]), w0, s0);
                s0 = fmaf(sigmoidf_fast(acc[nt][1]), w1, s0);
                s1 = fmaf(sigmoidf_fast(acc[nt][2]), w0, s1);
                s1 = fmaf(sigmoidf_fast(acc[nt][3]), w1, s1);
            }
            s0 += __shfl_xor_sync(0xffffffffu, s0, 1);
            s0 += __shfl_xor_sync(0xffffffffu, s0, 2);
            s1 += __shfl_xor_sync(0xffffffffu, s1, 1);
            s1 += __shfl_xor_sync(0xffffffffu, s1, 2);
            if (q == 0) {
                int t0g = t0 + mtl * 16 + g, t1g = t0g + 8;
                if (t0g < T) {
                    float m = mask[(size_t)b * T + t0g];
                    sc[t0g] = (m > 0.0f) ? (s0 + ba3v) : -1e9f;
                }
                if (t1g < T) {
                    float m = mask[(size_t)b * T + t1g];
                    sc[t1g] = (m > 0.0f) ? (s1 + ba3v) : -1e9f;
                }
            }
        }
    }
    __syncthreads();

    float v = (tid < T) ? sc[tid] : -FLT_MAX;
#pragma unroll
    for (int o = 16; o > 0; o >>= 1) v = fmaxf(v, __shfl_xor_sync(0xffffffffu, v, o));
    if (lane == 0) red[wid] = v;
    __syncthreads();
    if (tid == 0) {
        float mx = red[0];
#pragma unroll
        for (int w = 1; w < 8; w++) mx = fmaxf(mx, red[w]);
        red[12] = mx;
    }
    __syncthreads();
    float mx = red[12];

    float e = (tid < T) ? __expf(sc[tid] - mx) : 0.0f;
    float s = e;
#pragma unroll
    for (int o = 16; o > 0; o >>= 1) s += __shfl_xor_sync(0xffffffffu, s, o);
    __syncthreads();
    if (lane == 0) red[wid] = s;
    __syncthreads();
    if (tid == 0) {
        float sum = 0.0f;
#pragma unroll
        for (int w = 0; w < 8; w++) sum += red[w];
        red[13] = 1.0f / sum;
    }
    __syncthreads();
    if (tid < T) alpha[(size_t)b * T + tid] = e * red[13];
}

// ======================================================================
// FCN head + hist_sum (unchanged).
// ======================================================================
__global__ void fcn_kernel(const int* __restrict__ u, const int* __restrict__ ii,
                           const int* __restrict__ hist_i,
                           const float* __restrict__ item_emb,
                           const float* __restrict__ user_emb,
                           const float* __restrict__ final2,
                           const float* __restrict__ W1, const float* __restrict__ b1,
                           const float* __restrict__ p1,
                           const float* __restrict__ W2, const float* __restrict__ b2,
                           const float* __restrict__ p2,
                           const float* __restrict__ W3, const float* __restrict__ b3,
                           float* __restrict__ out)
{
    __shared__ float xs[320];
    __shared__ float h1s[128];
    __shared__ float h2s[40];

    const int b = blockIdx.x;
    const int tid = threadIdx.x;

    if (tid < 64) {
        const int* hi = hist_i + (size_t)b * T;
        float s0 = 0.f, s1 = 0.f, s2 = 0.f, s3 = 0.f;
        for (int t = 0; t < T; t += 4) {
            s0 += item_emb[(size_t)hi[t]     * 64 + tid];
            s1 += item_emb[(size_t)hi[t + 1] * 64 + tid];
            s2 += item_emb[(size_t)hi[t + 2] * 64 + tid];
            s3 += item_emb[(size_t)hi[t + 3] * 64 + tid];
        }
        xs[128 + tid] = (s0 + s1) + (s2 + s3);
    } else {
        int j = tid - 64;
        xs[j]       = user_emb[(size_t)u[b]  * 64 + j];
        xs[64 + j]  = item_emb[(size_t)ii[b] * 64 + j];
        xs[256 + j] = final2[(size_t)b * 64 + j];
    }
    __syncthreads();
    if (tid < 64) xs[192 + tid] = xs[64 + tid] * xs[128 + tid];
    __syncthreads();

    {
        float a0 = b1[tid], a1 = 0.0f;
#pragma unroll 8
        for (int k = 0; k < 320; k += 2) {
            a0 = fmaf(xs[k],     W1[k * 128 + tid],       a0);
            a1 = fmaf(xs[k + 1], W1[(k + 1) * 128 + tid], a1);
        }
        float h = a0 + a1;
        h1s[tid] = (h >= 0.0f) ? h : p1[tid] * h;
    }
    __syncthreads();

    if (tid < 40) {
        float a0 = b2[tid], a1 = 0.0f;
#pragma unroll 16
        for (int k = 0; k < 128; k += 2) {
            a0 = fmaf(h1s[k],     W2[k * 40 + tid],       a0);
            a1 = fmaf(h1s[k + 1], W2[(k + 1) * 40 + tid], a1);
        }
        float h = a0 + a1;
        h2s[tid] = (h >= 0.0f) ? h : p2[tid] * h;
    }
    __syncthreads();

    if (tid == 0) {
        float acc = b3[0];
#pragma unroll
        for (int k = 0; k < 40; k++) acc = fmaf(h2s[k], W3[k], acc);
        out[b] = acc;
    }
}

// ======================================================================
extern "C" void kernel_launch(void* const* d_in, const int* in_sizes, int n_in,
                              void* d_out, int out_size)
{
    const int*   u        = (const int*)d_in[0];
    const int*   ii       = (const int*)d_in[1];
    const int*   hist_i   = (const int*)d_in[2];
    const float* mask     = (const float*)d_in[3];
    const float* item_emb = (const float*)d_in[4];
    const float* user_emb = (const float*)d_in[5];
    const float* g1_Wg = (const float*)d_in[6];
    const float* g1_Ug = (const float*)d_in[7];
    const float* g1_bg = (const float*)d_in[8];
    const float* g1_Wc = (const float*)d_in[9];
    const float* g1_Uc = (const float*)d_in[10];
    const float* g1_bc = (const float*)d_in[11];
    const float* Wa1 = (const float*)d_in[12];
    const float* ba1 = (const float*)d_in[13];
    const float* Wa2 = (const float*)d_in[14];
    const float* ba2 = (const float*)d_in[15];
    const float* Wa3 = (const float*)d_in[16];
    const float* ba3 = (const float*)d_in[17];
    const float* g2_Wg = (const float*)d_in[18];
    const float* g2_Ug = (const float*)d_in[19];
    const float* g2_bg = (const float*)d_in[20];
    const float* g2_Wc = (const float*)d_in[21];
    const float* g2_Uc = (const float*)d_in[22];
    const float* g2_bc = (const float*)d_in[23];
    const float* W1 = (const float*)d_in[24];
    const float* b1 = (const float*)d_in[25];
    const float* p1 = (const float*)d_in[26];
    const float* W2 = (const float*)d_in[27];
    const float* b2 = (const float*)d_in[28];
    const float* p2 = (const float*)d_in[29];
    const float* W3 = (const float*)d_in[30];
    const float* b3 = (const float*)d_in[31];
    float* out = (float*)d_out;

    float *xg, *xc, *rnn1, *alpha, *final2;
    __nv_bfloat16 *bh1, *bl1, *bh2, *bl2;
    cudaGetSymbolAddress((void**)&xg,     g_xg);
    cudaGetSymbolAddress((void**)&xc,     g_xc);
    cudaGetSymbolAddress((void**)&rnn1,   g_rnn1);
    cudaGetSymbolAddress((void**)&alpha,  g_alpha);
    cudaGetSymbolAddress((void**)&final2, g_final2);
    cudaGetSymbolAddress((void**)&bh1, g_bh1);
    cudaGetSymbolAddress((void**)&bl1, g_bl1);
    cudaGetSymbolAddress((void**)&bh2, g_bh2);
    cudaGetSymbolAddress((void**)&bl2, g_bl2);

    cudaFuncSetAttribute(proj_mma_kernel<0>, cudaFuncAttributeMaxDynamicSharedMemorySize, PSM_TOTAL);
    cudaFuncSetAttribute(proj_mma_kernel<1>, cudaFuncAttributeMaxDynamicSharedMemorySize, PSM_TOTAL);
    cudaFuncSetAttribute(gru_tc_kernel<true>,  cudaFuncAttributeMaxDynamicSharedMemorySize, GSM_TOTAL);
    cudaFuncSetAttribute(gru_tc_kernel<false>, cudaFuncAttributeMaxDynamicSharedMemorySize, GSM_TOTAL);
    cudaFuncSetAttribute(attn_mma_kernel, cudaFuncAttributeMaxDynamicSharedMemorySize, ASM_TOTAL);

    // 0) split projection weights to bf16 hi/lo (both GRUs)
    wsplit_kernel<<<48, 256>>>(g1_Wg, g1_Wc, bh1, bl1);
    wsplit_kernel<<<48, 256>>>(g2_Wg, g2_Wc, bh2, bl2);
    // 1) GRU1 input projections via HMMA
    proj_mma_kernel<0><<<BT / 128, 256, PSM_TOTAL>>>(item_emb, hist_i, nullptr,
                                                     bh1, bl1, g1_bg, g1_bc, xg, xc);
    // 2) GRU1 recurrence via HMMA -> rnn1
    gru_tc_kernel<true><<<B / GM, 256, GSM_TOTAL>>>(xg, xc, mask, g1_Ug, g1_Uc, rnn1);
    // 3) DIN attention via HMMA (chunked, 2 CTAs/SM) -> alpha
    attn_mma_kernel<<<B, 256, ASM_TOTAL>>>(ii, item_emb, rnn1, mask,
                                           Wa1, ba1, Wa2, ba2, Wa3, ba3, alpha);
    // 4) GRU2 input projections via HMMA (rnn1 * alpha)
    proj_mma_kernel<1><<<BT / 128, 256, PSM_TOTAL>>>(rnn1, nullptr, alpha,
                                                     bh2, bl2, g2_bg, g2_bc, xg, xc);
    // 5) GRU2 recurrence via HMMA -> final2 only
    gru_tc_kernel<false><<<B / GM, 256, GSM_TOTAL>>>(xg, xc, mask, g2_Ug, g2_Uc, final2);
    // 6) FCN head -> logits
    fcn_kernel<<<B, 128>>>(u, ii, hist_i, item_emb, user_emb, final2,
                           W1, b1, p1, W2, b2, p2, W3, b3, out);
}

// round 15
// speedup vs baseline: 1.8800x; 1.1215x over previous
#include <cuda_runtime.h>
#include <cuda_bf16.h>
#include <math.h>
#include <float.h>
#include <cstdint>

#define B 4096
#define T 200
#define BT (B*T)
#define GM 16   // batch rows per GRU-TC block (grid = 256, 2 CTAs/SM)

// ---------------- scratch (device globals: no allocs allowed) ----------------
__device__ float g_xg[(size_t)BT * 128];
__device__ float g_xc[(size_t)BT * 64];
__device__ float g_rnn1[(size_t)BT * 64];
__device__ float g_alpha[BT];
__device__ float g_final2[B * 64];
// split-bf16 weights for the two projection GEMMs: layout [n(192)][k(64)]
__device__ __nv_bfloat16 g_bh1[192 * 64];
__device__ __nv_bfloat16 g_bl1[192 * 64];
__device__ __nv_bfloat16 g_bh2[192 * 64];
__device__ __nv_bfloat16 g_bl2[192 * 64];

__device__ __forceinline__ float sigmoidf_fast(float x) {
    return 1.0f / (1.0f + __expf(-x));
}
__device__ __forceinline__ float tanh_fast(float x) {
    float ax = fabsf(x);
    float e = __expf(-2.0f * ax);
    float th = __fdividef(1.0f - e, 1.0f + e);
    return copysignf(th, x);
}

__device__ __forceinline__ uint32_t smem_u32(const void* p) {
    uint32_t a;
    asm("{ .reg .u64 t; cvta.to.shared.u64 t, %1; cvt.u32.u64 %0, t; }" : "=r"(a) : "l"(p));
    return a;
}
__device__ __forceinline__ void ldsm_x4(uint32_t& r0, uint32_t& r1, uint32_t& r2, uint32_t& r3,
                                        uint32_t addr) {
    asm volatile("ldmatrix.sync.aligned.m8n8.x4.shared.b16 {%0,%1,%2,%3}, [%4];"
                 : "=r"(r0), "=r"(r1), "=r"(r2), "=r"(r3) : "r"(addr));
}
__device__ __forceinline__ void mma16816(float* c, const uint32_t* a, uint32_t b0, uint32_t b1) {
    asm volatile("mma.sync.aligned.m16n8k16.row.col.f32.bf16.bf16.f32 "
                 "{%0,%1,%2,%3}, {%4,%5,%6,%7}, {%8,%9}, {%0,%1,%2,%3};"
                 : "+f"(c[0]), "+f"(c[1]), "+f"(c[2]), "+f"(c[3])
                 : "r"(a[0]), "r"(a[1]), "r"(a[2]), "r"(a[3]), "r"(b0), "r"(b1));
}
__device__ __forceinline__ void store_bf16_pair(char* basep, int byteoff, float v0, float v1,
                                                char* basel, float l0, float l1) {
    __nv_bfloat162 h, l;
    h.x = __float2bfloat16(v0); h.y = __float2bfloat16(v1);
    l.x = __float2bfloat16(l0); l.y = __float2bfloat16(l1);
    *(__nv_bfloat162*)(basep + byteoff) = h;
    *(__nv_bfloat162*)(basel + byteoff) = l;
}
// split fp32 -> hi/lo bf16 pair store at byte offset (pair of adjacent cols)
__device__ __forceinline__ void split_pair(char* hi_base, char* lo_base, int byteoff,
                                           float v0, float v1) {
    __nv_bfloat16 h0 = __float2bfloat16(v0), h1 = __float2bfloat16(v1);
    store_bf16_pair(hi_base, byteoff, v0, v1, lo_base,
                    v0 - __bfloat162float(h0), v1 - __bfloat162float(h1));
}

// ======================================================================
// Weight split prep: W[64,128]|[64,64] fp32 -> Bhi/Blo [n=192][k=64] bf16
// ======================================================================
__global__ void wsplit_kernel(const float* __restrict__ Wg, const float* __restrict__ Wc,
                              __nv_bfloat16* __restrict__ Bhi, __nv_bfloat16* __restrict__ Blo)
{
    int idx = blockIdx.x * 256 + threadIdx.x;
    if (idx >= 192 * 64) return;
    int n = idx >> 6, k = idx & 63;
    float w = (n < 128) ? Wg[k * 128 + n] : Wc[k * 64 + (n - 128)];
    __nv_bfloat16 hi = __float2bfloat16(w);
    __nv_bfloat16 lo = __float2bfloat16(w - __bfloat162float(hi));
    Bhi[idx] = hi;
    Blo[idx] = lo;
}

// ======================================================================
// HMMA projection (unchanged, passing).
// ======================================================================
#define PAD_K 72
#define PSM_BIAS 0
#define PSM_AHI  768
#define PSM_ALO  (PSM_AHI + 128 * PAD_K * 2)
#define PSM_BHI  (PSM_ALO + 128 * PAD_K * 2)
#define PSM_BLO  (PSM_BHI + 192 * PAD_K * 2)
#define PSM_TOTAL (PSM_BLO + 192 * PAD_K * 2)   // 92928 bytes

template<int MODE>
__global__ void __launch_bounds__(256, 2) proj_mma_kernel(
        const float* __restrict__ src,
        const int*   __restrict__ hist_i,
        const float* __restrict__ alpha,
        const __nv_bfloat16* __restrict__ Bhi,
        const __nv_bfloat16* __restrict__ Blo,
        const float* __restrict__ bg,
        const float* __restrict__ bc,
        float* __restrict__ xg,
        float* __restrict__ xc)
{
    extern __shared__ char smem[];
    const uint32_t sbase = smem_u32(smem);
    const int tid = threadIdx.x;
    const int wid = tid >> 5;
    const int lane = tid & 31;
    const int m0 = blockIdx.x * 128;

    float* bs = (float*)(smem + PSM_BIAS);
    if (tid < 192) bs[tid] = (tid < 128) ? bg[tid] : bc[tid - 128];

    {
        const uint4* sh = (const uint4*)Bhi;
        const uint4* sl = (const uint4*)Blo;
#pragma unroll
        for (int i = 0; i < 6; i++) {
            int idx = tid + 256 * i;
            int n = idx >> 3, seg = idx & 7;
            int off = n * (PAD_K * 2) + seg * 16;
            *(uint4*)(smem + PSM_BHI + off) = sh[idx];
            *(uint4*)(smem + PSM_BLO + off) = sl[idx];
        }
    }

    {
        const int r = tid >> 1;
        const int half = tid & 1;
        const float* srow;
        float scale = 1.0f;
        if (MODE == 0) {
            srow = src + (size_t)hist_i[m0 + r] * 64;
        } else {
            srow = src + (size_t)(m0 + r) * 64;
            scale = alpha[m0 + r];
        }
        srow += half * 32;
        const int kb = half * 32;
#pragma unroll
        for (int c = 0; c < 4; c++) {
            float4 v0 = *(const float4*)(srow + 8 * c);
            float4 v1 = *(const float4*)(srow + 8 * c + 4);
            float vv[8] = {v0.x, v0.y, v0.z, v0.w, v1.x, v1.y, v1.z, v1.w};
            __nv_bfloat16 hb[8], lb[8];
#pragma unroll
            for (int e = 0; e < 8; e++) {
                float f = vv[e] * scale;
                hb[e] = __float2bfloat16(f);
                lb[e] = __float2bfloat16(f - __bfloat162float(hb[e]));
            }
            int off = r * (PAD_K * 2) + (kb + 8 * c) * 2;
            *(uint4*)(smem + PSM_AHI + off) = *(uint4*)hb;
            *(uint4*)(smem + PSM_ALO + off) = *(uint4*)lb;
        }
    }
    __syncthreads();

    const int arow = wid * 16 + (lane & 15);
    const int acolb = ((lane >> 4) << 3);
    const uint32_t a_off = (uint32_t)arow * (PAD_K * 2) + acolb * 2;
    const uint32_t aH_base = sbase + PSM_AHI + a_off;
    const uint32_t aL_base = sbase + PSM_ALO + a_off;

    const int bnrow_l = (lane & 7) + ((lane & 16) >> 1);
    const int bcol_l = (lane & 8);
    const uint32_t b_off_l = (uint32_t)bnrow_l * (PAD_K * 2) + bcol_l * 2;

    const int g = lane >> 2;
    const int tq = lane & 3;

#pragma unroll
    for (int nh = 0; nh < 2; nh++) {
        const uint32_t bH_base = sbase + PSM_BHI + b_off_l + (uint32_t)nh * 96 * (PAD_K * 2);
        const uint32_t bL_base = sbase + PSM_BLO + b_off_l + (uint32_t)nh * 96 * (PAD_K * 2);

        float acc[12][4];
#pragma unroll
        for (int i = 0; i < 12; i++)
#pragma unroll
            for (int qq = 0; qq < 4; qq++) acc[i][qq] = 0.0f;

#pragma unroll
        for (int ks = 0; ks < 4; ks++) {
            uint32_t aH[4], aL[4];
            ldsm_x4(aH[0], aH[1], aH[2], aH[3], aH_base + ks * 32);
            ldsm_x4(aL[0], aL[1], aL[2], aL[3], aL_base + ks * 32);
#pragma unroll
            for (int np = 0; np < 6; np++) {
                uint32_t bh0, bh1, bh2, bh3;
                ldsm_x4(bh0, bh1, bh2, bh3,
                        bH_base + (uint32_t)np * 16 * (PAD_K * 2) + ks * 32);
                mma16816(acc[2 * np],     aH, bh0, bh1);
                mma16816(acc[2 * np + 1], aH, bh2, bh3);
                mma16816(acc[2 * np],     aL, bh0, bh1);
                mma16816(acc[2 * np + 1], aL, bh2, bh3);
                uint32_t bl0, bl1, bl2, bl3;
                ldsm_x4(bl0, bl1, bl2, bl3,
                        bL_base + (uint32_t)np * 16 * (PAD_K * 2) + ks * 32);
                mma16816(acc[2 * np],     aH, bl0, bl1);
                mma16816(acc[2 * np + 1], aH, bl2, bl3);
            }
        }

        const int r0 = m0 + wid * 16 + g;
        const int r1 = r0 + 8;
#pragma unroll
        for (int nt = 0; nt < 12; nt++) {
            const int n = nh * 96 + nt * 8 + 2 * tq;
            const float bx = bs[n], by = bs[n + 1];
            float2 o0 = make_float2(acc[nt][0] + bx, acc[nt][1] + by);
            float2 o1 = make_float2(acc[nt][2] + bx, acc[nt][3] + by);
            if (n < 128) {
                *(float2*)(xg + (size_t)r0 * 128 + n) = o0;
                *(float2*)(xg + (size_t)r1 * 128 + n) = o1;
            } else {
                *(float2*)(xc + (size_t)r0 * 64 + (n - 128)) = o0;
                *(float2*)(xc + (size_t)r1 * 64 + (n - 128)) = o1;
            }
        }
    }
}

// ======================================================================
// GRU recurrence via HMMA v2: 16 batch rows per CTA, grid 256, 2 CTAs/SM.
//   gate[16x128] = h[16x64] @ Ug   (8 warps x 16 cols, 24 MMA each)
//   cand[16x64]  = rhs[16x64] @ Uc (8 warps x 8 cols, 12 MMA each)
// Same fragment maps / split-bf16 3-term as R14 (validated).
// ======================================================================
#define GSM_UG_HI 0
#define GSM_UG_LO (GSM_UG_HI + 128 * 144)
#define GSM_UC_HI (GSM_UG_LO + 128 * 144)
#define GSM_UC_LO (GSM_UC_HI + 64 * 144)
#define GSM_HA_HI (GSM_UC_LO + 64 * 144)
#define GSM_HA_LO (GSM_HA_HI + GM * 144)
#define GSM_RA_HI (GSM_HA_LO + GM * 144)
#define GSM_RA_LO (GSM_RA_HI + GM * 144)
#define GSM_HF    (GSM_RA_LO + GM * 144)         // fp32 [16][68]
#define GSM_ZF    (GSM_HF + GM * 68 * 4)         // fp32 [16][68]
#define GSM_MSK   (GSM_ZF + GM * 68 * 4)         // fp32 [16][200]
#define GSM_TOTAL (GSM_MSK + GM * 200 * 4)       // 86016 bytes

template<bool STORE_ALL>
__global__ void __launch_bounds__(256, 2) gru_tc_kernel(
        const float* __restrict__ xg,
        const float* __restrict__ xc,
        const float* __restrict__ mask,
        const float* __restrict__ Ug,   // [64,128]
        const float* __restrict__ Uc,   // [64,64]
        float* __restrict__ out)        // [B,T,64] or [B,64]
{
    extern __shared__ char smem[];
    const uint32_t sbase = smem_u32(smem);
    const int tid = threadIdx.x;
    const int wid = tid >> 5, lane = tid & 31;
    const int b0 = blockIdx.x * GM;

    // ---- stage UgT/UcT split-bf16 (scalar 2-byte stores) ----
    for (int idx = tid; idx < 128 * 64; idx += 256) {
        int k = idx >> 7, n = idx & 127;
        float w = Ug[k * 128 + n];
        __nv_bfloat16 hi = __float2bfloat16(w);
        *(__nv_bfloat16*)(smem + GSM_UG_HI + n * 144 + k * 2) = hi;
        *(__nv_bfloat16*)(smem + GSM_UG_LO + n * 144 + k * 2) =
            __float2bfloat16(w - __bfloat162float(hi));
    }
    for (int idx = tid; idx < 64 * 64; idx += 256) {
        int k = idx >> 6, n = idx & 63;
        float w = Uc[k * 64 + n];
        __nv_bfloat16 hi = __float2bfloat16(w);
        *(__nv_bfloat16*)(smem + GSM_UC_HI + n * 144 + k * 2) = hi;
        *(__nv_bfloat16*)(smem + GSM_UC_LO + n * 144 + k * 2) =
            __float2bfloat16(w - __bfloat162float(hi));
    }
    // zero hA (both planes) and h fp32
    for (int idx = tid; idx < (2 * GM * 144) / 16; idx += 256)
        ((uint4*)(smem + GSM_HA_HI))[idx] = make_uint4(0, 0, 0, 0);
    for (int idx = tid; idx < GM * 68; idx += 256)
        ((float*)(smem + GSM_HF))[idx] = 0.0f;
    // mask -> smem
    float* msk = (float*)(smem + GSM_MSK);
    for (int idx = tid; idx < GM * T; idx += 256) {
        int r = idx / T, t = idx - r * T;
        msk[idx] = mask[(size_t)(b0 + r) * T + t];
    }
    __syncthreads();

    const int g = lane >> 2, q = lane & 3;
    const int arow_l = lane & 15;
    const int acolb = (lane >> 4) << 3;
    const int bnrow_l = (lane & 7) + ((lane & 16) >> 1);
    const int bcol_l = lane & 8;

    const size_t xg0 = (size_t)(b0 + g) * (T * 128);
    const size_t xg1 = (size_t)(b0 + g + 8) * (T * 128);
    const size_t xc0 = (size_t)(b0 + g) * (T * 64);
    const size_t xc1 = (size_t)(b0 + g + 8) * (T * 64);

    const uint32_t aHg = sbase + GSM_HA_HI + (uint32_t)arow_l * 144 + acolb * 2;
    const uint32_t aLg = sbase + GSM_HA_LO + (uint32_t)arow_l * 144 + acolb * 2;
    const uint32_t aHc = sbase + GSM_RA_HI + (uint32_t)arow_l * 144 + acolb * 2;
    const uint32_t aLc = sbase + GSM_RA_LO + (uint32_t)arow_l * 144 + acolb * 2;
    const uint32_t bHg = sbase + GSM_UG_HI + (uint32_t)(wid * 16 + bnrow_l) * 144 + bcol_l * 2;
    const uint32_t bLg = sbase + GSM_UG_LO + (uint32_t)(wid * 16 + bnrow_l) * 144 + bcol_l * 2;
    const uint32_t bHc = sbase + GSM_UC_HI + (uint32_t)(wid * 8 + bnrow_l) * 144 + bcol_l * 2;
    const uint32_t bLc = sbase + GSM_UC_LO + (uint32_t)(wid * 8 + bnrow_l) * 144 + bcol_l * 2;

    float* hf = (float*)(smem + GSM_HF);
    float* zf = (float*)(smem + GSM_ZF);

    for (int t = 0; t < T; t++) {
        // ---------------- gate (16 cols per warp) ----------------
        float xgv[8];
#pragma unroll
        for (int nt = 0; nt < 2; nt++) {
            const int col = wid * 16 + nt * 8 + 2 * q;
            float2 v0 = *(const float2*)(xg + xg0 + (size_t)t * 128 + col);
            float2 v1 = *(const float2*)(xg + xg1 + (size_t)t * 128 + col);
            xgv[4 * nt + 0] = v0.x; xgv[4 * nt + 1] = v0.y;
            xgv[4 * nt + 2] = v1.x; xgv[4 * nt + 3] = v1.y;
        }

        float acc[2][4];
#pragma unroll
        for (int i = 0; i < 2; i++)
#pragma unroll
            for (int e = 0; e < 4; e++) acc[i][e] = 0.0f;

#pragma unroll
        for (int ks = 0; ks < 4; ks++) {
            uint32_t aH[4], aL[4];
            ldsm_x4(aH[0], aH[1], aH[2], aH[3], aHg + ks * 32);
            ldsm_x4(aL[0], aL[1], aL[2], aL[3], aLg + ks * 32);
            uint32_t c0, c1, c2, c3;
            ldsm_x4(c0, c1, c2, c3, bHg + ks * 32);
            mma16816(acc[0], aH, c0, c1);
            mma16816(acc[1], aH, c2, c3);
            mma16816(acc[0], aL, c0, c1);
            mma16816(acc[1], aL, c2, c3);
            ldsm_x4(c0, c1, c2, c3, bLg + ks * 32);
            mma16816(acc[0], aH, c0, c1);
            mma16816(acc[1], aH, c2, c3);
        }

        if (wid < 4) {
            // cols 0..63: rhs = sigmoid(gate) * h  -> split bf16
#pragma unroll
            for (int nt = 0; nt < 2; nt++) {
                const int col = wid * 16 + nt * 8 + 2 * q;
                float s0 = sigmoidf_fast(acc[nt][0] + xgv[4 * nt + 0]);
                float s1 = sigmoidf_fast(acc[nt][1] + xgv[4 * nt + 1]);
                float s2 = sigmoidf_fast(acc[nt][2] + xgv[4 * nt + 2]);
                float s3 = sigmoidf_fast(acc[nt][3] + xgv[4 * nt + 3]);
                float rh0 = s0 * hf[g * 68 + col];
                float rh1 = s1 * hf[g * 68 + col + 1];
                float rh2 = s2 * hf[(g + 8) * 68 + col];
                float rh3 = s3 * hf[(g + 8) * 68 + col + 1];
                split_pair(smem + GSM_RA_HI, smem + GSM_RA_LO, g * 144 + col * 2, rh0, rh1);
                split_pair(smem + GSM_RA_HI, smem + GSM_RA_LO, (g + 8) * 144 + col * 2, rh2, rh3);
            }
        } else {
            // cols 64..127: z
#pragma unroll
            for (int nt = 0; nt < 2; nt++) {
                const int zc = wid * 16 + nt * 8 + 2 * q - 64;
                zf[g * 68 + zc]           = sigmoidf_fast(acc[nt][0] + xgv[4 * nt + 0]);
                zf[g * 68 + zc + 1]       = sigmoidf_fast(acc[nt][1] + xgv[4 * nt + 1]);
                zf[(g + 8) * 68 + zc]     = sigmoidf_fast(acc[nt][2] + xgv[4 * nt + 2]);
                zf[(g + 8) * 68 + zc + 1] = sigmoidf_fast(acc[nt][3] + xgv[4 * nt + 3]);
            }
        }
        __syncthreads();

        // ---------------- candidate (8 cols per warp) ----------------
        const int ccol = wid * 8 + 2 * q;
        float xcv[4];
        {
            float2 v0 = *(const float2*)(xc + xc0 + (size_t)t * 64 + ccol);
            float2 v1 = *(const float2*)(xc + xc1 + (size_t)t * 64 + ccol);
            xcv[0] = v0.x; xcv[1] = v0.y; xcv[2] = v1.x; xcv[3] = v1.y;
        }

        float cac[4];
#pragma unroll
        for (int e = 0; e < 4; e++) cac[e] = 0.0f;

#pragma unroll
        for (int ks = 0; ks < 4; ks++) {
            uint32_t aH[4], aL[4];
            ldsm_x4(aH[0], aH[1], aH[2], aH[3], aHc + ks * 32);
            ldsm_x4(aL[0], aL[1], aL[2], aL[3], aLc + ks * 32);
            uint32_t c0, c1, c2, c3;
            ldsm_x4(c0, c1, c2, c3, bHc + ks * 32);   // only c0,c1 used (n8 tile)
            mma16816(cac, aH, c0, c1);
            mma16816(cac, aL, c0, c1);
            ldsm_x4(c0, c1, c2, c3, bLc + ks * 32);
            mma16816(cac, aH, c0, c1);
        }

        // epilogue: h update
        {
            float hn[4];
#pragma unroll
            for (int e = 0; e < 4; e++) {
                const int rr = (e < 2) ? g : (g + 8);
                const int cc = ccol + (e & 1);
                float cand = tanh_fast(cac[e] + xcv[e]);
                float z = zf[rr * 68 + cc];
                float h = hf[rr * 68 + cc];
                float v = fmaf(z, h - cand, cand);
                float m = msk[rr * T + t];
                hn[e] = fmaf(m, v - h, h);
                hf[rr * 68 + cc] = hn[e];
            }
            split_pair(smem + GSM_HA_HI, smem + GSM_HA_LO, g * 144 + ccol * 2, hn[0], hn[1]);
            split_pair(smem + GSM_HA_HI, smem + GSM_HA_LO, (g + 8) * 144 + ccol * 2, hn[2], hn[3]);
            if (STORE_ALL) {
                *(float2*)(out + (size_t)(b0 + g) * (T * 64) + (size_t)t * 64 + ccol) =
                    make_float2(hn[0], hn[1]);
                *(float2*)(out + (size_t)(b0 + g + 8) * (T * 64) + (size_t)t * 64 + ccol) =
                    make_float2(hn[2], hn[3]);
            }
        }
        __syncthreads();
    }

    if (!STORE_ALL) {
        for (int idx = tid; idx < GM * 64; idx += 256) {
            int r = idx >> 6, c = idx & 63;
            out[(size_t)(b0 + r) * 64 + c] = hf[r * 68 + c];
        }
    }
}

// ======================================================================
// DIN attention via HMMA, chunked (2 CTAs/SM) — unchanged from R12.
// ======================================================================
#define ACH 112
#define APK  72
#define APK2 88

#define ASM_QS    0
#define ASM_BASE  256
#define ASM_BA2   640
#define ASM_WA3   832
#define ASM_SC    992
#define ASM_RED   1888
#define ASM_KHI   2048
#define ASM_KLO   (ASM_KHI + ACH * APK * 2)
#define ASM_WHI   (ASM_KLO + ACH * APK * 2)
#define ASM_WLO   (ASM_WHI + 80 * APK * 2)
#define ASM_W2HI  (ASM_WLO + 80 * APK * 2)
#define ASM_W2LO  (ASM_W2HI + 48 * APK2 * 2)
#define ASM_D1HI  (ASM_W2LO + 48 * APK2 * 2)
#define ASM_D1LO  (ASM_D1HI + ACH * APK2 * 2)
#define ASM_TOTAL (ASM_D1LO + ACH * APK2 * 2)   // 113664

__global__ void __launch_bounds__(256, 2) attn_mma_kernel(
        const int*   __restrict__ item_i,
        const float* __restrict__ item_emb,
        const float* __restrict__ rnn1,
        const float* __restrict__ mask,
        const float* __restrict__ Wa1, const float* __restrict__ ba1,
        const float* __restrict__ Wa2, const float* __restrict__ ba2,
        const float* __restrict__ Wa3, const float* __restrict__ ba3,
        float* __restrict__ alpha)
{
    extern __shared__ char smem[];
    const uint32_t sbase = smem_u32(smem);
    const int b = blockIdx.x;
    const int tid = threadIdx.x;
    const int wid = tid >> 5, lane = tid & 31;

    float* qs   = (float*)(smem + ASM_QS);
    float* base = (float*)(smem + ASM_BASE);
    float* ba2s = (float*)(smem + ASM_BA2);
    float* wa3s = (float*)(smem + ASM_WA3);
    float* sc   = (float*)(smem + ASM_SC);
    float* red  = (float*)(smem + ASM_RED);

    if (tid < 64) qs[tid] = item_emb[(size_t)item_i[b] * 64 + tid];
    if (tid >= 64 && tid < 112) ba2s[tid - 64] = (tid - 64 < 40) ? ba2[tid - 64] : 0.0f;
    if (tid >= 112 && tid < 152) wa3s[tid - 112] = Wa3[tid - 112];
    for (int i = tid; i < 88; i += 256) {
        int r = 40 + i / 11, s = i % 11;
        *(uint4*)(smem + ASM_W2HI + r * 176 + s * 16) = make_uint4(0, 0, 0, 0);
        *(uint4*)(smem + ASM_W2LO + r * 176 + s * 16) = make_uint4(0, 0, 0, 0);
    }
    __syncthreads();

    if (tid < 80) {
        float acc = ba1[tid];
#pragma unroll 8
        for (int k = 0; k < 64; k++)
            acc = fmaf(qs[k], Wa1[k * 80 + tid] + Wa1[(128 + k) * 80 + tid], acc);
        base[tid] = acc;
    }
    for (int idx = tid; idx < 5120; idx += 256) {
        int k = idx / 80, c = idx - k * 80;
        float w = Wa1[(64 + k) * 80 + c] - Wa1[(128 + k) * 80 + c]
                + qs[k] * Wa1[(192 + k) * 80 + c];
        __nv_bfloat16 hi = __float2bfloat16(w);
        *(__nv_bfloat16*)(smem + ASM_WHI + c * 144 + k * 2) = hi;
        *(__nv_bfloat16*)(smem + ASM_WLO + c * 144 + k * 2) =
            __float2bfloat16(w - __bfloat162float(hi));
    }
    for (int idx = tid; idx < 3200; idx += 256) {
        int k = idx / 40, n = idx - k * 40;
        float w = Wa2[idx];
        __nv_bfloat16 hi = __float2bfloat16(w);
        *(__nv_bfloat16*)(smem + ASM_W2HI + n * 176 + k * 2) = hi;
        *(__nv_bfloat16*)(smem + ASM_W2LO + n * 176 + k * 2) =
            __float2bfloat16(w - __bfloat162float(hi));
    }

    const int arow_l = lane & 15;
    const int acolb  = (lane >> 4) << 3;
    const int bnrow_l = (lane & 7) + ((lane & 16) >> 1);
    const int bcol_l  = lane & 8;
    const int g = lane >> 2, q = lane & 3;
    const float ba3v = ba3[0];

    for (int cc = 0; cc < 2; cc++) {
        const int t0 = cc * ACH;

        __syncthreads();
        for (int idx = tid; idx < ACH * 16; idx += 256) {
            int r = idx >> 4, c4 = idx & 15;
            int tg = t0 + r; if (tg > T - 1) tg = T - 1;
            float4 v = *(const float4*)(rnn1 + ((size_t)b * T + tg) * 64 + c4 * 4);
            __nv_bfloat16 h[4], l[4];
            h[0] = __float2bfloat16(v.x); l[0] = __float2bfloat16(v.x - __bfloat162float(h[0]));
            h[1] = __float2bfloat16(v.y); l[1] = __float2bfloat16(v.y - __bfloat162float(h[1]));
            h[2] = __float2bfloat16(v.z); l[2] = __float2bfloat16(v.z - __bfloat162float(h[2]));
            h[3] = __float2bfloat16(v.w); l[3] = __float2bfloat16(v.w - __bfloat162float(h[3]));
            int off = r * 144 + c4 * 8;
            *(uint2*)(smem + ASM_KHI + off) = *(uint2*)h;
            *(uint2*)(smem + ASM_KLO + off) = *(uint2*)l;
        }
        __syncthreads();

        for (int mtl = wid; mtl < 7; mtl += 8) {
            float acc[10][4];
#pragma unroll
            for (int nt = 0; nt < 10; nt++) {
                float b0 = base[nt * 8 + 2 * q], b1 = base[nt * 8 + 2 * q + 1];
                acc[nt][0] = b0; acc[nt][1] = b1; acc[nt][2] = b0; acc[nt][3] = b1;
            }
            const uint32_t aHb = sbase + ASM_KHI + (uint32_t)(mtl * 16 + arow_l) * 144 + acolb * 2;
            const uint32_t aLb = sbase + ASM_KLO + (uint32_t)(mtl * 16 + arow_l) * 144 + acolb * 2;
            const uint32_t bHb = sbase + ASM_WHI + (uint32_t)bnrow_l * 144 + bcol_l * 2;
            const uint32_t bLb = sbase + ASM_WLO + (uint32_t)bnrow_l * 144 + bcol_l * 2;
#pragma unroll
            for (int ks = 0; ks < 4; ks++) {
                uint32_t aH[4], aL[4];
                ldsm_x4(aH[0], aH[1], aH[2], aH[3], aHb + ks * 32);
                ldsm_x4(aL[0], aL[1], aL[2], aL[3], aLb + ks * 32);
#pragma unroll
                for (int np = 0; np < 5; np++) {
                    uint32_t c0, c1, c2, c3;
                    ldsm_x4(c0, c1, c2, c3, bHb + (uint32_t)np * 16 * 144 + ks * 32);
                    mma16816(acc[2 * np],     aH, c0, c1);
                    mma16816(acc[2 * np + 1], aH, c2, c3);
                    mma16816(acc[2 * np],     aL, c0, c1);
                    mma16816(acc[2 * np + 1], aL, c2, c3);
                    ldsm_x4(c0, c1, c2, c3, bLb + (uint32_t)np * 16 * 144 + ks * 32);
                    mma16816(acc[2 * np],     aH, c0, c1);
                    mma16816(acc[2 * np + 1], aH, c2, c3);
                }
            }
            const int r0 = mtl * 16 + g, r1 = r0 + 8;
#pragma unroll
            for (int nt = 0; nt < 10; nt++) {
                const int c0 = nt * 8 + 2 * q;
                float s00 = sigmoidf_fast(acc[nt][0]);
                float s01 = sigmoidf_fast(acc[nt][1]);
                float s10 = sigmoidf_fast(acc[nt][2]);
                float s11 = sigmoidf_fast(acc[nt][3]);
                split_pair(smem + ASM_D1HI, smem + ASM_D1LO, r0 * 176 + c0 * 2, s00, s01);
                split_pair(smem + ASM_D1HI, smem + ASM_D1LO, r1 * 176 + c0 * 2, s10, s11);
            }
        }
        __syncthreads();

        for (int mtl = wid; mtl < 7; mtl += 8) {
            float acc[6][4];
#pragma unroll
            for (int nt = 0; nt < 6; nt++) {
                float b0 = ba2s[nt * 8 + 2 * q], b1 = ba2s[nt * 8 + 2 * q + 1];
                acc[nt][0] = b0; acc[nt][1] = b1; acc[nt][2] = b0; acc[nt][3] = b1;
            }
            const uint32_t aHb = sbase + ASM_D1HI + (uint32_t)(mtl * 16 + arow_l) * 176 + acolb * 2;
            const uint32_t aLb = sbase + ASM_D1LO + (uint32_t)(mtl * 16 + arow_l) * 176 + acolb * 2;
            const uint32_t bHb = sbase + ASM_W2HI + (uint32_t)bnrow_l * 176 + bcol_l * 2;
            const uint32_t bLb = sbase + ASM_W2LO + (uint32_t)bnrow_l * 176 + bcol_l * 2;
#pragma unroll
            for (int ks = 0; ks < 5; ks++) {
                uint32_t aH[4], aL[4];
                ldsm_x4(aH[0], aH[1], aH[2], aH[3], aHb + ks * 32);
                ldsm_x4(aL[0], aL[1], aL[2], aL[3], aLb + ks * 32);
#pragma unroll
                for (int np = 0; np < 3; np++) {
                    uint32_t c0, c1, c2, c3;
                    ldsm_x4(c0, c1, c2, c3, bHb + (uint32_t)np * 16 * 176 + ks * 32);
                    mma16816(acc[2 * np],     aH, c0, c1);
                    mma16816(acc[2 * np + 1], aH, c2, c3);
                    mma16816(acc[2 * np],     aL, c0, c1);
                    mma16816(acc[2 * np + 1], aL, c2, c3);
                    ldsm_x4(c0, c1, c2, c3, bLb + (uint32_t)np * 16 * 176 + ks * 32);
                    mma16816(acc[2 * np],     aH, c0, c1);
                    mma16816(acc[2 * np + 1], aH, c2, c3);
                }
            }
            float s0 = 0.0f, s1 = 0.0f;
#pragma unroll
            for (int nt = 0; nt < 5; nt++) {
                const int c0 = nt * 8 + 2 * q;
                float w0 = wa3s[c0], w1 = wa3s[c0 + 1];
                s0 = fmaf(sigmoidf_fast(acc[nt][0]), w0, s0);
                s0 = fmaf(sigmoidf_fast(acc[nt][1]), w1, s0);
                s1 = fmaf(sigmoidf_fast(acc[nt][2]), w0, s1);
                s1 = fmaf(sigmoidf_fast(acc[nt][3]), w1, s1);
            }
            s0 += __shfl_xor_sync(0xffffffffu, s0, 1);
            s0 += __shfl_xor_sync(0xffffffffu, s0, 2);
            s1 += __shfl_xor_sync(0xffffffffu, s1, 1);
            s1 += __shfl_xor_sync(0xffffffffu, s1, 2);
            if (q == 0) {
                int t0g = t0 + mtl * 16 + g, t1g = t0g + 8;
                if (t0g < T) {
                    float m = mask[(size_t)b * T + t0g];
                    sc[t0g] = (m > 0.0f) ? (s0 + ba3v) : -1e9f;
                }
                if (t1g < T) {
                    float m = mask[(size_t)b * T + t1g];
                    sc[t1g] = (m > 0.0f) ? (s1 + ba3v) : -1e9f;
                }
            }
        }
    }
    __syncthreads();

    float v = (tid < T) ? sc[tid] : -FLT_MAX;
#pragma unroll
    for (int o = 16; o > 0; o >>= 1) v = fmaxf(v, __shfl_xor_sync(0xffffffffu, v, o));
    if (lane == 0) red[wid] = v;
    __syncthreads();
    if (tid == 0) {
        float mx = red[0];
#pragma unroll
        for (int w = 1; w < 8; w++) mx = fmaxf(mx, red[w]);
        red[12] = mx;
    }
    __syncthreads();
    float mx = red[12];

    float e = (tid < T) ? __expf(sc[tid] - mx) : 0.0f;
    float s = e;
#pragma unroll
    for (int o = 16; o > 0; o >>= 1) s += __shfl_xor_sync(0xffffffffu, s, o);
    __syncthreads();
    if (lane == 0) red[wid] = s;
    __syncthreads();
    if (tid == 0) {
        float sum = 0.0f;
#pragma unroll
        for (int w = 0; w < 8; w++) sum += red[w];
        red[13] = 1.0f / sum;
    }
    __syncthreads();
    if (tid < T) alpha[(size_t)b * T + tid] = e * red[13];
}

// ======================================================================
// FCN head + hist_sum (unchanged).
// ======================================================================
__global__ void fcn_kernel(const int* __restrict__ u, const int* __restrict__ ii,
                           const int* __restrict__ hist_i,
                           const float* __restrict__ item_emb,
                           const float* __restrict__ user_emb,
                           const float* __restrict__ final2,
                           const float* __restrict__ W1, const float* __restrict__ b1,
                           const float* __restrict__ p1,
                           const float* __restrict__ W2, const float* __restrict__ b2,
                           const float* __restrict__ p2,
                           const float* __restrict__ W3, const float* __restrict__ b3,
                           float* __restrict__ out)
{
    __shared__ float xs[320];
    __shared__ float h1s[128];
    __shared__ float h2s[40];

    const int b = blockIdx.x;
    const int tid = threadIdx.x;

    if (tid < 64) {
        const int* hi = hist_i + (size_t)b * T;
        float s0 = 0.f, s1 = 0.f, s2 = 0.f, s3 = 0.f;
        for (int t = 0; t < T; t += 4) {
            s0 += item_emb[(size_t)hi[t]     * 64 + tid];
            s1 += item_emb[(size_t)hi[t + 1] * 64 + tid];
            s2 += item_emb[(size_t)hi[t + 2] * 64 + tid];
            s3 += item_emb[(size_t)hi[t + 3] * 64 + tid];
        }
        xs[128 + tid] = (s0 + s1) + (s2 + s3);
    } else {
        int j = tid - 64;
        xs[j]       = user_emb[(size_t)u[b]  * 64 + j];
        xs[64 + j]  = item_emb[(size_t)ii[b] * 64 + j];
        xs[256 + j] = final2[(size_t)b * 64 + j];
    }
    __syncthreads();
    if (tid < 64) xs[192 + tid] = xs[64 + tid] * xs[128 + tid];
    __syncthreads();

    {
        float a0 = b1[tid], a1 = 0.0f;
#pragma unroll 8
        for (int k = 0; k < 320; k += 2) {
            a0 = fmaf(xs[k],     W1[k * 128 + tid],       a0);
            a1 = fmaf(xs[k + 1], W1[(k + 1) * 128 + tid], a1);
        }
        float h = a0 + a1;
        h1s[tid] = (h >= 0.0f) ? h : p1[tid] * h;
    }
    __syncthreads();

    if (tid < 40) {
        float a0 = b2[tid], a1 = 0.0f;
#pragma unroll 16
        for (int k = 0; k < 128; k += 2) {
            a0 = fmaf(h1s[k],     W2[k * 40 + tid],       a0);
            a1 = fmaf(h1s[k + 1], W2[(k + 1) * 40 + tid], a1);
        }
        float h = a0 + a1;
        h2s[tid] = (h >= 0.0f) ? h : p2[tid] * h;
    }
    __syncthreads();

    if (tid == 0) {
        float acc = b3[0];
#pragma unroll
        for (int k = 0; k < 40; k++) acc = fmaf(h2s[k], W3[k], acc);
        out[b] = acc;
    }
}

// ======================================================================
extern "C" void kernel_launch(void* const* d_in, const int* in_sizes, int n_in,
                              void* d_out, int out_size)
{
    const int*   u        = (const int*)d_in[0];
    const int*   ii       = (const int*)d_in[1];
    const int*   hist_i   = (const int*)d_in[2];
    const float* mask     = (const float*)d_in[3];
    const float* item_emb = (const float*)d_in[4];
    const float* user_emb = (const float*)d_in[5];
    const float* g1_Wg = (const float*)d_in[6];
    const float* g1_Ug = (const float*)d_in[7];
    const float* g1_bg = (const float*)d_in[8];
    const float* g1_Wc = (const float*)d_in[9];
    const float* g1_Uc = (const float*)d_in[10];
    const float* g1_bc = (const float*)d_in[11];
    const float* Wa1 = (const float*)d_in[12];
    const float* ba1 = (const float*)d_in[13];
    const float* Wa2 = (const float*)d_in[14];
    const float* ba2 = (const float*)d_in[15];
    const float* Wa3 = (const float*)d_in[16];
    const float* ba3 = (const float*)d_in[17];
    const float* g2_Wg = (const float*)d_in[18];
    const float* g2_Ug = (const float*)d_in[19];
    const float* g2_bg = (const float*)d_in[20];
    const float* g2_Wc = (const float*)d_in[21];
    const float* g2_Uc = (const float*)d_in[22];
    const float* g2_bc = (const float*)d_in[23];
    const float* W1 = (const float*)d_in[24];
    const float* b1 = (const float*)d_in[25];
    const float* p1 = (const float*)d_in[26];
    const float* W2 = (const float*)d_in[27];
    const float* b2 = (const float*)d_in[28];
    const float* p2 = (const float*)d_in[29];
    const float* W3 = (const float*)d_in[30];
    const float* b3 = (const float*)d_in[31];
    float* out = (float*)d_out;

    float *xg, *xc, *rnn1, *alpha, *final2;
    __nv_bfloat16 *bh1, *bl1, *bh2, *bl2;
    cudaGetSymbolAddress((void**)&xg,     g_xg);
    cudaGetSymbolAddress((void**)&xc,     g_xc);
    cudaGetSymbolAddress((void**)&rnn1,   g_rnn1);
    cudaGetSymbolAddress((void**)&alpha,  g_alpha);
    cudaGetSymbolAddress((void**)&final2, g_final2);
    cudaGetSymbolAddress((void**)&bh1, g_bh1);
    cudaGetSymbolAddress((void**)&bl1, g_bl1);
    cudaGetSymbolAddress((void**)&bh2, g_bh2);
    cudaGetSymbolAddress((void**)&bl2, g_bl2);

    cudaFuncSetAttribute(proj_mma_kernel<0>, cudaFuncAttributeMaxDynamicSharedMemorySize, PSM_TOTAL);
    cudaFuncSetAttribute(proj_mma_kernel<1>, cudaFuncAttributeMaxDynamicSharedMemorySize, PSM_TOTAL);
    cudaFuncSetAttribute(gru_tc_kernel<true>,  cudaFuncAttributeMaxDynamicSharedMemorySize, GSM_TOTAL);
    cudaFuncSetAttribute(gru_tc_kernel<false>, cudaFuncAttributeMaxDynamicSharedMemorySize, GSM_TOTAL);
    cudaFuncSetAttribute(attn_mma_kernel, cudaFuncAttributeMaxDynamicSharedMemorySize, ASM_TOTAL);

    // 0) split projection weights to bf16 hi/lo (both GRUs)
    wsplit_kernel<<<48, 256>>>(g1_Wg, g1_Wc, bh1, bl1);
    wsplit_kernel<<<48, 256>>>(g2_Wg, g2_Wc, bh2, bl2);
    // 1) GRU1 input projections via HMMA
    proj_mma_kernel<0><<<BT / 128, 256, PSM_TOTAL>>>(item_emb, hist_i, nullptr,
                                                     bh1, bl1, g1_bg, g1_bc, xg, xc);
    // 2) GRU1 recurrence via HMMA (grid 256, 2 CTAs/SM) -> rnn1
    gru_tc_kernel<true><<<B / GM, 256, GSM_TOTAL>>>(xg, xc, mask, g1_Ug, g1_Uc, rnn1);
    // 3) DIN attention via HMMA (chunked, 2 CTAs/SM) -> alpha
    attn_mma_kernel<<<B, 256, ASM_TOTAL>>>(ii, item_emb, rnn1, mask,
                                           Wa1, ba1, Wa2, ba2, Wa3, ba3, alpha);
    // 4) GRU2 input projections via HMMA (rnn1 * alpha)
    proj_mma_kernel<1><<<BT / 128, 256, PSM_TOTAL>>>(rnn1, nullptr, alpha,
                                                     bh2, bl2, g2_bg, g2_bc, xg, xc);
    // 5) GRU2 recurrence via HMMA -> final2 only
    gru_tc_kernel<false><<<B / GM, 256, GSM_TOTAL>>>(xg, xc, mask, g2_Ug, g2_Uc, final2);
    // 6) FCN head -> logits
    fcn_kernel<<<B, 128>>>(u, ii, hist_i, item_emb, user_emb, final2,
                           W1, b1, p1, W2, b2, p2, W3, b3, out);
}

// round 16
// speedup vs baseline: 1.8867x; 1.0036x over previous
#include <cuda_runtime.h>
#include <cuda_bf16.h>
#include <math.h>
#include <float.h>
#include <cstdint>

#define B 4096
#define T 200
#define BT (B*T)
#define GM 16   // batch rows per GRU-TC block (grid = 256, 3 CTAs/SM)

// ---------------- scratch (device globals: no allocs allowed) ----------------
__device__ float g_xg[(size_t)BT * 128];
__device__ float g_xc[(size_t)BT * 64];
__device__ float g_rnn1[(size_t)BT * 64];
__device__ float g_alpha[BT];
__device__ float g_final2[B * 64];
// split-bf16 weights for the two projection GEMMs: layout [n(192)][k(64)]
__device__ __nv_bfloat16 g_bh1[192 * 64];
__device__ __nv_bfloat16 g_bl1[192 * 64];
__device__ __nv_bfloat16 g_bh2[192 * 64];
__device__ __nv_bfloat16 g_bl2[192 * 64];

__device__ __forceinline__ float sigmoidf_fast(float x) {
    return 1.0f / (1.0f + __expf(-x));
}
__device__ __forceinline__ float tanh_fast(float x) {
    float ax = fabsf(x);
    float e = __expf(-2.0f * ax);
    float th = __fdividef(1.0f - e, 1.0f + e);
    return copysignf(th, x);
}

__device__ __forceinline__ uint32_t smem_u32(const void* p) {
    uint32_t a;
    asm("{ .reg .u64 t; cvta.to.shared.u64 t, %1; cvt.u32.u64 %0, t; }" : "=r"(a) : "l"(p));
    return a;
}
__device__ __forceinline__ void ldsm_x4(uint32_t& r0, uint32_t& r1, uint32_t& r2, uint32_t& r3,
                                        uint32_t addr) {
    asm volatile("ldmatrix.sync.aligned.m8n8.x4.shared.b16 {%0,%1,%2,%3}, [%4];"
                 : "=r"(r0), "=r"(r1), "=r"(r2), "=r"(r3) : "r"(addr));
}
__device__ __forceinline__ void mma16816(float* c, const uint32_t* a, uint32_t b0, uint32_t b1) {
    asm volatile("mma.sync.aligned.m16n8k16.row.col.f32.bf16.bf16.f32 "
                 "{%0,%1,%2,%3}, {%4,%5,%6,%7}, {%8,%9}, {%0,%1,%2,%3};"
                 : "+f"(c[0]), "+f"(c[1]), "+f"(c[2]), "+f"(c[3])
                 : "r"(a[0]), "r"(a[1]), "r"(a[2]), "r"(a[3]), "r"(b0), "r"(b1));
}
__device__ __forceinline__ void store_bf16_pair(char* basep, int byteoff, float v0, float v1,
                                                char* basel, float l0, float l1) {
    __nv_bfloat162 h, l;
    h.x = __float2bfloat16(v0); h.y = __float2bfloat16(v1);
    l.x = __float2bfloat16(l0); l.y = __float2bfloat16(l1);
    *(__nv_bfloat162*)(basep + byteoff) = h;
    *(__nv_bfloat162*)(basel + byteoff) = l;
}
// split fp32 -> hi/lo bf16 pair store at byte offset (pair of adjacent cols)
__device__ __forceinline__ void split_pair(char* hi_base, char* lo_base, int byteoff,
                                           float v0, float v1) {
    __nv_bfloat16 h0 = __float2bfloat16(v0), h1 = __float2bfloat16(v1);
    store_bf16_pair(hi_base, byteoff, v0, v1, lo_base,
                    v0 - __bfloat162float(h0), v1 - __bfloat162float(h1));
}

// ======================================================================
// Weight split prep: W[64,128]|[64,64] fp32 -> Bhi/Blo [n=192][k=64] bf16
// ======================================================================
__global__ void wsplit_kernel(const float* __restrict__ Wg, const float* __restrict__ Wc,
                              __nv_bfloat16* __restrict__ Bhi, __nv_bfloat16* __restrict__ Blo)
{
    int idx = blockIdx.x * 256 + threadIdx.x;
    if (idx >= 192 * 64) return;
    int n = idx >> 6, k = idx & 63;
    float w = (n < 128) ? Wg[k * 128 + n] : Wc[k * 64 + (n - 128)];
    __nv_bfloat16 hi = __float2bfloat16(w);
    __nv_bfloat16 lo = __float2bfloat16(w - __bfloat162float(hi));
    Bhi[idx] = hi;
    Blo[idx] = lo;
}

// ======================================================================
// HMMA projection (unchanged, passing).
// ======================================================================
#define PAD_K 72
#define PSM_BIAS 0
#define PSM_AHI  768
#define PSM_ALO  (PSM_AHI + 128 * PAD_K * 2)
#define PSM_BHI  (PSM_ALO + 128 * PAD_K * 2)
#define PSM_BLO  (PSM_BHI + 192 * PAD_K * 2)
#define PSM_TOTAL (PSM_BLO + 192 * PAD_K * 2)   // 92928 bytes

template<int MODE>
__global__ void __launch_bounds__(256, 2) proj_mma_kernel(
        const float* __restrict__ src,
        const int*   __restrict__ hist_i,
        const float* __restrict__ alpha,
        const __nv_bfloat16* __restrict__ Bhi,
        const __nv_bfloat16* __restrict__ Blo,
        const float* __restrict__ bg,
        const float* __restrict__ bc,
        float* __restrict__ xg,
        float* __restrict__ xc)
{
    extern __shared__ char smem[];
    const uint32_t sbase = smem_u32(smem);
    const int tid = threadIdx.x;
    const int wid = tid >> 5;
    const int lane = tid & 31;
    const int m0 = blockIdx.x * 128;

    float* bs = (float*)(smem + PSM_BIAS);
    if (tid < 192) bs[tid] = (tid < 128) ? bg[tid] : bc[tid - 128];

    {
        const uint4* sh = (const uint4*)Bhi;
        const uint4* sl = (const uint4*)Blo;
#pragma unroll
        for (int i = 0; i < 6; i++) {
            int idx = tid + 256 * i;
            int n = idx >> 3, seg = idx & 7;
            int off = n * (PAD_K * 2) + seg * 16;
            *(uint4*)(smem + PSM_BHI + off) = sh[idx];
            *(uint4*)(smem + PSM_BLO + off) = sl[idx];
        }
    }

    {
        const int r = tid >> 1;
        const int half = tid & 1;
        const float* srow;
        float scale = 1.0f;
        if (MODE == 0) {
            srow = src + (size_t)hist_i[m0 + r] * 64;
        } else {
            srow = src + (size_t)(m0 + r) * 64;
            scale = alpha[m0 + r];
        }
        srow += half * 32;
        const int kb = half * 32;
#pragma unroll
        for (int c = 0; c < 4; c++) {
            float4 v0 = *(const float4*)(srow + 8 * c);
            float4 v1 = *(const float4*)(srow + 8 * c + 4);
            float vv[8] = {v0.x, v0.y, v0.z, v0.w, v1.x, v1.y, v1.z, v1.w};
            __nv_bfloat16 hb[8], lb[8];
#pragma unroll
            for (int e = 0; e < 8; e++) {
                float f = vv[e] * scale;
                hb[e] = __float2bfloat16(f);
                lb[e] = __float2bfloat16(f - __bfloat162float(hb[e]));
            }
            int off = r * (PAD_K * 2) + (kb + 8 * c) * 2;
            *(uint4*)(smem + PSM_AHI + off) = *(uint4*)hb;
            *(uint4*)(smem + PSM_ALO + off) = *(uint4*)lb;
        }
    }
    __syncthreads();

    const int arow = wid * 16 + (lane & 15);
    const int acolb = ((lane >> 4) << 3);
    const uint32_t a_off = (uint32_t)arow * (PAD_K * 2) + acolb * 2;
    const uint32_t aH_base = sbase + PSM_AHI + a_off;
    const uint32_t aL_base = sbase + PSM_ALO + a_off;

    const int bnrow_l = (lane & 7) + ((lane & 16) >> 1);
    const int bcol_l = (lane & 8);
    const uint32_t b_off_l = (uint32_t)bnrow_l * (PAD_K * 2) + bcol_l * 2;

    const int g = lane >> 2;
    const int tq = lane & 3;

#pragma unroll
    for (int nh = 0; nh < 2; nh++) {
        const uint32_t bH_base = sbase + PSM_BHI + b_off_l + (uint32_t)nh * 96 * (PAD_K * 2);
        const uint32_t bL_base = sbase + PSM_BLO + b_off_l + (uint32_t)nh * 96 * (PAD_K * 2);

        float acc[12][4];
#pragma unroll
        for (int i = 0; i < 12; i++)
#pragma unroll
            for (int qq = 0; qq < 4; qq++) acc[i][qq] = 0.0f;

#pragma unroll
        for (int ks = 0; ks < 4; ks++) {
            uint32_t aH[4], aL[4];
            ldsm_x4(aH[0], aH[1], aH[2], aH[3], aH_base + ks * 32);
            ldsm_x4(aL[0], aL[1], aL[2], aL[3], aL_base + ks * 32);
#pragma unroll
            for (int np = 0; np < 6; np++) {
                uint32_t bh0, bh1, bh2, bh3;
                ldsm_x4(bh0, bh1, bh2, bh3,
                        bH_base + (uint32_t)np * 16 * (PAD_K * 2) + ks * 32);
                mma16816(acc[2 * np],     aH, bh0, bh1);
                mma16816(acc[2 * np + 1], aH, bh2, bh3);
                mma16816(acc[2 * np],     aL, bh0, bh1);
                mma16816(acc[2 * np + 1], aL, bh2, bh3);
                uint32_t bl0, bl1, bl2, bl3;
                ldsm_x4(bl0, bl1, bl2, bl3,
                        bL_base + (uint32_t)np * 16 * (PAD_K * 2) + ks * 32);
                mma16816(acc[2 * np],     aH, bl0, bl1);
                mma16816(acc[2 * np + 1], aH, bl2, bl3);
            }
        }

        const int r0 = m0 + wid * 16 + g;
        const int r1 = r0 + 8;
#pragma unroll
        for (int nt = 0; nt < 12; nt++) {
            const int n = nh * 96 + nt * 8 + 2 * tq;
            const float bx = bs[n], by = bs[n + 1];
            float2 o0 = make_float2(acc[nt][0] + bx, acc[nt][1] + by);
            float2 o1 = make_float2(acc[nt][2] + bx, acc[nt][3] + by);
            if (n < 128) {
                *(float2*)(xg + (size_t)r0 * 128 + n) = o0;
                *(float2*)(xg + (size_t)r1 * 128 + n) = o1;
            } else {
                *(float2*)(xc + (size_t)r0 * 64 + (n - 128)) = o0;
                *(float2*)(xc + (size_t)r1 * 64 + (n - 128)) = o1;
            }
        }
    }
}

// ======================================================================
// GRU recurrence via HMMA v3: 16 rows/CTA, grid 256, mask as uint8 ->
// smem 76,416 B -> 3 CTAs/SM. Same fragment maps / split-bf16 as R15.
// ======================================================================
#define GSM_UG_HI 0
#define GSM_UG_LO (GSM_UG_HI + 128 * 144)
#define GSM_UC_HI (GSM_UG_LO + 128 * 144)
#define GSM_UC_LO (GSM_UC_HI + 64 * 144)
#define GSM_HA_HI (GSM_UC_LO + 64 * 144)
#define GSM_HA_LO (GSM_HA_HI + GM * 144)
#define GSM_RA_HI (GSM_HA_LO + GM * 144)
#define GSM_RA_LO (GSM_RA_HI + GM * 144)
#define GSM_HF    (GSM_RA_LO + GM * 144)         // fp32 [16][68]
#define GSM_ZF    (GSM_HF + GM * 68 * 4)         // fp32 [16][68]
#define GSM_MSK   (GSM_ZF + GM * 68 * 4)         // uint8 [16][200]
#define GSM_TOTAL (GSM_MSK + GM * T)             // 76416 bytes

template<bool STORE_ALL>
__global__ void __launch_bounds__(256, 3) gru_tc_kernel(
        const float* __restrict__ xg,
        const float* __restrict__ xc,
        const float* __restrict__ mask,
        const float* __restrict__ Ug,   // [64,128]
        const float* __restrict__ Uc,   // [64,64]
        float* __restrict__ out)        // [B,T,64] or [B,64]
{
    extern __shared__ char smem[];
    const uint32_t sbase = smem_u32(smem);
    const int tid = threadIdx.x;
    const int wid = tid >> 5, lane = tid & 31;
    const int b0 = blockIdx.x * GM;

    // ---- stage UgT/UcT split-bf16 (scalar 2-byte stores) ----
    for (int idx = tid; idx < 128 * 64; idx += 256) {
        int k = idx >> 7, n = idx & 127;
        float w = Ug[k * 128 + n];
        __nv_bfloat16 hi = __float2bfloat16(w);
        *(__nv_bfloat16*)(smem + GSM_UG_HI + n * 144 + k * 2) = hi;
        *(__nv_bfloat16*)(smem + GSM_UG_LO + n * 144 + k * 2) =
            __float2bfloat16(w - __bfloat162float(hi));
    }
    for (int idx = tid; idx < 64 * 64; idx += 256) {
        int k = idx >> 6, n = idx & 63;
        float w = Uc[k * 64 + n];
        __nv_bfloat16 hi = __float2bfloat16(w);
        *(__nv_bfloat16*)(smem + GSM_UC_HI + n * 144 + k * 2) = hi;
        *(__nv_bfloat16*)(smem + GSM_UC_LO + n * 144 + k * 2) =
            __float2bfloat16(w - __bfloat162float(hi));
    }
    // zero hA (both planes) and h fp32
    for (int idx = tid; idx < (2 * GM * 144) / 16; idx += 256)
        ((uint4*)(smem + GSM_HA_HI))[idx] = make_uint4(0, 0, 0, 0);
    for (int idx = tid; idx < GM * 68; idx += 256)
        ((float*)(smem + GSM_HF))[idx] = 0.0f;
    // mask -> smem (binary -> uint8)
    unsigned char* msk = (unsigned char*)(smem + GSM_MSK);
    for (int idx = tid; idx < GM * T; idx += 256) {
        int r = idx / T, t = idx - r * T;
        msk[idx] = (mask[(size_t)(b0 + r) * T + t] > 0.0f) ? 1 : 0;
    }
    __syncthreads();

    const int g = lane >> 2, q = lane & 3;
    const int arow_l = lane & 15;
    const int acolb = (lane >> 4) << 3;
    const int bnrow_l = (lane & 7) + ((lane & 16) >> 1);
    const int bcol_l = lane & 8;

    const size_t xg0 = (size_t)(b0 + g) * (T * 128);
    const size_t xg1 = (size_t)(b0 + g + 8) * (T * 128);
    const size_t xc0 = (size_t)(b0 + g) * (T * 64);
    const size_t xc1 = (size_t)(b0 + g + 8) * (T * 64);

    const uint32_t aHg = sbase + GSM_HA_HI + (uint32_t)arow_l * 144 + acolb * 2;
    const uint32_t aLg = sbase + GSM_HA_LO + (uint32_t)arow_l * 144 + acolb * 2;
    const uint32_t aHc = sbase + GSM_RA_HI + (uint32_t)arow_l * 144 + acolb * 2;
    const uint32_t aLc = sbase + GSM_RA_LO + (uint32_t)arow_l * 144 + acolb * 2;
    const uint32_t bHg = sbase + GSM_UG_HI + (uint32_t)(wid * 16 + bnrow_l) * 144 + bcol_l * 2;
    const uint32_t bLg = sbase + GSM_UG_LO + (uint32_t)(wid * 16 + bnrow_l) * 144 + bcol_l * 2;
    const uint32_t bHc = sbase + GSM_UC_HI + (uint32_t)(wid * 8 + bnrow_l) * 144 + bcol_l * 2;
    const uint32_t bLc = sbase + GSM_UC_LO + (uint32_t)(wid * 8 + bnrow_l) * 144 + bcol_l * 2;

    float* hf = (float*)(smem + GSM_HF);
    float* zf = (float*)(smem + GSM_ZF);

    for (int t = 0; t < T; t++) {
        // ---------------- gate (16 cols per warp) ----------------
        float xgv[8];
#pragma unroll
        for (int nt = 0; nt < 2; nt++) {
            const int col = wid * 16 + nt * 8 + 2 * q;
            float2 v0 = *(const float2*)(xg + xg0 + (size_t)t * 128 + col);
            float2 v1 = *(const float2*)(xg + xg1 + (size_t)t * 128 + col);
            xgv[4 * nt + 0] = v0.x; xgv[4 * nt + 1] = v0.y;
            xgv[4 * nt + 2] = v1.x; xgv[4 * nt + 3] = v1.y;
        }

        float acc[2][4];
#pragma unroll
        for (int i = 0; i < 2; i++)
#pragma unroll
            for (int e = 0; e < 4; e++) acc[i][e] = 0.0f;

#pragma unroll
        for (int ks = 0; ks < 4; ks++) {
            uint32_t aH[4], aL[4];
            ldsm_x4(aH[0], aH[1], aH[2], aH[3], aHg + ks * 32);
            ldsm_x4(aL[0], aL[1], aL[2], aL[3], aLg + ks * 32);
            uint32_t c0, c1, c2, c3;
            ldsm_x4(c0, c1, c2, c3, bHg + ks * 32);
            mma16816(acc[0], aH, c0, c1);
            mma16816(acc[1], aH, c2, c3);
            mma16816(acc[0], aL, c0, c1);
            mma16816(acc[1], aL, c2, c3);
            ldsm_x4(c0, c1, c2, c3, bLg + ks * 32);
            mma16816(acc[0], aH, c0, c1);
            mma16816(acc[1], aH, c2, c3);
        }

        if (wid < 4) {
            // cols 0..63: rhs = sigmoid(gate) * h  -> split bf16
#pragma unroll
            for (int nt = 0; nt < 2; nt++) {
                const int col = wid * 16 + nt * 8 + 2 * q;
                float s0 = sigmoidf_fast(acc[nt][0] + xgv[4 * nt + 0]);
                float s1 = sigmoidf_fast(acc[nt][1] + xgv[4 * nt + 1]);
                float s2 = sigmoidf_fast(acc[nt][2] + xgv[4 * nt + 2]);
                float s3 = sigmoidf_fast(acc[nt][3] + xgv[4 * nt + 3]);
                float rh0 = s0 * hf[g * 68 + col];
                float rh1 = s1 * hf[g * 68 + col + 1];
                float rh2 = s2 * hf[(g + 8) * 68 + col];
                float rh3 = s3 * hf[(g + 8) * 68 + col + 1];
                split_pair(smem + GSM_RA_HI, smem + GSM_RA_LO, g * 144 + col * 2, rh0, rh1);
                split_pair(smem + GSM_RA_HI, smem + GSM_RA_LO, (g + 8) * 144 + col * 2, rh2, rh3);
            }
        } else {
            // cols 64..127: z
#pragma unroll
            for (int nt = 0; nt < 2; nt++) {
                const int zc = wid * 16 + nt * 8 + 2 * q - 64;
                zf[g * 68 + zc]           = sigmoidf_fast(acc[nt][0] + xgv[4 * nt + 0]);
                zf[g * 68 + zc + 1]       = sigmoidf_fast(acc[nt][1] + xgv[4 * nt + 1]);
                zf[(g + 8) * 68 + zc]     = sigmoidf_fast(acc[nt][2] + xgv[4 * nt + 2]);
                zf[(g + 8) * 68 + zc + 1] = sigmoidf_fast(acc[nt][3] + xgv[4 * nt + 3]);
            }
        }
        __syncthreads();

        // ---------------- candidate (8 cols per warp) ----------------
        const int ccol = wid * 8 + 2 * q;
        float xcv[4];
        {
            float2 v0 = *(const float2*)(xc + xc0 + (size_t)t * 64 + ccol);
            float2 v1 = *(const float2*)(xc + xc1 + (size_t)t * 64 + ccol);
            xcv[0] = v0.x; xcv[1] = v0.y; xcv[2] = v1.x; xcv[3] = v1.y;
        }

        float cac[4];
#pragma unroll
        for (int e = 0; e < 4; e++) cac[e] = 0.0f;

#pragma unroll
        for (int ks = 0; ks < 4; ks++) {
            uint32_t aH[4], aL[4];
            ldsm_x4(aH[0], aH[1], aH[2], aH[3], aHc + ks * 32);
            ldsm_x4(aL[0], aL[1], aL[2], aL[3], aLc + ks * 32);
            uint32_t c0, c1, c2, c3;
            ldsm_x4(c0, c1, c2, c3, bHc + ks * 32);   // only c0,c1 used (n8 tile)
            mma16816(cac, aH, c0, c1);
            mma16816(cac, aL, c0, c1);
            ldsm_x4(c0, c1, c2, c3, bLc + ks * 32);
            mma16816(cac, aH, c0, c1);
        }

        // epilogue: h update (exact select on binary mask)
        {
            float hn[4];
#pragma unroll
            for (int e = 0; e < 4; e++) {
                const int rr = (e < 2) ? g : (g + 8);
                const int cc = ccol + (e & 1);
                float cand = tanh_fast(cac[e] + xcv[e]);
                float z = zf[rr * 68 + cc];
                float h = hf[rr * 68 + cc];
                float v = fmaf(z, h - cand, cand);
                hn[e] = msk[rr * T + t] ? v : h;
                hf[rr * 68 + cc] = hn[e];
            }
            split_pair(smem + GSM_HA_HI, smem + GSM_HA_LO, g * 144 + ccol * 2, hn[0], hn[1]);
            split_pair(smem + GSM_HA_HI, smem + GSM_HA_LO, (g + 8) * 144 + ccol * 2, hn[2], hn[3]);
            if (STORE_ALL) {
                *(float2*)(out + (size_t)(b0 + g) * (T * 64) + (size_t)t * 64 + ccol) =
                    make_float2(hn[0], hn[1]);
                *(float2*)(out + (size_t)(b0 + g + 8) * (T * 64) + (size_t)t * 64 + ccol) =
                    make_float2(hn[2], hn[3]);
            }
        }
        __syncthreads();
    }

    if (!STORE_ALL) {
        for (int idx = tid; idx < GM * 64; idx += 256) {
            int r = idx >> 6, c = idx & 63;
            out[(size_t)(b0 + r) * 64 + c] = hf[r * 68 + c];
        }
    }
}

// ======================================================================
// DIN attention via HMMA, chunked (2 CTAs/SM) — unchanged from R12.
// ======================================================================
#define ACH 112
#define APK  72
#define APK2 88

#define ASM_QS    0
#define ASM_BASE  256
#define ASM_BA2   640
#define ASM_WA3   832
#define ASM_SC    992
#define ASM_RED   1888
#define ASM_KHI   2048
#define ASM_KLO   (ASM_KHI + ACH * APK * 2)
#define ASM_WHI   (ASM_KLO + ACH * APK * 2)
#define ASM_WLO   (ASM_WHI + 80 * APK * 2)
#define ASM_W2HI  (ASM_WLO + 80 * APK * 2)
#define ASM_W2LO  (ASM_W2HI + 48 * APK2 * 2)
#define ASM_D1HI  (ASM_W2LO + 48 * APK2 * 2)
#define ASM_D1LO  (ASM_D1HI + ACH * APK2 * 2)
#define ASM_TOTAL (ASM_D1LO + ACH * APK2 * 2)   // 113664

__global__ void __launch_bounds__(256, 2) attn_mma_kernel(
        const int*   __restrict__ item_i,
        const float* __restrict__ item_emb,
        const float* __restrict__ rnn1,
        const float* __restrict__ mask,
        const float* __restrict__ Wa1, const float* __restrict__ ba1,
        const float* __restrict__ Wa2, const float* __restrict__ ba2,
        const float* __restrict__ Wa3, const float* __restrict__ ba3,
        float* __restrict__ alpha)
{
    extern __shared__ char smem[];
    const uint32_t sbase = smem_u32(smem);
    const int b = blockIdx.x;
    const int tid = threadIdx.x;
    const int wid = tid >> 5, lane = tid & 31;

    float* qs   = (float*)(smem + ASM_QS);
    float* base = (float*)(smem + ASM_BASE);
    float* ba2s = (float*)(smem + ASM_BA2);
    float* wa3s = (float*)(smem + ASM_WA3);
    float* sc   = (float*)(smem + ASM_SC);
    float* red  = (float*)(smem + ASM_RED);

    if (tid < 64) qs[tid] = item_emb[(size_t)item_i[b] * 64 + tid];
    if (tid >= 64 && tid < 112) ba2s[tid - 64] = (tid - 64 < 40) ? ba2[tid - 64] : 0.0f;
    if (tid >= 112 && tid < 152) wa3s[tid - 112] = Wa3[tid - 112];
    for (int i = tid; i < 88; i += 256) {
        int r = 40 + i / 11, s = i % 11;
        *(uint4*)(smem + ASM_W2HI + r * 176 + s * 16) = make_uint4(0, 0, 0, 0);
        *(uint4*)(smem + ASM_W2LO + r * 176 + s * 16) = make_uint4(0, 0, 0, 0);
    }
    __syncthreads();

    if (tid < 80) {
        float acc = ba1[tid];
#pragma unroll 8
        for (int k = 0; k < 64; k++)
            acc = fmaf(qs[k], Wa1[k * 80 + tid] + Wa1[(128 + k) * 80 + tid], acc);
        base[tid] = acc;
    }
    for (int idx = tid; idx < 5120; idx += 256) {
        int k = idx / 80, c = idx - k * 80;
        float w = Wa1[(64 + k) * 80 + c] - Wa1[(128 + k) * 80 + c]
                + qs[k] * Wa1[(192 + k) * 80 + c];
        __nv_bfloat16 hi = __float2bfloat16(w);
        *(__nv_bfloat16*)(smem + ASM_WHI + c * 144 + k * 2) = hi;
        *(__nv_bfloat16*)(smem + ASM_WLO + c * 144 + k * 2) =
            __float2bfloat16(w - __bfloat162float(hi));
    }
    for (int idx = tid; idx < 3200; idx += 256) {
        int k = idx / 40, n = idx - k * 40;
        float w = Wa2[idx];
        __nv_bfloat16 hi = __float2bfloat16(w);
        *(__nv_bfloat16*)(smem + ASM_W2HI + n * 176 + k * 2) = hi;
        *(__nv_bfloat16*)(smem + ASM_W2LO + n * 176 + k * 2) =
            __float2bfloat16(w - __bfloat162float(hi));
    }

    const int arow_l = lane & 15;
    const int acolb  = (lane >> 4) << 3;
    const int bnrow_l = (lane & 7) + ((lane & 16) >> 1);
    const int bcol_l  = lane & 8;
    const int g = lane >> 2, q = lane & 3;
    const float ba3v = ba3[0];

    for (int cc = 0; cc < 2; cc++) {
        const int t0 = cc * ACH;

        __syncthreads();
        for (int idx = tid; idx < ACH * 16; idx += 256) {
            int r = idx >> 4, c4 = idx & 15;
            int tg = t0 + r; if (tg > T - 1) tg = T - 1;
            float4 v = *(const float4*)(rnn1 + ((size_t)b * T + tg) * 64 + c4 * 4);
            __nv_bfloat16 h[4], l[4];
            h[0] = __float2bfloat16(v.x); l[0] = __float2bfloat16(v.x - __bfloat162float(h[0]));
            h[1] = __float2bfloat16(v.y); l[1] = __float2bfloat16(v.y - __bfloat162float(h[1]));
            h[2] = __float2bfloat16(v.z); l[2] = __float2bfloat16(v.z - __bfloat162float(h[2]));
            h[3] = __float2bfloat16(v.w); l[3] = __float2bfloat16(v.w - __bfloat162float(h[3]));
            int off = r * 144 + c4 * 8;
            *(uint2*)(smem + ASM_KHI + off) = *(uint2*)h;
            *(uint2*)(smem + ASM_KLO + off) = *(uint2*)l;
        }
        __syncthreads();

        for (int mtl = wid; mtl < 7; mtl += 8) {
            float acc[10][4];
#pragma unroll
            for (int nt = 0; nt < 10; nt++) {
                float b0 = base[nt * 8 + 2 * q], b1 = base[nt * 8 + 2 * q + 1];
                acc[nt][0] = b0; acc[nt][1] = b1; acc[nt][2] = b0; acc[nt][3] = b1;
            }
            const uint32_t aHb = sbase + ASM_KHI + (uint32_t)(mtl * 16 + arow_l) * 144 + acolb * 2;
            const uint32_t aLb = sbase + ASM_KLO + (uint32_t)(mtl * 16 + arow_l) * 144 + acolb * 2;
            const uint32_t bHb = sbase + ASM_WHI + (uint32_t)bnrow_l * 144 + bcol_l * 2;
            const uint32_t bLb = sbase + ASM_WLO + (uint32_t)bnrow_l * 144 + bcol_l * 2;
#pragma unroll
            for (int ks = 0; ks < 4; ks++) {
                uint32_t aH[4], aL[4];
                ldsm_x4(aH[0], aH[1], aH[2], aH[3], aHb + ks * 32);
                ldsm_x4(aL[0], aL[1], aL[2], aL[3], aLb + ks * 32);
#pragma unroll
                for (int np = 0; np < 5; np++) {
                    uint32_t c0, c1, c2, c3;
                    ldsm_x4(c0, c1, c2, c3, bHb + (uint32_t)np * 16 * 144 + ks * 32);
                    mma16816(acc[2 * np],     aH, c0, c1);
                    mma16816(acc[2 * np + 1], aH, c2, c3);
                    mma16816(acc[2 * np],     aL, c0, c1);
                    mma16816(acc[2 * np + 1], aL, c2, c3);
                    ldsm_x4(c0, c1, c2, c3, bLb + (uint32_t)np * 16 * 144 + ks * 32);
                    mma16816(acc[2 * np],     aH, c0, c1);
                    mma16816(acc[2 * np + 1], aH, c2, c3);
                }
            }
            const int r0 = mtl * 16 + g, r1 = r0 + 8;
#pragma unroll
            for (int nt = 0; nt < 10; nt++) {
                const int c0 = nt * 8 + 2 * q;
                float s00 = sigmoidf_fast(acc[nt][0]);
                float s01 = sigmoidf_fast(acc[nt][1]);
                float s10 = sigmoidf_fast(acc[nt][2]);
                float s11 = sigmoidf_fast(acc[nt][3]);
                split_pair(smem + ASM_D1HI, smem + ASM_D1LO, r0 * 176 + c0 * 2, s00, s01);
                split_pair(smem + ASM_D1HI, smem + ASM_D1LO, r1 * 176 + c0 * 2, s10, s11);
            }
        }
        __syncthreads();

        for (int mtl = wid; mtl < 7; mtl += 8) {
            float acc[6][4];
#pragma unroll
            for (int nt = 0; nt < 6; nt++) {
                float b0 = ba2s[nt * 8 + 2 * q], b1 = ba2s[nt * 8 + 2 * q + 1];
                acc[nt][0] = b0; acc[nt][1] = b1; acc[nt][2] = b0; acc[nt][3] = b1;
            }
            const uint32_t aHb = sbase + ASM_D1HI + (uint32_t)(mtl * 16 + arow_l) * 176 + acolb * 2;
            const uint32_t aLb = sbase + ASM_D1LO + (uint32_t)(mtl * 16 + arow_l) * 176 + acolb * 2;
            const uint32_t bHb = sbase + ASM_W2HI + (uint32_t)bnrow_l * 176 + bcol_l * 2;
            const uint32_t bLb = sbase + ASM_W2LO + (uint32_t)bnrow_l * 176 + bcol_l * 2;
#pragma unroll
            for (int ks = 0; ks < 5; ks++) {
                uint32_t aH[4], aL[4];
                ldsm_x4(aH[0], aH[1], aH[2], aH[3], aHb + ks * 32);
                ldsm_x4(aL[0], aL[1], aL[2], aL[3], aLb + ks * 32);
#pragma unroll
                for (int np = 0; np < 3; np++) {
                    uint32_t c0, c1, c2, c3;
                    ldsm_x4(c0, c1, c2, c3, bHb + (uint32_t)np * 16 * 176 + ks * 32);
                    mma16816(acc[2 * np],     aH, c0, c1);
                    mma16816(acc[2 * np + 1], aH, c2, c3);
                    mma16816(acc[2 * np],     aL, c0, c1);
                    mma16816(acc[2 * np + 1], aL, c2, c3);
                    ldsm_x4(c0, c1, c2, c3, bLb + (uint32_t)np * 16 * 176 + ks * 32);
                    mma16816(acc[2 * np],     aH, c0, c1);
                    mma16816(acc[2 * np + 1], aH, c2, c3);
                }
            }
            float s0 = 0.0f, s1 = 0.0f;
#pragma unroll
            for (int nt = 0; nt < 5; nt++) {
                const int c0 = nt * 8 + 2 * q;
                float w0 = wa3s[c0], w1 = wa3s[c0 + 1];
                s0 = fmaf(sigmoidf_fast(acc[nt][0]), w0, s0);
                s0 = fmaf(sigmoidf_fast(acc[nt][1]), w1, s0);
                s1 = fmaf(sigmoidf_fast(acc[nt][2]), w0, s1);
                s1 = fmaf(sigmoidf_fast(acc[nt][3]), w1, s1);
            }
            s0 += __shfl_xor_sync(0xffffffffu, s0, 1);
            s0 += __shfl_xor_sync(0xffffffffu, s0, 2);
            s1 += __shfl_xor_sync(0xffffffffu, s1, 1);
            s1 += __shfl_xor_sync(0xffffffffu, s1, 2);
            if (q == 0) {
                int t0g = t0 + mtl * 16 + g, t1g = t0g + 8;
                if (t0g < T) {
                    float m = mask[(size_t)b * T + t0g];
                    sc[t0g] = (m > 0.0f) ? (s0 + ba3v) : -1e9f;
                }
                if (t1g < T) {
                    float m = mask[(size_t)b * T + t1g];
                    sc[t1g] = (m > 0.0f) ? (s1 + ba3v) : -1e9f;
                }
            }
        }
    }
    __syncthreads();

    float v = (tid < T) ? sc[tid] : -FLT_MAX;
#pragma unroll
    for (int o = 16; o > 0; o >>= 1) v = fmaxf(v, __shfl_xor_sync(0xffffffffu, v, o));
    if (lane == 0) red[wid] = v;
    __syncthreads();
    if (tid == 0) {
        float mx = red[0];
#pragma unroll
        for (int w = 1; w < 8; w++) mx = fmaxf(mx, red[w]);
        red[12] = mx;
    }
    __syncthreads();
    float mx = red[12];

    float e = (tid < T) ? __expf(sc[tid] - mx) : 0.0f;
    float s = e;
#pragma unroll
    for (int o = 16; o > 0; o >>= 1) s += __shfl_xor_sync(0xffffffffu, s, o);
    __syncthreads();
    if (lane == 0) red[wid] = s;
    __syncthreads();
    if (tid == 0) {
        float sum = 0.0f;
#pragma unroll
        for (int w = 0; w < 8; w++) sum += red[w];
        red[13] = 1.0f / sum;
    }
    __syncthreads();
    if (tid < T) alpha[(size_t)b * T + tid] = e * red[13];
}

// ======================================================================
// FCN head + hist_sum (unchanged).
// ======================================================================
__global__ void fcn_kernel(const int* __restrict__ u, const int* __restrict__ ii,
                           const int* __restrict__ hist_i,
                           const float* __restrict__ item_emb,
                           const float* __restrict__ user_emb,
                           const float* __restrict__ final2,
                           const float* __restrict__ W1, const float* __restrict__ b1,
                           const float* __restrict__ p1,
                           const float* __restrict__ W2, const float* __restrict__ b2,
                           const float* __restrict__ p2,
                           const float* __restrict__ W3, const float* __restrict__ b3,
                           float* __restrict__ out)
{
    __shared__ float xs[320];
    __shared__ float h1s[128];
    __shared__ float h2s[40];

    const int b = blockIdx.x;
    const int tid = threadIdx.x;

    if (tid < 64) {
        const int* hi = hist_i + (size_t)b * T;
        float s0 = 0.f, s1 = 0.f, s2 = 0.f, s3 = 0.f;
        for (int t = 0; t < T; t += 4) {
            s0 += item_emb[(size_t)hi[t]     * 64 + tid];
            s1 += item_emb[(size_t)hi[t + 1] * 64 + tid];
            s2 += item_emb[(size_t)hi[t + 2] * 64 + tid];
            s3 += item_emb[(size_t)hi[t + 3] * 64 + tid];
        }
        xs[128 + tid] = (s0 + s1) + (s2 + s3);
    } else {
        int j = tid - 64;
        xs[j]       = user_emb[(size_t)u[b]  * 64 + j];
        xs[64 + j]  = item_emb[(size_t)ii[b] * 64 + j];
        xs[256 + j] = final2[(size_t)b * 64 + j];
    }
    __syncthreads();
    if (tid < 64) xs[192 + tid] = xs[64 + tid] * xs[128 + tid];
    __syncthreads();

    {
        float a0 = b1[tid], a1 = 0.0f;
#pragma unroll 8
        for (int k = 0; k < 320; k += 2) {
            a0 = fmaf(xs[k],     W1[k * 128 + tid],       a0);
            a1 = fmaf(xs[k + 1], W1[(k + 1) * 128 + tid], a1);
        }
        float h = a0 + a1;
        h1s[tid] = (h >= 0.0f) ? h : p1[tid] * h;
    }
    __syncthreads();

    if (tid < 40) {
        float a0 = b2[tid], a1 = 0.0f;
#pragma unroll 16
        for (int k = 0; k < 128; k += 2) {
            a0 = fmaf(h1s[k],     W2[k * 40 + tid],       a0);
            a1 = fmaf(h1s[k + 1], W2[(k + 1) * 40 + tid], a1);
        }
        float h = a0 + a1;
        h2s[tid] = (h >= 0.0f) ? h : p2[tid] * h;
    }
    __syncthreads();

    if (tid == 0) {
        float acc = b3[0];
#pragma unroll
        for (int k = 0; k < 40; k++) acc = fmaf(h2s[k], W3[k], acc);
        out[b] = acc;
    }
}

// ======================================================================
extern "C" void kernel_launch(void* const* d_in, const int* in_sizes, int n_in,
                              void* d_out, int out_size)
{
    const int*   u        = (const int*)d_in[0];
    const int*   ii       = (const int*)d_in[1];
    const int*   hist_i   = (const int*)d_in[2];
    const float* mask     = (const float*)d_in[3];
    const float* item_emb = (const float*)d_in[4];
    const float* user_emb = (const float*)d_in[5];
    const float* g1_Wg = (const float*)d_in[6];
    const float* g1_Ug = (const float*)d_in[7];
    const float* g1_bg = (const float*)d_in[8];
    const float* g1_Wc = (const float*)d_in[9];
    const float* g1_Uc = (const float*)d_in[10];
    const float* g1_bc = (const float*)d_in[11];
    const float* Wa1 = (const float*)d_in[12];
    const float* ba1 = (const float*)d_in[13];
    const float* Wa2 = (const float*)d_in[14];
    const float* ba2 = (const float*)d_in[15];
    const float* Wa3 = (const float*)d_in[16];
    const float* ba3 = (const float*)d_in[17];
    const float* g2_Wg = (const float*)d_in[18];
    const float* g2_Ug = (const float*)d_in[19];
    const float* g2_bg = (const float*)d_in[20];
    const float* g2_Wc = (const float*)d_in[21];
    const float* g2_Uc = (const float*)d_in[22];
    const float* g2_bc = (const float*)d_in[23];
    const float* W1 = (const float*)d_in[24];
    const float* b1 = (const float*)d_in[25];
    const float* p1 = (const float*)d_in[26];
    const float* W2 = (const float*)d_in[27];
    const float* b2 = (const float*)d_in[28];
    const float* p2 = (const float*)d_in[29];
    const float* W3 = (const float*)d_in[30];
    const float* b3 = (const float*)d_in[31];
    float* out = (float*)d_out;

    float *xg, *xc, *rnn1, *alpha, *final2;
    __nv_bfloat16 *bh1, *bl1, *bh2, *bl2;
    cudaGetSymbolAddress((void**)&xg,     g_xg);
    cudaGetSymbolAddress((void**)&xc,     g_xc);
    cudaGetSymbolAddress((void**)&rnn1,   g_rnn1);
    cudaGetSymbolAddress((void**)&alpha,  g_alpha);
    cudaGetSymbolAddress((void**)&final2, g_final2);
    cudaGetSymbolAddress((void**)&bh1, g_bh1);
    cudaGetSymbolAddress((void**)&bl1, g_bl1);
    cudaGetSymbolAddress((void**)&bh2, g_bh2);
    cudaGetSymbolAddress((void**)&bl2, g_bl2);

    cudaFuncSetAttribute(proj_mma_kernel<0>, cudaFuncAttributeMaxDynamicSharedMemorySize, PSM_TOTAL);
    cudaFuncSetAttribute(proj_mma_kernel<1>, cudaFuncAttributeMaxDynamicSharedMemorySize, PSM_TOTAL);
    cudaFuncSetAttribute(gru_tc_kernel<true>,  cudaFuncAttributeMaxDynamicSharedMemorySize, GSM_TOTAL);
    cudaFuncSetAttribute(gru_tc_kernel<false>, cudaFuncAttributeMaxDynamicSharedMemorySize, GSM_TOTAL);
    cudaFuncSetAttribute(attn_mma_kernel, cudaFuncAttributeMaxDynamicSharedMemorySize, ASM_TOTAL);

    // 0) split projection weights to bf16 hi/lo (both GRUs)
    wsplit_kernel<<<48, 256>>>(g1_Wg, g1_Wc, bh1, bl1);
    wsplit_kernel<<<48, 256>>>(g2_Wg, g2_Wc, bh2, bl2);
    // 1) GRU1 input projections via HMMA
    proj_mma_kernel<0><<<BT / 128, 256, PSM_TOTAL>>>(item_emb, hist_i, nullptr,
                                                     bh1, bl1, g1_bg, g1_bc, xg, xc);
    // 2) GRU1 recurrence via HMMA (grid 256, 3 CTAs/SM) -> rnn1
    gru_tc_kernel<true><<<B / GM, 256, GSM_TOTAL>>>(xg, xc, mask, g1_Ug, g1_Uc, rnn1);
    // 3) DIN attention via HMMA (chunked, 2 CTAs/SM) -> alpha
    attn_mma_kernel<<<B, 256, ASM_TOTAL>>>(ii, item_emb, rnn1, mask,
                                           Wa1, ba1, Wa2, ba2, Wa3, ba3, alpha);
    // 4) GRU2 input projections via HMMA (rnn1 * alpha)
    proj_mma_kernel<1><<<BT / 128, 256, PSM_TOTAL>>>(rnn1, nullptr, alpha,
                                                     bh2, bl2, g2_bg, g2_bc, xg, xc);
    // 5) GRU2 recurrence via HMMA -> final2 only
    gru_tc_kernel<false><<<B / GM, 256, GSM_TOTAL>>>(xg, xc, mask, g2_Ug, g2_Uc, final2);
    // 6) FCN head -> logits
    fcn_kernel<<<B, 128>>>(u, ii, hist_i, item_emb, user_emb, final2,
                           W1, b1, p1, W2, b2, p2, W3, b3, out);
}

// round 17
// speedup vs baseline: 1.9314x; 1.0237x over previous
#include <cuda_runtime.h>
#include <cuda_bf16.h>
#include <math.h>
#include <float.h>
#include <cstdint>

#define B 4096
#define T 200
#define BT (B*T)
#define GM 16   // batch rows per GRU-TC block (grid = 256)

// ---------------- scratch (device globals: no allocs allowed) ----------------
__device__ float g_xg[(size_t)BT * 128];
__device__ float g_xc[(size_t)BT * 64];
__device__ float g_rnn1[(size_t)BT * 64];
__device__ float g_alpha[BT];
__device__ float g_final2[B * 64];
// split-bf16 weights for the two projection GEMMs: layout [n(192)][k(64)]
__device__ __nv_bfloat16 g_bh1[192 * 64];
__device__ __nv_bfloat16 g_bl1[192 * 64];
__device__ __nv_bfloat16 g_bh2[192 * 64];
__device__ __nv_bfloat16 g_bl2[192 * 64];

__device__ __forceinline__ float sigmoidf_fast(float x) {
    return 1.0f / (1.0f + __expf(-x));
}
__device__ __forceinline__ float tanh_fast(float x) {
    float ax = fabsf(x);
    float e = __expf(-2.0f * ax);
    float th = __fdividef(1.0f - e, 1.0f + e);
    return copysignf(th, x);
}

__device__ __forceinline__ uint32_t smem_u32(const void* p) {
    uint32_t a;
    asm("{ .reg .u64 t; cvta.to.shared.u64 t, %1; cvt.u32.u64 %0, t; }" : "=r"(a) : "l"(p));
    return a;
}
__device__ __forceinline__ void ldsm_x4(uint32_t& r0, uint32_t& r1, uint32_t& r2, uint32_t& r3,
                                        uint32_t addr) {
    asm volatile("ldmatrix.sync.aligned.m8n8.x4.shared.b16 {%0,%1,%2,%3}, [%4];"
                 : "=r"(r0), "=r"(r1), "=r"(r2), "=r"(r3) : "r"(addr));
}
__device__ __forceinline__ void ldsm_x2(uint32_t& r0, uint32_t& r1, uint32_t addr) {
    asm volatile("ldmatrix.sync.aligned.m8n8.x2.shared.b16 {%0,%1}, [%2];"
                 : "=r"(r0), "=r"(r1) : "r"(addr));
}
__device__ __forceinline__ void mma16816(float* c, const uint32_t* a, uint32_t b0, uint32_t b1) {
    asm volatile("mma.sync.aligned.m16n8k16.row.col.f32.bf16.bf16.f32 "
                 "{%0,%1,%2,%3}, {%4,%5,%6,%7}, {%8,%9}, {%0,%1,%2,%3};"
                 : "+f"(c[0]), "+f"(c[1]), "+f"(c[2]), "+f"(c[3])
                 : "r"(a[0]), "r"(a[1]), "r"(a[2]), "r"(a[3]), "r"(b0), "r"(b1));
}
__device__ __forceinline__ void store_bf16_pair(char* basep, int byteoff, float v0, float v1,
                                                char* basel, float l0, float l1) {
    __nv_bfloat162 h, l;
    h.x = __float2bfloat16(v0); h.y = __float2bfloat16(v1);
    l.x = __float2bfloat16(l0); l.y = __float2bfloat16(l1);
    *(__nv_bfloat162*)(basep + byteoff) = h;
    *(__nv_bfloat162*)(basel + byteoff) = l;
}
// split fp32 -> hi/lo bf16 pair store at byte offset (pair of adjacent cols)
__device__ __forceinline__ void split_pair(char* hi_base, char* lo_base, int byteoff,
                                           float v0, float v1) {
    __nv_bfloat16 h0 = __float2bfloat16(v0), h1 = __float2bfloat16(v1);
    store_bf16_pair(hi_base, byteoff, v0, v1, lo_base,
                    v0 - __bfloat162float(h0), v1 - __bfloat162float(h1));
}

// ======================================================================
// Weight split prep: W[64,128]|[64,64] fp32 -> Bhi/Blo [n=192][k=64] bf16
// ======================================================================
__global__ void wsplit_kernel(const float* __restrict__ Wg, const float* __restrict__ Wc,
                              __nv_bfloat16* __restrict__ Bhi, __nv_bfloat16* __restrict__ Blo)
{
    int idx = blockIdx.x * 256 + threadIdx.x;
    if (idx >= 192 * 64) return;
    int n = idx >> 6, k = idx & 63;
    float w = (n < 128) ? Wg[k * 128 + n] : Wc[k * 64 + (n - 128)];
    __nv_bfloat16 hi = __float2bfloat16(w);
    __nv_bfloat16 lo = __float2bfloat16(w - __bfloat162float(hi));
    Bhi[idx] = hi;
    Blo[idx] = lo;
}

// ======================================================================
// HMMA projection (unchanged, passing).
// ======================================================================
#define PAD_K 72
#define PSM_BIAS 0
#define PSM_AHI  768
#define PSM_ALO  (PSM_AHI + 128 * PAD_K * 2)
#define PSM_BHI  (PSM_ALO + 128 * PAD_K * 2)
#define PSM_BLO  (PSM_BHI + 192 * PAD_K * 2)
#define PSM_TOTAL (PSM_BLO + 192 * PAD_K * 2)   // 92928 bytes

template<int MODE>
__global__ void __launch_bounds__(256, 2) proj_mma_kernel(
        const float* __restrict__ src,
        const int*   __restrict__ hist_i,
        const float* __restrict__ alpha,
        const __nv_bfloat16* __restrict__ Bhi,
        const __nv_bfloat16* __restrict__ Blo,
        const float* __restrict__ bg,
        const float* __restrict__ bc,
        float* __restrict__ xg,
        float* __restrict__ xc)
{
    extern __shared__ char smem[];
    const uint32_t sbase = smem_u32(smem);
    const int tid = threadIdx.x;
    const int wid = tid >> 5;
    const int lane = tid & 31;
    const int m0 = blockIdx.x * 128;

    float* bs = (float*)(smem + PSM_BIAS);
    if (tid < 192) bs[tid] = (tid < 128) ? bg[tid] : bc[tid - 128];

    {
        const uint4* sh = (const uint4*)Bhi;
        const uint4* sl = (const uint4*)Blo;
#pragma unroll
        for (int i = 0; i < 6; i++) {
            int idx = tid + 256 * i;
            int n = idx >> 3, seg = idx & 7;
            int off = n * (PAD_K * 2) + seg * 16;
            *(uint4*)(smem + PSM_BHI + off) = sh[idx];
            *(uint4*)(smem + PSM_BLO + off) = sl[idx];
        }
    }

    {
        const int r = tid >> 1;
        const int half = tid & 1;
        const float* srow;
        float scale = 1.0f;
        if (MODE == 0) {
            srow = src + (size_t)hist_i[m0 + r] * 64;
        } else {
            srow = src + (size_t)(m0 + r) * 64;
            scale = alpha[m0 + r];
        }
        srow += half * 32;
        const int kb = half * 32;
#pragma unroll
        for (int c = 0; c < 4; c++) {
            float4 v0 = *(const float4*)(srow + 8 * c);
            float4 v1 = *(const float4*)(srow + 8 * c + 4);
            float vv[8] = {v0.x, v0.y, v0.z, v0.w, v1.x, v1.y, v1.z, v1.w};
            __nv_bfloat16 hb[8], lb[8];
#pragma unroll
            for (int e = 0; e < 8; e++) {
                float f = vv[e] * scale;
                hb[e] = __float2bfloat16(f);
                lb[e] = __float2bfloat16(f - __bfloat162float(hb[e]));
            }
            int off = r * (PAD_K * 2) + (kb + 8 * c) * 2;
            *(uint4*)(smem + PSM_AHI + off) = *(uint4*)hb;
            *(uint4*)(smem + PSM_ALO + off) = *(uint4*)lb;
        }
    }
    __syncthreads();

    const int arow = wid * 16 + (lane & 15);
    const int acolb = ((lane >> 4) << 3);
    const uint32_t a_off = (uint32_t)arow * (PAD_K * 2) + acolb * 2;
    const uint32_t aH_base = sbase + PSM_AHI + a_off;
    const uint32_t aL_base = sbase + PSM_ALO + a_off;

    const int bnrow_l = (lane & 7) + ((lane & 16) >> 1);
    const int bcol_l = (lane & 8);
    const uint32_t b_off_l = (uint32_t)bnrow_l * (PAD_K * 2) + bcol_l * 2;

    const int g = lane >> 2;
    const int tq = lane & 3;

#pragma unroll
    for (int nh = 0; nh < 2; nh++) {
        const uint32_t bH_base = sbase + PSM_BHI + b_off_l + (uint32_t)nh * 96 * (PAD_K * 2);
        const uint32_t bL_base = sbase + PSM_BLO + b_off_l + (uint32_t)nh * 96 * (PAD_K * 2);

        float acc[12][4];
#pragma unroll
        for (int i = 0; i < 12; i++)
#pragma unroll
            for (int qq = 0; qq < 4; qq++) acc[i][qq] = 0.0f;

#pragma unroll
        for (int ks = 0; ks < 4; ks++) {
            uint32_t aH[4], aL[4];
            ldsm_x4(aH[0], aH[1], aH[2], aH[3], aH_base + ks * 32);
            ldsm_x4(aL[0], aL[1], aL[2], aL[3], aL_base + ks * 32);
#pragma unroll
            for (int np = 0; np < 6; np++) {
                uint32_t bh0, bh1, bh2, bh3;
                ldsm_x4(bh0, bh1, bh2, bh3,
                        bH_base + (uint32_t)np * 16 * (PAD_K * 2) + ks * 32);
                mma16816(acc[2 * np],     aH, bh0, bh1);
                mma16816(acc[2 * np + 1], aH, bh2, bh3);
                mma16816(acc[2 * np],     aL, bh0, bh1);
                mma16816(acc[2 * np + 1], aL, bh2, bh3);
                uint32_t bl0, bl1, bl2, bl3;
                ldsm_x4(bl0, bl1, bl2, bl3,
                        bL_base + (uint32_t)np * 16 * (PAD_K * 2) + ks * 32);
                mma16816(acc[2 * np],     aH, bl0, bl1);
                mma16816(acc[2 * np + 1], aH, bl2, bl3);
            }
        }

        const int r0 = m0 + wid * 16 + g;
        const int r1 = r0 + 8;
#pragma unroll
        for (int nt = 0; nt < 12; nt++) {
            const int n = nh * 96 + nt * 8 + 2 * tq;
            const float bx = bs[n], by = bs[n + 1];
            float2 o0 = make_float2(acc[nt][0] + bx, acc[nt][1] + by);
            float2 o1 = make_float2(acc[nt][2] + bx, acc[nt][3] + by);
            if (n < 128) {
                *(float2*)(xg + (size_t)r0 * 128 + n) = o0;
                *(float2*)(xg + (size_t)r1 * 128 + n) = o1;
            } else {
                *(float2*)(xc + (size_t)r0 * 64 + (n - 128)) = o0;
                *(float2*)(xc + (size_t)r1 * 64 + (n - 128)) = o1;
            }
        }
    }
}

// ======================================================================
// GRU recurrence via HMMA v4: 16 rows/CTA, grid 256, weight B-fragments
// HOISTED INTO REGISTERS (loop-invariant across all 200 steps).
// Per-step smem loads: only A fragments (h / rhs). 2 barriers/step.
// ======================================================================
#define GSM_UG_HI 0
#define GSM_UG_LO (GSM_UG_HI + 128 * 144)
#define GSM_UC_HI (GSM_UG_LO + 128 * 144)
#define GSM_UC_LO (GSM_UC_HI + 64 * 144)
#define GSM_HA_HI (GSM_UC_LO + 64 * 144)
#define GSM_HA_LO (GSM_HA_HI + GM * 144)
#define GSM_RA_HI (GSM_HA_LO + GM * 144)
#define GSM_RA_LO (GSM_RA_HI + GM * 144)
#define GSM_HF    (GSM_RA_LO + GM * 144)         // fp32 [16][68]
#define GSM_ZF    (GSM_HF + GM * 68 * 4)         // fp32 [16][68]
#define GSM_MSK   (GSM_ZF + GM * 68 * 4)         // uint8 [16][200]
#define GSM_TOTAL (GSM_MSK + GM * T)             // 76416 bytes

template<bool STORE_ALL>
__global__ void __launch_bounds__(256, 2) gru_tc_kernel(
        const float* __restrict__ xg,
        const float* __restrict__ xc,
        const float* __restrict__ mask,
        const float* __restrict__ Ug,   // [64,128]
        const float* __restrict__ Uc,   // [64,64]
        float* __restrict__ out)        // [B,T,64] or [B,64]
{
    extern __shared__ char smem[];
    const uint32_t sbase = smem_u32(smem);
    const int tid = threadIdx.x;
    const int wid = tid >> 5, lane = tid & 31;
    const int b0 = blockIdx.x * GM;

    // ---- stage UgT/UcT split-bf16 (scalar 2-byte stores) ----
    for (int idx = tid; idx < 128 * 64; idx += 256) {
        int k = idx >> 7, n = idx & 127;
        float w = Ug[k * 128 + n];
        __nv_bfloat16 hi = __float2bfloat16(w);
        *(__nv_bfloat16*)(smem + GSM_UG_HI + n * 144 + k * 2) = hi;
        *(__nv_bfloat16*)(smem + GSM_UG_LO + n * 144 + k * 2) =
            __float2bfloat16(w - __bfloat162float(hi));
    }
    for (int idx = tid; idx < 64 * 64; idx += 256) {
        int k = idx >> 6, n = idx & 63;
        float w = Uc[k * 64 + n];
        __nv_bfloat16 hi = __float2bfloat16(w);
        *(__nv_bfloat16*)(smem + GSM_UC_HI + n * 144 + k * 2) = hi;
        *(__nv_bfloat16*)(smem + GSM_UC_LO + n * 144 + k * 2) =
            __float2bfloat16(w - __bfloat162float(hi));
    }
    // zero hA (both planes) and h fp32
    for (int idx = tid; idx < (2 * GM * 144) / 16; idx += 256)
        ((uint4*)(smem + GSM_HA_HI))[idx] = make_uint4(0, 0, 0, 0);
    for (int idx = tid; idx < GM * 68; idx += 256)
        ((float*)(smem + GSM_HF))[idx] = 0.0f;
    // mask -> smem (binary -> uint8)
    unsigned char* msk = (unsigned char*)(smem + GSM_MSK);
    for (int idx = tid; idx < GM * T; idx += 256) {
        int r = idx / T, t = idx - r * T;
        msk[idx] = (mask[(size_t)(b0 + r) * T + t] > 0.0f) ? 1 : 0;
    }
    __syncthreads();

    const int g = lane >> 2, q = lane & 3;
    const int arow_l = lane & 15;
    const int acolb = (lane >> 4) << 3;
    const int bnrow_l = (lane & 7) + ((lane & 16) >> 1);
    const int bcol_l = lane & 8;

    const size_t xg0 = (size_t)(b0 + g) * (T * 128);
    const size_t xg1 = (size_t)(b0 + g + 8) * (T * 128);
    const size_t xc0 = (size_t)(b0 + g) * (T * 64);
    const size_t xc1 = (size_t)(b0 + g + 8) * (T * 64);

    const uint32_t aHg = sbase + GSM_HA_HI + (uint32_t)arow_l * 144 + acolb * 2;
    const uint32_t aLg = sbase + GSM_HA_LO + (uint32_t)arow_l * 144 + acolb * 2;
    const uint32_t aHc = sbase + GSM_RA_HI + (uint32_t)arow_l * 144 + acolb * 2;
    const uint32_t aLc = sbase + GSM_RA_LO + (uint32_t)arow_l * 144 + acolb * 2;
    const uint32_t bHg = sbase + GSM_UG_HI + (uint32_t)(wid * 16 + bnrow_l) * 144 + bcol_l * 2;
    const uint32_t bLg = sbase + GSM_UG_LO + (uint32_t)(wid * 16 + bnrow_l) * 144 + bcol_l * 2;
    const uint32_t bHc = sbase + GSM_UC_HI + (uint32_t)(wid * 8 + bnrow_l) * 144 + bcol_l * 2;
    const uint32_t bLc = sbase + GSM_UC_LO + (uint32_t)(wid * 8 + bnrow_l) * 144 + bcol_l * 2;

    // ---- hoist weight B-fragments into registers (loop-invariant) ----
    uint32_t gbh[4][4], gbl[4][4];   // gate Ug hi/lo
    uint32_t cbh[4][2], cbl[4][2];   // cand Uc hi/lo (n8 tile)
#pragma unroll
    for (int ks = 0; ks < 4; ks++) {
        ldsm_x4(gbh[ks][0], gbh[ks][1], gbh[ks][2], gbh[ks][3], bHg + ks * 32);
        ldsm_x4(gbl[ks][0], gbl[ks][1], gbl[ks][2], gbl[ks][3], bLg + ks * 32);
        ldsm_x2(cbh[ks][0], cbh[ks][1], bHc + ks * 32);
        ldsm_x2(cbl[ks][0], cbl[ks][1], bLc + ks * 32);
    }

    float* hf = (float*)(smem + GSM_HF);
    float* zf = (float*)(smem + GSM_ZF);

    for (int t = 0; t < T; t++) {
        // ---------------- gate (16 cols per warp) ----------------
        float xgv[8];
#pragma unroll
        for (int nt = 0; nt < 2; nt++) {
            const int col = wid * 16 + nt * 8 + 2 * q;
            float2 v0 = *(const float2*)(xg + xg0 + (size_t)t * 128 + col);
            float2 v1 = *(const float2*)(xg + xg1 + (size_t)t * 128 + col);
            xgv[4 * nt + 0] = v0.x; xgv[4 * nt + 1] = v0.y;
            xgv[4 * nt + 2] = v1.x; xgv[4 * nt + 3] = v1.y;
        }

        float acc[2][4];
#pragma unroll
        for (int i = 0; i < 2; i++)
#pragma unroll
            for (int e = 0; e < 4; e++) acc[i][e] = 0.0f;

#pragma unroll
        for (int ks = 0; ks < 4; ks++) {
            uint32_t aH[4], aL[4];
            ldsm_x4(aH[0], aH[1], aH[2], aH[3], aHg + ks * 32);
            ldsm_x4(aL[0], aL[1], aL[2], aL[3], aLg + ks * 32);
            mma16816(acc[0], aH, gbh[ks][0], gbh[ks][1]);
            mma16816(acc[1], aH, gbh[ks][2], gbh[ks][3]);
            mma16816(acc[0], aL, gbh[ks][0], gbh[ks][1]);
            mma16816(acc[1], aL, gbh[ks][2], gbh[ks][3]);
            mma16816(acc[0], aH, gbl[ks][0], gbl[ks][1]);
            mma16816(acc[1], aH, gbl[ks][2], gbl[ks][3]);
        }

        if (wid < 4) {
            // cols 0..63: rhs = sigmoid(gate) * h  -> split bf16
#pragma unroll
            for (int nt = 0; nt < 2; nt++) {
                const int col = wid * 16 + nt * 8 + 2 * q;
                float s0 = sigmoidf_fast(acc[nt][0] + xgv[4 * nt + 0]);
                float s1 = sigmoidf_fast(acc[nt][1] + xgv[4 * nt + 1]);
                float s2 = sigmoidf_fast(acc[nt][2] + xgv[4 * nt + 2]);
                float s3 = sigmoidf_fast(acc[nt][3] + xgv[4 * nt + 3]);
                float rh0 = s0 * hf[g * 68 + col];
                float rh1 = s1 * hf[g * 68 + col + 1];
                float rh2 = s2 * hf[(g + 8) * 68 + col];
                float rh3 = s3 * hf[(g + 8) * 68 + col + 1];
                split_pair(smem + GSM_RA_HI, smem + GSM_RA_LO, g * 144 + col * 2, rh0, rh1);
                split_pair(smem + GSM_RA_HI, smem + GSM_RA_LO, (g + 8) * 144 + col * 2, rh2, rh3);
            }
        } else {
            // cols 64..127: z
#pragma unroll
            for (int nt = 0; nt < 2; nt++) {
                const int zc = wid * 16 + nt * 8 + 2 * q - 64;
                zf[g * 68 + zc]           = sigmoidf_fast(acc[nt][0] + xgv[4 * nt + 0]);
                zf[g * 68 + zc + 1]       = sigmoidf_fast(acc[nt][1] + xgv[4 * nt + 1]);
                zf[(g + 8) * 68 + zc]     = sigmoidf_fast(acc[nt][2] + xgv[4 * nt + 2]);
                zf[(g + 8) * 68 + zc + 1] = sigmoidf_fast(acc[nt][3] + xgv[4 * nt + 3]);
            }
        }
        __syncthreads();

        // ---------------- candidate (8 cols per warp) ----------------
        const int ccol = wid * 8 + 2 * q;
        float xcv[4];
        {
            float2 v0 = *(const float2*)(xc + xc0 + (size_t)t * 64 + ccol);
            float2 v1 = *(const float2*)(xc + xc1 + (size_t)t * 64 + ccol);
            xcv[0] = v0.x; xcv[1] = v0.y; xcv[2] = v1.x; xcv[3] = v1.y;
        }

        float cac[4];
#pragma unroll
        for (int e = 0; e < 4; e++) cac[e] = 0.0f;

#pragma unroll
        for (int ks = 0; ks < 4; ks++) {
            uint32_t aH[4], aL[4];
            ldsm_x4(aH[0], aH[1], aH[2], aH[3], aHc + ks * 32);
            ldsm_x4(aL[0], aL[1], aL[2], aL[3], aLc + ks * 32);
            mma16816(cac, aH, cbh[ks][0], cbh[ks][1]);
            mma16816(cac, aL, cbh[ks][0], cbh[ks][1]);
            mma16816(cac, aH, cbl[ks][0], cbl[ks][1]);
        }

        // epilogue: h update (exact select on binary mask)
        {
            float hn[4];
#pragma unroll
            for (int e = 0; e < 4; e++) {
                const int rr = (e < 2) ? g : (g + 8);
                const int cc = ccol + (e & 1);
                float cand = tanh_fast(cac[e] + xcv[e]);
                float z = zf[rr * 68 + cc];
                float h = hf[rr * 68 + cc];
                float v = fmaf(z, h - cand, cand);
                hn[e] = msk[rr * T + t] ? v : h;
                hf[rr * 68 + cc] = hn[e];
            }
            split_pair(smem + GSM_HA_HI, smem + GSM_HA_LO, g * 144 + ccol * 2, hn[0], hn[1]);
            split_pair(smem + GSM_HA_HI, smem + GSM_HA_LO, (g + 8) * 144 + ccol * 2, hn[2], hn[3]);
            if (STORE_ALL) {
                *(float2*)(out + (size_t)(b0 + g) * (T * 64) + (size_t)t * 64 + ccol) =
                    make_float2(hn[0], hn[1]);
                *(float2*)(out + (size_t)(b0 + g + 8) * (T * 64) + (size_t)t * 64 + ccol) =
                    make_float2(hn[2], hn[3]);
            }
        }
        __syncthreads();
    }

    if (!STORE_ALL) {
        for (int idx = tid; idx < GM * 64; idx += 256) {
            int r = idx >> 6, c = idx & 63;
            out[(size_t)(b0 + r) * 64 + c] = hf[r * 68 + c];
        }
    }
}

// ======================================================================
// DIN attention via HMMA, chunked (2 CTAs/SM) — unchanged from R12.
// ======================================================================
#define ACH 112
#define APK  72
#define APK2 88

#define ASM_QS    0
#define ASM_BASE  256
#define ASM_BA2   640
#define ASM_WA3   832
#define ASM_SC    992
#define ASM_RED   1888
#define ASM_KHI   2048
#define ASM_KLO   (ASM_KHI + ACH * APK * 2)
#define ASM_WHI   (ASM_KLO + ACH * APK * 2)
#define ASM_WLO   (ASM_WHI + 80 * APK * 2)
#define ASM_W2HI  (ASM_WLO + 80 * APK * 2)
#define ASM_W2LO  (ASM_W2HI + 48 * APK2 * 2)
#define ASM_D1HI  (ASM_W2LO + 48 * APK2 * 2)
#define ASM_D1LO  (ASM_D1HI + ACH * APK2 * 2)
#define ASM_TOTAL (ASM_D1LO + ACH * APK2 * 2)   // 113664

__global__ void __launch_bounds__(256, 2) attn_mma_kernel(
        const int*   __restrict__ item_i,
        const float* __restrict__ item_emb,
        const float* __restrict__ rnn1,
        const float* __restrict__ mask,
        const float* __restrict__ Wa1, const float* __restrict__ ba1,
        const float* __restrict__ Wa2, const float* __restrict__ ba2,
        const float* __restrict__ Wa3, const float* __restrict__ ba3,
        float* __restrict__ alpha)
{
    extern __shared__ char smem[];
    const uint32_t sbase = smem_u32(smem);
    const int b = blockIdx.x;
    const int tid = threadIdx.x;
    const int wid = tid >> 5, lane = tid & 31;

    float* qs   = (float*)(smem + ASM_QS);
    float* base = (float*)(smem + ASM_BASE);
    float* ba2s = (float*)(smem + ASM_BA2);
    float* wa3s = (float*)(smem + ASM_WA3);
    float* sc   = (float*)(smem + ASM_SC);
    float* red  = (float*)(smem + ASM_RED);

    if (tid < 64) qs[tid] = item_emb[(size_t)item_i[b] * 64 + tid];
    if (tid >= 64 && tid < 112) ba2s[tid - 64] = (tid - 64 < 40) ? ba2[tid - 64] : 0.0f;
    if (tid >= 112 && tid < 152) wa3s[tid - 112] = Wa3[tid - 112];
    for (int i = tid; i < 88; i += 256) {
        int r = 40 + i / 11, s = i % 11;
        *(uint4*)(smem + ASM_W2HI + r * 176 + s * 16) = make_uint4(0, 0, 0, 0);
        *(uint4*)(smem + ASM_W2LO + r * 176 + s * 16) = make_uint4(0, 0, 0, 0);
    }
    __syncthreads();

    if (tid < 80) {
        float acc = ba1[tid];
#pragma unroll 8
        for (int k = 0; k < 64; k++)
            acc = fmaf(qs[k], Wa1[k * 80 + tid] + Wa1[(128 + k) * 80 + tid], acc);
        base[tid] = acc;
    }
    for (int idx = tid; idx < 5120; idx += 256) {
        int k = idx / 80, c = idx - k * 80;
        float w = Wa1[(64 + k) * 80 + c] - Wa1[(128 + k) * 80 + c]
                + qs[k] * Wa1[(192 + k) * 80 + c];
        __nv_bfloat16 hi = __float2bfloat16(w);
        *(__nv_bfloat16*)(smem + ASM_WHI + c * 144 + k * 2) = hi;
        *(__nv_bfloat16*)(smem + ASM_WLO + c * 144 + k * 2) =
            __float2bfloat16(w - __bfloat162float(hi));
    }
    for (int idx = tid; idx < 3200; idx += 256) {
        int k = idx / 40, n = idx - k * 40;
        float w = Wa2[idx];
        __nv_bfloat16 hi = __float2bfloat16(w);
        *(__nv_bfloat16*)(smem + ASM_W2HI + n * 176 + k * 2) = hi;
        *(__nv_bfloat16*)(smem + ASM_W2LO + n * 176 + k * 2) =
            __float2bfloat16(w - __bfloat162float(hi));
    }

    const int arow_l = lane & 15;
    const int acolb  = (lane >> 4) << 3;
    const int bnrow_l = (lane & 7) + ((lane & 16) >> 1);
    const int bcol_l  = lane & 8;
    const int g = lane >> 2, q = lane & 3;
    const float ba3v = ba3[0];

    for (int cc = 0; cc < 2; cc++) {
        const int t0 = cc * ACH;

        __syncthreads();
        for (int idx = tid; idx < ACH * 16; idx += 256) {
            int r = idx >> 4, c4 = idx & 15;
            int tg = t0 + r; if (tg > T - 1) tg = T - 1;
            float4 v = *(const float4*)(rnn1 + ((size_t)b * T + tg) * 64 + c4 * 4);
            __nv_bfloat16 h[4], l[4];
            h[0] = __float2bfloat16(v.x); l[0] = __float2bfloat16(v.x - __bfloat162float(h[0]));
            h[1] = __float2bfloat16(v.y); l[1] = __float2bfloat16(v.y - __bfloat162float(h[1]));
            h[2] = __float2bfloat16(v.z); l[2] = __float2bfloat16(v.z - __bfloat162float(h[2]));
            h[3] = __float2bfloat16(v.w); l[3] = __float2bfloat16(v.w - __bfloat162float(h[3]));
            int off = r * 144 + c4 * 8;
            *(uint2*)(smem + ASM_KHI + off) = *(uint2*)h;
            *(uint2*)(smem + ASM_KLO + off) = *(uint2*)l;
        }
        __syncthreads();

        for (int mtl = wid; mtl < 7; mtl += 8) {
            float acc[10][4];
#pragma unroll
            for (int nt = 0; nt < 10; nt++) {
                float b0 = base[nt * 8 + 2 * q], b1 = base[nt * 8 + 2 * q + 1];
                acc[nt][0] = b0; acc[nt][1] = b1; acc[nt][2] = b0; acc[nt][3] = b1;
            }
            const uint32_t aHb = sbase + ASM_KHI + (uint32_t)(mtl * 16 + arow_l) * 144 + acolb * 2;
            const uint32_t aLb = sbase + ASM_KLO + (uint32_t)(mtl * 16 + arow_l) * 144 + acolb * 2;
            const uint32_t bHb = sbase + ASM_WHI + (uint32_t)bnrow_l * 144 + bcol_l * 2;
            const uint32_t bLb = sbase + ASM_WLO + (uint32_t)bnrow_l * 144 + bcol_l * 2;
#pragma unroll
            for (int ks = 0; ks < 4; ks++) {
                uint32_t aH[4], aL[4];
                ldsm_x4(aH[0], aH[1], aH[2], aH[3], aHb + ks * 32);
                ldsm_x4(aL[0], aL[1], aL[2], aL[3], aLb + ks * 32);
#pragma unroll
                for (int np = 0; np < 5; np++) {
                    uint32_t c0, c1, c2, c3;
                    ldsm_x4(c0, c1, c2, c3, bHb + (uint32_t)np * 16 * 144 + ks * 32);
                    mma16816(acc[2 * np],     aH, c0, c1);
                    mma16816(acc[2 * np + 1], aH, c2, c3);
                    mma16816(acc[2 * np],     aL, c0, c1);
                    mma16816(acc[2 * np + 1], aL, c2, c3);
                    ldsm_x4(c0, c1, c2, c3, bLb + (uint32_t)np * 16 * 144 + ks * 32);
                    mma16816(acc[2 * np],     aH, c0, c1);
                    mma16816(acc[2 * np + 1], aH, c2, c3);
                }
            }
            const int r0 = mtl * 16 + g, r1 = r0 + 8;
#pragma unroll
            for (int nt = 0; nt < 10; nt++) {
                const int c0 = nt * 8 + 2 * q;
                float s00 = sigmoidf_fast(acc[nt][0]);
                float s01 = sigmoidf_fast(acc[nt][1]);
                float s10 = sigmoidf_fast(acc[nt][2]);
                float s11 = sigmoidf_fast(acc[nt][3]);
                split_pair(smem + ASM_D1HI, smem + ASM_D1LO, r0 * 176 + c0 * 2, s00, s01);
                split_pair(smem + ASM_D1HI, smem + ASM_D1LO, r1 * 176 + c0 * 2, s10, s11);
            }
        }
        __syncthreads();

        for (int mtl = wid; mtl < 7; mtl += 8) {
            float acc[6][4];
#pragma unroll
            for (int nt = 0; nt < 6; nt++) {
                float b0 = ba2s[nt * 8 + 2 * q], b1 = ba2s[nt * 8 + 2 * q + 1];
                acc[nt][0] = b0; acc[nt][1] = b1; acc[nt][2] = b0; acc[nt][3] = b1;
            }
            const uint32_t aHb = sbase + ASM_D1HI + (uint32_t)(mtl * 16 + arow_l) * 176 + acolb * 2;
            const uint32_t aLb = sbase + ASM_D1LO + (uint32_t)(mtl * 16 + arow_l) * 176 + acolb * 2;
            const uint32_t bHb = sbase + ASM_W2HI + (uint32_t)bnrow_l * 176 + bcol_l * 2;
            const uint32_t bLb = sbase + ASM_W2LO + (uint32_t)bnrow_l * 176 + bcol_l * 2;
#pragma unroll
            for (int ks = 0; ks < 5; ks++) {
                uint32_t aH[4], aL[4];
                ldsm_x4(aH[0], aH[1], aH[2], aH[3], aHb + ks * 32);
                ldsm_x4(aL[0], aL[1], aL[2], aL[3], aLb + ks * 32);
#pragma unroll
                for (int np = 0; np < 3; np++) {
                    uint32_t c0, c1, c2, c3;
                    ldsm_x4(c0, c1, c2, c3, bHb + (uint32_t)np * 16 * 176 + ks * 32);
                    mma16816(acc[2 * np],     aH, c0, c1);
                    mma16816(acc[2 * np + 1], aH, c2, c3);
                    mma16816(acc[2 * np],     aL, c0, c1);
                    mma16816(acc[2 * np + 1], aL, c2, c3);
                    ldsm_x4(c0, c1, c2, c3, bLb + (uint32_t)np * 16 * 176 + ks * 32);
                    mma16816(acc[2 * np],     aH, c0, c1);
                    mma16816(acc[2 * np + 1], aH, c2, c3);
                }
            }
            float s0 = 0.0f, s1 = 0.0f;
#pragma unroll
            for (int nt = 0; nt < 5; nt++) {
                const int c0 = nt * 8 + 2 * q;
                float w0 = wa3s[c0], w1 = wa3s[c0 + 1];
                s0 = fmaf(sigmoidf_fast(acc[nt][0]), w0, s0);
                s0 = fmaf(sigmoidf_fast(acc[nt][1]), w1, s0);
                s1 = fmaf(sigmoidf_fast(acc[nt][2]), w0, s1);
                s1 = fmaf(sigmoidf_fast(acc[nt][3]), w1, s1);
            }
            s0 += __shfl_xor_sync(0xffffffffu, s0, 1);
            s0 += __shfl_xor_sync(0xffffffffu, s0, 2);
            s1 += __shfl_xor_sync(0xffffffffu, s1, 1);
            s1 += __shfl_xor_sync(0xffffffffu, s1, 2);
            if (q == 0) {
                int t0g = t0 + mtl * 16 + g, t1g = t0g + 8;
                if (t0g < T) {
                    float m = mask[(size_t)b * T + t0g];
                    sc[t0g] = (m > 0.0f) ? (s0 + ba3v) : -1e9f;
                }
                if (t1g < T) {
                    float m = mask[(size_t)b * T + t1g];
                    sc[t1g] = (m > 0.0f) ? (s1 + ba3v) : -1e9f;
                }
            }
        }
    }
    __syncthreads();

    float v = (tid < T) ? sc[tid] : -FLT_MAX;
#pragma unroll
    for (int o = 16; o > 0; o >>= 1) v = fmaxf(v, __shfl_xor_sync(0xffffffffu, v, o));
    if (lane == 0) red[wid] = v;
    __syncthreads();
    if (tid == 0) {
        float mx = red[0];
#pragma unroll
        for (int w = 1; w < 8; w++) mx = fmaxf(mx, red[w]);
        red[12] = mx;
    }
    __syncthreads();
    float mx = red[12];

    float e = (tid < T) ? __expf(sc[tid] - mx) : 0.0f;
    float s = e;
#pragma unroll
    for (int o = 16; o > 0; o >>= 1) s += __shfl_xor_sync(0xffffffffu, s, o);
    __syncthreads();
    if (lane == 0) red[wid] = s;
    __syncthreads();
    if (tid == 0) {
        float sum = 0.0f;
#pragma unroll
        for (int w = 0; w < 8; w++) sum += red[w];
        red[13] = 1.0f / sum;
    }
    __syncthreads();
    if (tid < T) alpha[(size_t)b * T + tid] = e * red[13];
}

// ======================================================================
// FCN head + hist_sum (unchanged).
// ======================================================================
__global__ void fcn_kernel(const int* __restrict__ u, const int* __restrict__ ii,
                           const int* __restrict__ hist_i,
                           const float* __restrict__ item_emb,
                           const float* __restrict__ user_emb,
                           const float* __restrict__ final2,
                           const float* __restrict__ W1, const float* __restrict__ b1,
                           const float* __restrict__ p1,
                           const float* __restrict__ W2, const float* __restrict__ b2,
                           const float* __restrict__ p2,
                           const float* __restrict__ W3, const float* __restrict__ b3,
                           float* __restrict__ out)
{
    __shared__ float xs[320];
    __shared__ float h1s[128];
    __shared__ float h2s[40];

    const int b = blockIdx.x;
    const int tid = threadIdx.x;

    if (tid < 64) {
        const int* hi = hist_i + (size_t)b * T;
        float s0 = 0.f, s1 = 0.f, s2 = 0.f, s3 = 0.f;
        for (int t = 0; t < T; t += 4) {
            s0 += item_emb[(size_t)hi[t]     * 64 + tid];
            s1 += item_emb[(size_t)hi[t + 1] * 64 + tid];
            s2 += item_emb[(size_t)hi[t + 2] * 64 + tid];
            s3 += item_emb[(size_t)hi[t + 3] * 64 + tid];
        }
        xs[128 + tid] = (s0 + s1) + (s2 + s3);
    } else {
        int j = tid - 64;
        xs[j]       = user_emb[(size_t)u[b]  * 64 + j];
        xs[64 + j]  = item_emb[(size_t)ii[b] * 64 + j];
        xs[256 + j] = final2[(size_t)b * 64 + j];
    }
    __syncthreads();
    if (tid < 64) xs[192 + tid] = xs[64 + tid] * xs[128 + tid];
    __syncthreads();

    {
        float a0 = b1[tid], a1 = 0.0f;
#pragma unroll 8
        for (int k = 0; k < 320; k += 2) {
            a0 = fmaf(xs[k],     W1[k * 128 + tid],       a0);
            a1 = fmaf(xs[k + 1], W1[(k + 1) * 128 + tid], a1);
        }
        float h = a0 + a1;
        h1s[tid] = (h >= 0.0f) ? h : p1[tid] * h;
    }
    __syncthreads();

    if (tid < 40) {
        float a0 = b2[tid], a1 = 0.0f;
#pragma unroll 16
        for (int k = 0; k < 128; k += 2) {
            a0 = fmaf(h1s[k],     W2[k * 40 + tid],       a0);
            a1 = fmaf(h1s[k + 1], W2[(k + 1) * 40 + tid], a1);
        }
        float h = a0 + a1;
        h2s[tid] = (h >= 0.0f) ? h : p2[tid] * h;
    }
    __syncthreads();

    if (tid == 0) {
        float acc = b3[0];
#pragma unroll
        for (int k = 0; k < 40; k++) acc = fmaf(h2s[k], W3[k], acc);
        out[b] = acc;
    }
}

// ======================================================================
extern "C" void kernel_launch(void* const* d_in, const int* in_sizes, int n_in,
                              void* d_out, int out_size)
{
    const int*   u        = (const int*)d_in[0];
    const int*   ii       = (const int*)d_in[1];
    const int*   hist_i   = (const int*)d_in[2];
    const float* mask     = (const float*)d_in[3];
    const float* item_emb = (const float*)d_in[4];
    const float* user_emb = (const float*)d_in[5];
    const float* g1_Wg = (const float*)d_in[6];
    const float* g1_Ug = (const float*)d_in[7];
    const float* g1_bg = (const float*)d_in[8];
    const float* g1_Wc = (const float*)d_in[9];
    const float* g1_Uc = (const float*)d_in[10];
    const float* g1_bc = (const float*)d_in[11];
    const float* Wa1 = (const float*)d_in[12];
    const float* ba1 = (const float*)d_in[13];
    const float* Wa2 = (const float*)d_in[14];
    const float* ba2 = (const float*)d_in[15];
    const float* Wa3 = (const float*)d_in[16];
    const float* ba3 = (const float*)d_in[17];
    const float* g2_Wg = (const float*)d_in[18];
    const float* g2_Ug = (const float*)d_in[19];
    const float* g2_bg = (const float*)d_in[20];
    const float* g2_Wc = (const float*)d_in[21];
    const float* g2_Uc = (const float*)d_in[22];
    const float* g2_bc = (const float*)d_in[23];
    const float* W1 = (const float*)d_in[24];
    const float* b1 = (const float*)d_in[25];
    const float* p1 = (const float*)d_in[26];
    const float* W2 = (const float*)d_in[27];
    const float* b2 = (const float*)d_in[28];
    const float* p2 = (const float*)d_in[29];
    const float* W3 = (const float*)d_in[30];
    const float* b3 = (const float*)d_in[31];
    float* out = (float*)d_out;

    float *xg, *xc, *rnn1, *alpha, *final2;
    __nv_bfloat16 *bh1, *bl1, *bh2, *bl2;
    cudaGetSymbolAddress((void**)&xg,     g_xg);
    cudaGetSymbolAddress((void**)&xc,     g_xc);
    cudaGetSymbolAddress((void**)&rnn1,   g_rnn1);
    cudaGetSymbolAddress((void**)&alpha,  g_alpha);
    cudaGetSymbolAddress((void**)&final2, g_final2);
    cudaGetSymbolAddress((void**)&bh1, g_bh1);
    cudaGetSymbolAddress((void**)&bl1, g_bl1);
    cudaGetSymbolAddress((void**)&bh2, g_bh2);
    cudaGetSymbolAddress((void**)&bl2, g_bl2);

    cudaFuncSetAttribute(proj_mma_kernel<0>, cudaFuncAttributeMaxDynamicSharedMemorySize, PSM_TOTAL);
    cudaFuncSetAttribute(proj_mma_kernel<1>, cudaFuncAttributeMaxDynamicSharedMemorySize, PSM_TOTAL);
    cudaFuncSetAttribute(gru_tc_kernel<true>,  cudaFuncAttributeMaxDynamicSharedMemorySize, GSM_TOTAL);
    cudaFuncSetAttribute(gru_tc_kernel<false>, cudaFuncAttributeMaxDynamicSharedMemorySize, GSM_TOTAL);
    cudaFuncSetAttribute(attn_mma_kernel, cudaFuncAttributeMaxDynamicSharedMemorySize, ASM_TOTAL);

    // 0) split projection weights to bf16 hi/lo (both GRUs)
    wsplit_kernel<<<48, 256>>>(g1_Wg, g1_Wc, bh1, bl1);
    wsplit_kernel<<<48, 256>>>(g2_Wg, g2_Wc, bh2, bl2);
    // 1) GRU1 input projections via HMMA
    proj_mma_kernel<0><<<BT / 128, 256, PSM_TOTAL>>>(item_emb, hist_i, nullptr,
                                                     bh1, bl1, g1_bg, g1_bc, xg, xc);
    // 2) GRU1 recurrence via HMMA (weights in registers) -> rnn1
    gru_tc_kernel<true><<<B / GM, 256, GSM_TOTAL>>>(xg, xc, mask, g1_Ug, g1_Uc, rnn1);
    // 3) DIN attention via HMMA (chunked, 2 CTAs/SM) -> alpha
    attn_mma_kernel<<<B, 256, ASM_TOTAL>>>(ii, item_emb, rnn1, mask,
                                           Wa1, ba1, Wa2, ba2, Wa3, ba3, alpha);
    // 4) GRU2 input projections via HMMA (rnn1 * alpha)
    proj_mma_kernel<1><<<BT / 128, 256, PSM_TOTAL>>>(rnn1, nullptr, alpha,
                                                     bh2, bl2, g2_bg, g2_bc, xg, xc);
    // 5) GRU2 recurrence via HMMA -> final2 only
    gru_tc_kernel<false><<<B / GM, 256, GSM_TOTAL>>>(xg, xc, mask, g2_Ug, g2_Uc, final2);
    // 6) FCN head -> logits
    fcn_kernel<<<B, 128>>>(u, ii, hist_i, item_emb, user_emb, final2,
                           W1, b1, p1, W2, b2, p2, W3, b3, out);
}